// round 1
// baseline (speedup 1.0000x reference)
#include <cuda_runtime.h>
#include <math.h>

// ---------------- problem constants ----------------
#define BATCH 4
#define SEQ   2048
#define DMODEL 768
#define NHEAD 12
#define DH    64
#define NTOK  (BATCH*SEQ)          // 8192
#define QKVN  (3*DMODEL)           // 2304
#define FDIM  3072
#define PLANE ((size_t)NTOK*DH*NHEAD) // 6,291,456 elems per q/k/v plane

// ---------------- scratch (__device__ globals; no allocation) ----------------
__device__ float g_Weff[(size_t)DMODEL*QKVN];       // 768 x 2304
__device__ float g_biasqkv[QKVN];
__device__ float g_qkv[3*PLANE];                    // [3][B][H][M][64]
__device__ float g_attn[(size_t)NTOK*DMODEL];       // [B*M, 768]
__device__ float g_t256[(size_t)NTOK*256];
__device__ float g_mid[(size_t)NTOK*FDIM];
__device__ float g_pre[(size_t)NTOK*DMODEL];
__device__ float g_x1[(size_t)NTOK*DMODEL];

// ---------------- fuse low-rank weights: Weff[d][c] = sum_r P[h][d][r]*V[h][r][j] ----------------
__global__ void fuse_w_kernel(const float* __restrict__ Pq, const float* __restrict__ Vq, const float* __restrict__ bq,
                              const float* __restrict__ Pk, const float* __restrict__ Vk, const float* __restrict__ bk,
                              const float* __restrict__ Pv, const float* __restrict__ Vv, const float* __restrict__ bv)
{
    int idx = blockIdx.x * blockDim.x + threadIdx.x;
    if (idx >= DMODEL * QKVN) return;
    int d = idx / QKVN;
    int c = idx - d * QKVN;
    int p = c / DMODEL;
    int c2 = c - p * DMODEL;
    int h = c2 >> 6;
    int j = c2 & 63;
    const float* P = (p == 0) ? Pq : (p == 1) ? Pk : Pv;
    const float* V = (p == 0) ? Vq : (p == 1) ? Vk : Vv;
    const float* B = (p == 0) ? bq : (p == 1) ? bk : bv;
    const float* Ph = P + (size_t)h * DMODEL * 32 + (size_t)d * 32;
    const float* Vh = V + (size_t)h * 32 * DH + j;
    float s = 0.f;
#pragma unroll
    for (int r = 0; r < 32; r++) s += Ph[r] * Vh[(size_t)r * DH];
    g_Weff[(size_t)d * QKVN + c] = s;
    if (d == 0) g_biasqkv[c] = B[h * DH + j];
}

// ---------------- SGEMM 128x128x8, 8x8 microtile, epilogue variants ----------------
// EPI: 0 = plain, 2 = QKV scatter (+bias), 3 = bias + exact GELU, 4 = bias + residual
template<int EPI>
__global__ __launch_bounds__(256) void sgemm_kernel(
    const float* __restrict__ A, const float* __restrict__ B, float* __restrict__ C,
    int M, int N, int K, const float* __restrict__ bias, const float* __restrict__ res)
{
    __shared__ float As[8][128];
    __shared__ float Bs[8][128];
    int tid = threadIdx.x;
    int tx = tid & 15, ty = tid >> 4;
    int rowBase = blockIdx.y * 128, colBase = blockIdx.x * 128;

    float acc[8][8];
#pragma unroll
    for (int i = 0; i < 8; i++)
#pragma unroll
        for (int j = 0; j < 8; j++) acc[i][j] = 0.f;

    int aRow = tid >> 1;            // 0..127
    int aK   = (tid & 1) << 2;      // 0 or 4
    int bK   = tid >> 5;            // 0..7
    int bN   = (tid & 31) << 2;     // 0..124
    const float* Aptr = A + (size_t)(rowBase + aRow) * K + aK;
    const float* Bptr = B + (size_t)bK * N + colBase + bN;

    for (int k0 = 0; k0 < K; k0 += 8) {
        float4 av = *(const float4*)(Aptr + k0);
        float4 bv = *(const float4*)(Bptr + (size_t)k0 * N);
        As[aK + 0][aRow] = av.x; As[aK + 1][aRow] = av.y;
        As[aK + 2][aRow] = av.z; As[aK + 3][aRow] = av.w;
        *(float4*)&Bs[bK][bN] = bv;
        __syncthreads();
#pragma unroll
        for (int kk = 0; kk < 8; kk++) {
            float4 a0 = *(float4*)&As[kk][ty * 8];
            float4 a1 = *(float4*)&As[kk][ty * 8 + 4];
            float4 b0 = *(float4*)&Bs[kk][tx * 8];
            float4 b1 = *(float4*)&Bs[kk][tx * 8 + 4];
            float ar[8] = {a0.x, a0.y, a0.z, a0.w, a1.x, a1.y, a1.z, a1.w};
            float br[8] = {b0.x, b0.y, b0.z, b0.w, b1.x, b1.y, b1.z, b1.w};
#pragma unroll
            for (int i = 0; i < 8; i++)
#pragma unroll
                for (int j = 0; j < 8; j++) acc[i][j] += ar[i] * br[j];
        }
        __syncthreads();
    }

    int row0 = rowBase + ty * 8;
    int col0 = colBase + tx * 8;
#pragma unroll
    for (int i = 0; i < 8; i++) {
        int row = row0 + i;
#pragma unroll
        for (int j = 0; j < 8; j++) {
            int col = col0 + j;
            float v = acc[i][j];
            if (EPI == 0) {
                C[(size_t)row * N + col] = v;
            } else if (EPI == 2) {
                v += bias[col];
                int p = col / DMODEL;
                int c2 = col - p * DMODEL;
                int h = c2 >> 6, jj = c2 & 63;
                int b = row >> 11, m = row & 2047;
                C[(size_t)p * PLANE + ((size_t)((b * NHEAD + h) * SEQ + m)) * DH + jj] = v;
            } else if (EPI == 3) {
                float g = v + bias[col];
                C[(size_t)row * N + col] = 0.5f * g * (1.f + erff(g * 0.70710678118654752f));
            } else if (EPI == 4) {
                C[(size_t)row * N + col] = v + bias[col] + res[(size_t)row * N + col];
            }
        }
    }
}

// ---------------- flash attention (fp32, BM=64, BN=32) ----------------
__global__ __launch_bounds__(256) void flash_kernel(const float* __restrict__ mask)
{
    __shared__ float q_s[64][68];
    __shared__ float k_s[32][68];
    __shared__ float v_s[32][68];
    __shared__ float p_s[64][36];

    int b = blockIdx.z, h = blockIdx.y;
    int m0 = blockIdx.x * 64;
    int tid = threadIdx.x;
    int r = tid >> 2;     // 0..63 query row within tile
    int qd = tid & 3;     // quarter

    const float* qbase = g_qkv + ((size_t)(b * NHEAD + h) * SEQ + m0) * DH;
    const float* kbase = g_qkv + PLANE     + (size_t)(b * NHEAD + h) * SEQ * DH;
    const float* vbase = g_qkv + 2 * PLANE + (size_t)(b * NHEAD + h) * SEQ * DH;
    const float* mrow = mask + b * SEQ;

    // load Q tile
    for (int idx = tid; idx < 64 * 16; idx += 256) {
        int rr = idx >> 4;
        int c4 = (idx & 15) << 2;
        *(float4*)&q_s[rr][c4] = *(const float4*)(qbase + (size_t)rr * DH + c4);
    }

    float o[16];
#pragma unroll
    for (int i = 0; i < 16; i++) o[i] = 0.f;
    float mi = -1e30f, li = 0.f;

    for (int nt = 0; nt < SEQ; nt += 32) {
        __syncthreads();  // prior PV done before overwriting k/v
        for (int idx = tid; idx < 32 * 16; idx += 256) {
            int rr = idx >> 4;
            int c4 = (idx & 15) << 2;
            *(float4*)&k_s[rr][c4] = *(const float4*)(kbase + (size_t)(nt + rr) * DH + c4);
            *(float4*)&v_s[rr][c4] = *(const float4*)(vbase + (size_t)(nt + rr) * DH + c4);
        }
        __syncthreads();

        float sv[8];
        float smax = -1e30f;
#pragma unroll
        for (int nn = 0; nn < 8; nn++) {
            int n = (nn << 2) + qd;
            float s = 0.f;
#pragma unroll
            for (int d4 = 0; d4 < 64; d4 += 4) {
                float4 qa = *(float4*)&q_s[r][d4];
                float4 ka = *(float4*)&k_s[n][d4];
                s += qa.x * ka.x + qa.y * ka.y + qa.z * ka.z + qa.w * ka.w;
            }
            s = s * 0.125f + mrow[nt + n];
            sv[nn] = s;
            smax = fmaxf(smax, s);
        }
        smax = fmaxf(smax, __shfl_xor_sync(0xffffffffu, smax, 1));
        smax = fmaxf(smax, __shfl_xor_sync(0xffffffffu, smax, 2));
        float newm = fmaxf(mi, smax);
        float alpha = __expf(mi - newm);
        float ls = 0.f;
#pragma unroll
        for (int nn = 0; nn < 8; nn++) {
            float p = __expf(sv[nn] - newm);
            p_s[r][(nn << 2) + qd] = p;
            ls += p;
        }
        ls += __shfl_xor_sync(0xffffffffu, ls, 1);
        ls += __shfl_xor_sync(0xffffffffu, ls, 2);
        li = li * alpha + ls;
        mi = newm;
#pragma unroll
        for (int i = 0; i < 16; i++) o[i] *= alpha;
        __syncthreads();  // p_s visible

#pragma unroll 4
        for (int nn = 0; nn < 32; nn++) {
            float pv = p_s[r][nn];
            int dbase = qd * 16;
            float4 v0 = *(float4*)&v_s[nn][dbase];
            float4 v1 = *(float4*)&v_s[nn][dbase + 4];
            float4 v2 = *(float4*)&v_s[nn][dbase + 8];
            float4 v3 = *(float4*)&v_s[nn][dbase + 12];
            o[0]  += pv * v0.x; o[1]  += pv * v0.y; o[2]  += pv * v0.z; o[3]  += pv * v0.w;
            o[4]  += pv * v1.x; o[5]  += pv * v1.y; o[6]  += pv * v1.z; o[7]  += pv * v1.w;
            o[8]  += pv * v2.x; o[9]  += pv * v2.y; o[10] += pv * v2.z; o[11] += pv * v2.w;
            o[12] += pv * v3.x; o[13] += pv * v3.y; o[14] += pv * v3.z; o[15] += pv * v3.w;
        }
    }

    float inv = 1.f / li;
    float* outp = g_attn + ((size_t)(b * SEQ + m0 + r)) * DMODEL + h * DH + (qd << 4);
#pragma unroll
    for (int g = 0; g < 4; g++) {
        float4 ov;
        ov.x = o[g * 4 + 0] * inv; ov.y = o[g * 4 + 1] * inv;
        ov.z = o[g * 4 + 2] * inv; ov.w = o[g * 4 + 3] * inv;
        *(float4*)(outp + g * 4) = ov;
    }
}

// ---------------- LayerNorm (one block per row of 768) ----------------
__global__ __launch_bounds__(256) void ln_kernel(const float* __restrict__ in,
                                                 const float* __restrict__ gam,
                                                 const float* __restrict__ bet,
                                                 float* __restrict__ out)
{
    int row = blockIdx.x;
    int t = threadIdx.x;
    const float* ip = in + (size_t)row * DMODEL;
    float x0 = ip[t], x1 = ip[t + 256], x2 = ip[t + 512];
    __shared__ float rs[256], rq[256];
    rs[t] = x0 + x1 + x2;
    rq[t] = x0 * x0 + x1 * x1 + x2 * x2;
    __syncthreads();
    for (int off = 128; off > 0; off >>= 1) {
        if (t < off) { rs[t] += rs[t + off]; rq[t] += rq[t + off]; }
        __syncthreads();
    }
    float mu = rs[0] * (1.f / 768.f);
    float var = rq[0] * (1.f / 768.f) - mu * mu;
    float rstd = rsqrtf(var + 1e-12f);
    float* op = out + (size_t)row * DMODEL;
    op[t]       = (x0 - mu) * rstd * gam[t]       + bet[t];
    op[t + 256] = (x1 - mu) * rstd * gam[t + 256] + bet[t + 256];
    op[t + 512] = (x2 - mu) * rstd * gam[t + 512] + bet[t + 512];
}

// ---------------- launch ----------------
extern "C" void kernel_launch(void* const* d_in, const int* in_sizes, int n_in,
                              void* d_out, int out_size)
{
    const float* x    = (const float*)d_in[0];
    const float* mask = (const float*)d_in[1];
    const float* Pq = (const float*)d_in[2];
    const float* Vq = (const float*)d_in[3];
    const float* bq = (const float*)d_in[4];
    const float* Pk = (const float*)d_in[5];
    const float* Vk = (const float*)d_in[6];
    const float* bk = (const float*)d_in[7];
    const float* Pv = (const float*)d_in[8];
    const float* Vv = (const float*)d_in[9];
    const float* bv = (const float*)d_in[10];
    const float* Uo = (const float*)d_in[11];
    const float* Vo = (const float*)d_in[12];
    const float* bo = (const float*)d_in[13];
    const float* U1 = (const float*)d_in[14];
    const float* V1 = (const float*)d_in[15];
    const float* b1 = (const float*)d_in[16];
    const float* U2 = (const float*)d_in[17];
    const float* V2 = (const float*)d_in[18];
    const float* b2 = (const float*)d_in[19];
    const float* g1 = (const float*)d_in[20];
    const float* be1 = (const float*)d_in[21];
    const float* g2 = (const float*)d_in[22];
    const float* be2 = (const float*)d_in[23];

    float *Weff, *biasqkv, *qkv, *attn, *t256, *mid, *pre, *x1b;
    cudaGetSymbolAddress((void**)&Weff,    g_Weff);
    cudaGetSymbolAddress((void**)&biasqkv, g_biasqkv);
    cudaGetSymbolAddress((void**)&qkv,     g_qkv);
    cudaGetSymbolAddress((void**)&attn,    g_attn);
    cudaGetSymbolAddress((void**)&t256,    g_t256);
    cudaGetSymbolAddress((void**)&mid,     g_mid);
    cudaGetSymbolAddress((void**)&pre,     g_pre);
    cudaGetSymbolAddress((void**)&x1b,     g_x1);

    // 1) fold low-rank weights into one QKV matrix
    fuse_w_kernel<<<(DMODEL * QKVN + 255) / 256, 256>>>(Pq, Vq, bq, Pk, Vk, bk, Pv, Vv, bv);
    // 2) fused QKV GEMM with scatter: [8192,768] x [768,2304]
    sgemm_kernel<2><<<dim3(QKVN / 128, NTOK / 128), 256>>>(x, Weff, qkv, NTOK, QKVN, DMODEL, biasqkv, nullptr);
    // 3) flash attention -> [B*M, 768]
    flash_kernel<<<dim3(SEQ / 64, NHEAD, BATCH), 256>>>(mask);
    // 4) attn @ Uo -> [8192,256]
    sgemm_kernel<0><<<dim3(256 / 128, NTOK / 128), 256>>>(attn, Uo, t256, NTOK, 256, DMODEL, nullptr, nullptr);
    // 5) t @ Vo + bo + x -> pre1
    sgemm_kernel<4><<<dim3(DMODEL / 128, NTOK / 128), 256>>>(t256, Vo, pre, NTOK, DMODEL, 256, bo, x);
    // 6) LN1 -> x1
    ln_kernel<<<NTOK, 256>>>(pre, g1, be1, x1b);
    // 7) x1 @ U1 -> [8192,256]
    sgemm_kernel<0><<<dim3(256 / 128, NTOK / 128), 256>>>(x1b, U1, t256, NTOK, 256, DMODEL, nullptr, nullptr);
    // 8) gelu(t @ V1 + b1) -> [8192,3072]
    sgemm_kernel<3><<<dim3(FDIM / 128, NTOK / 128), 256>>>(t256, V1, mid, NTOK, FDIM, 256, b1, nullptr);
    // 9) mid @ U2 -> [8192,256]
    sgemm_kernel<0><<<dim3(256 / 128, NTOK / 128), 256>>>(mid, U2, t256, NTOK, 256, FDIM, nullptr, nullptr);
    // 10) t @ V2 + b2 + x1 -> pre2
    sgemm_kernel<4><<<dim3(DMODEL / 128, NTOK / 128), 256>>>(t256, V2, pre, NTOK, DMODEL, 256, b2, x1b);
    // 11) LN2 -> out
    ln_kernel<<<NTOK, 256>>>(pre, g2, be2, (float*)d_out);
}

// round 4
// speedup vs baseline: 6.1506x; 6.1506x over previous
#include <cuda_runtime.h>
#include <cuda_bf16.h>
#include <math.h>
#include <stdint.h>

// ---------------- problem constants ----------------
#define BATCH 4
#define SEQ   2048
#define DMODEL 768
#define NHEAD 12
#define DH    64
#define NTOK  (BATCH*SEQ)          // 8192
#define QKVN  (3*DMODEL)           // 2304
#define FDIM  3072
#define BH    (BATCH*NHEAD)        // 48

typedef __nv_bfloat16 bf16;
typedef __nv_bfloat162 bf162;

// ---------------- scratch (__device__ globals; no allocation) ----------------
__device__ bf16 g_xb[(size_t)NTOK*DMODEL];
__device__ bf16 g_Wtb[(size_t)QKVN*DMODEL];            // [2304][768]
__device__ float g_bqkv[QKVN];
__device__ bf16 g_q[(size_t)BH*SEQ*DH];                // [48][2048][64]
__device__ bf16 g_k[(size_t)BH*SEQ*DH];
__device__ bf16 g_v[(size_t)BH*SEQ*DH];
__device__ bf16 g_vt[(size_t)BH*DH*SEQ];               // [48][64][2048]
__device__ bf16 g_S[(size_t)BH*SEQ*SEQ];               // S then P (in-place)
__device__ bf16 g_attnb[(size_t)NTOK*DMODEL];
__device__ bf16 g_t256b[(size_t)NTOK*256];
__device__ bf16 g_mid[(size_t)NTOK*FDIM];
__device__ float g_pre[(size_t)NTOK*DMODEL];
__device__ float g_x1[(size_t)NTOK*DMODEL];
__device__ bf16 g_x1b[(size_t)NTOK*DMODEL];
__device__ bf16 g_Uot[256*DMODEL];
__device__ bf16 g_Vot[DMODEL*256];
__device__ bf16 g_U1t[256*DMODEL];
__device__ bf16 g_V1t[FDIM*256];
__device__ bf16 g_U2t[256*FDIM];
__device__ bf16 g_V2t[DMODEL*256];

// ---------------- PTX helpers (base ISA only: sm_80-compatible) ----------------
__device__ __forceinline__ uint32_t smem_u32(const void* p) {
    uint32_t a;
    asm("{ .reg .u64 t; cvta.to.shared.u64 t, %1; cvt.u32.u64 %0, t; }" : "=r"(a) : "l"(p));
    return a;
}
#define CPASYNC16(dst, src) asm volatile("cp.async.cg.shared.global [%0], [%1], 16;" :: "r"(dst), "l"(src))
#define CPCOMMIT()          asm volatile("cp.async.commit_group;" ::: "memory")
#define CPWAIT(n)           asm volatile("cp.async.wait_group %0;" :: "n"(n) : "memory")

__device__ __forceinline__ void ldsm4(uint32_t* r, uint32_t a) {
    asm volatile("ldmatrix.sync.aligned.m8n8.x4.shared.b16 {%0,%1,%2,%3}, [%4];"
        : "=r"(r[0]), "=r"(r[1]), "=r"(r[2]), "=r"(r[3]) : "r"(a));
}
__device__ __forceinline__ void ldsm2(uint32_t* r, uint32_t a) {
    asm volatile("ldmatrix.sync.aligned.m8n8.x2.shared.b16 {%0,%1}, [%2];"
        : "=r"(r[0]), "=r"(r[1]) : "r"(a));
}
__device__ __forceinline__ void mma16816(float* c, const uint32_t* a, const uint32_t* b) {
    asm volatile("mma.sync.aligned.m16n8k16.row.col.f32.bf16.bf16.f32 "
        "{%0,%1,%2,%3}, {%4,%5,%6,%7}, {%8,%9}, {%0,%1,%2,%3};"
        : "+f"(c[0]), "+f"(c[1]), "+f"(c[2]), "+f"(c[3])
        : "r"(a[0]), "r"(a[1]), "r"(a[2]), "r"(a[3]), "r"(b[0]), "r"(b[1]));
}

__device__ __forceinline__ float gelu_exact(float a) {
    return 0.5f * a * (1.f + erff(a * 0.70710678118654752f));
}

// ---------------- generic bf16 mma GEMM: C[128 x BN] = A[M,K] @ B[N,K]^T ----------------
// EPI: 0 = bf16 out (outB + z*sC + gm*ldC + gn)
//      1 = f32 out = v + bias[gn] + res[gm*ldC+gn]
//      2 = bf16 out = gelu(v + bias[gn])
//      3 = QKV scatter (+bias) into g_q/g_k/g_v planes
//      4 = PV scatter into g_attnb
#define BM 128
#define BK 32
#define RST 40   // smem row stride in elems (80B) -> conflict-free ldmatrix

template<int BN, int EPI>
__global__ __launch_bounds__(256) void bmma_gemm(
    const bf16* __restrict__ A, const bf16* __restrict__ B,
    int K, int ldA, int ldB, long long sA, long long sB,
    float* __restrict__ outF, bf16* __restrict__ outB,
    const float* __restrict__ bias, const float* __restrict__ res,
    int ldC, long long sC)
{
    constexpr int NT = BN / 32;              // n mma tiles per warp (warp n width BN/4)
    constexpr int ACH = BM * 4;              // 16B chunks for A per stage
    constexpr int TCH = (BM + BN) * 4;
    constexpr int SSA = BM * RST;            // elems
    constexpr int SS  = (BM + BN) * RST;

    __shared__ bf16 sm[2 * SS];

    int tid = threadIdx.x;
    int z = blockIdx.z;
    const bf16* Ab = A + (long long)z * sA + (long long)blockIdx.y * BM * ldA;
    const bf16* Bb = B + (long long)z * sB + (long long)blockIdx.x * BN * ldB;
    uint32_t smu = smem_u32(sm);

    float acc[4][NT][4];
#pragma unroll
    for (int i = 0; i < 4; i++)
#pragma unroll
        for (int j = 0; j < NT; j++)
#pragma unroll
            for (int k = 0; k < 4; k++) acc[i][j][k] = 0.f;

    int wid = tid >> 5, lane = tid & 31;
    int wm = (wid >> 2) * 64;
    int wn = (wid & 3) * (BN / 4);

    int nch = K / BK;

    // prefetch stage 0
    {
        uint32_t base = smu;
        for (int i = tid; i < TCH; i += 256) {
            if (i < ACH) {
                int row = i >> 2, c16 = i & 3;
                CPASYNC16(base + (uint32_t)(row * RST + c16 * 8) * 2,
                          Ab + (long long)row * ldA + c16 * 8);
            } else {
                int j = i - ACH;
                int row = j >> 2, c16 = j & 3;
                CPASYNC16(base + (uint32_t)(SSA + row * RST + c16 * 8) * 2,
                          Bb + (long long)row * ldB + c16 * 8);
            }
        }
        CPCOMMIT();
    }

    for (int c = 0; c < nch; c++) {
        int s = c & 1;
        if (c + 1 < nch) {
            int kof = (c + 1) * BK;
            uint32_t base = smu + (uint32_t)((s ^ 1) * SS) * 2;
            for (int i = tid; i < TCH; i += 256) {
                if (i < ACH) {
                    int row = i >> 2, c16 = i & 3;
                    CPASYNC16(base + (uint32_t)(row * RST + c16 * 8) * 2,
                              Ab + (long long)row * ldA + kof + c16 * 8);
                } else {
                    int j = i - ACH;
                    int row = j >> 2, c16 = j & 3;
                    CPASYNC16(base + (uint32_t)(SSA + row * RST + c16 * 8) * 2,
                              Bb + (long long)row * ldB + kof + c16 * 8);
                }
            }
            CPCOMMIT();
            CPWAIT(1);
        } else {
            CPWAIT(0);
        }
        __syncthreads();

        uint32_t Abase = smu + (uint32_t)(s * SS) * 2;
        uint32_t Bbase = Abase + (uint32_t)SSA * 2;
#pragma unroll
        for (int ks = 0; ks < 2; ks++) {
            uint32_t a[4][4], b[NT][2];
#pragma unroll
            for (int mt = 0; mt < 4; mt++) {
                uint32_t ad = Abase + (uint32_t)((wm + mt * 16 + (lane & 15)) * RST + ks * 16 + (lane >> 4) * 8) * 2;
                ldsm4(a[mt], ad);
            }
#pragma unroll
            for (int nt = 0; nt < NT; nt++) {
                int l = lane & 15;
                uint32_t bd = Bbase + (uint32_t)((wn + nt * 8 + (l & 7)) * RST + ks * 16 + ((l >> 3) & 1) * 8) * 2;
                ldsm2(b[nt], bd);
            }
#pragma unroll
            for (int mt = 0; mt < 4; mt++)
#pragma unroll
                for (int nt = 0; nt < NT; nt++)
                    mma16816(acc[mt][nt], a[mt], b[nt]);
        }
        __syncthreads();
    }

    // ---------------- epilogue (direct from registers) ----------------
    int m0 = blockIdx.y * BM, n0 = blockIdx.x * BN;
#pragma unroll
    for (int mt = 0; mt < 4; mt++)
#pragma unroll
        for (int nt = 0; nt < NT; nt++)
#pragma unroll
            for (int h2 = 0; h2 < 2; h2++) {
                int gm = m0 + wm + mt * 16 + (lane >> 2) + h2 * 8;
                int gn = n0 + wn + nt * 8 + ((lane & 3) << 1);
                float v0 = acc[mt][nt][h2 * 2];
                float v1 = acc[mt][nt][h2 * 2 + 1];
                if (EPI == 0) {
                    bf16* p = outB + (long long)z * sC + (long long)gm * ldC + gn;
                    *(bf162*)p = __floats2bfloat162_rn(v0, v1);
                } else if (EPI == 1) {
                    long long o = (long long)gm * ldC + gn;
                    outF[o]     = v0 + bias[gn]     + res[o];
                    outF[o + 1] = v1 + bias[gn + 1] + res[o + 1];
                } else if (EPI == 2) {
                    float a0 = gelu_exact(v0 + bias[gn]);
                    float a1 = gelu_exact(v1 + bias[gn + 1]);
                    bf16* p = outB + (long long)gm * ldC + gn;
                    *(bf162*)p = __floats2bfloat162_rn(a0, a1);
                } else if (EPI == 3) {
                    float a0 = v0 + bias[gn];
                    float a1 = v1 + bias[gn + 1];
                    int pp = gn / DMODEL;
                    int c2 = gn - pp * DMODEL;
                    int h = c2 >> 6, j = c2 & 63;
                    int b_ = gm >> 11, m = gm & 2047;
                    bf16* pl = (pp == 0 ? g_q : (pp == 1 ? g_k : g_v))
                             + (((long long)(b_ * NHEAD + h) << 11) + m) * DH + j;
                    *(bf162*)pl = __floats2bfloat162_rn(a0, a1);
                } else if (EPI == 4) {
                    int b_ = z / NHEAD, h = z - b_ * NHEAD;
                    bf16* pl = g_attnb + ((long long)(b_ * SEQ + gm)) * DMODEL + h * DH + gn;
                    *(bf162*)pl = __floats2bfloat162_rn(v0, v1);
                }
            }
}

// ---------------- fp32 -> bf16 convert ----------------
__global__ void f2b_kernel(const float* __restrict__ src, bf16* __restrict__ dst, long long n2)
{
    long long i = (long long)blockIdx.x * blockDim.x + threadIdx.x;
    if (i >= n2) return;
    float2 v = ((const float2*)src)[i];
    ((bf162*)dst)[i] = __floats2bfloat162_rn(v.x, v.y);
}

// ---------------- fuse low-rank QKV weights (transposed, bf16) ----------------
__global__ void fuse_w_kernel(const float* __restrict__ Pq, const float* __restrict__ Vq, const float* __restrict__ bq,
                              const float* __restrict__ Pk, const float* __restrict__ Vk, const float* __restrict__ bk,
                              const float* __restrict__ Pv, const float* __restrict__ Vv, const float* __restrict__ bv)
{
    int idx = blockIdx.x * blockDim.x + threadIdx.x;
    if (idx >= DMODEL * QKVN) return;
    int c = idx / DMODEL;
    int d = idx - c * DMODEL;
    int p = c / DMODEL;
    int c2 = c - p * DMODEL;
    int h = c2 >> 6, j = c2 & 63;
    const float* P = (p == 0) ? Pq : (p == 1) ? Pk : Pv;
    const float* V = (p == 0) ? Vq : (p == 1) ? Vk : Vv;
    const float* Bv_ = (p == 0) ? bq : (p == 1) ? bk : bv;
    const float* Ph = P + (size_t)h * DMODEL * 32 + (size_t)d * 32;
    const float* Vh = V + (size_t)h * 32 * DH + j;
    float s = 0.f;
#pragma unroll
    for (int r = 0; r < 32; r++) s += Ph[r] * Vh[(size_t)r * DH];
    g_Wtb[(size_t)c * DMODEL + d] = __float2bfloat16(s);
    if (d == 0) g_bqkv[c] = Bv_[h * DH + j];
}

// ---------------- weight transpose fp32 -> bf16 ----------------
__global__ void transpose_b16(const float* __restrict__ src, bf16* __restrict__ dst, int R, int C)
{
    __shared__ float t[32][33];
    int c0 = blockIdx.x * 32, r0 = blockIdx.y * 32;
    int x = threadIdx.x, y = threadIdx.y;
    for (int i = 0; i < 32; i += 8) t[y + i][x] = src[(size_t)(r0 + y + i) * C + c0 + x];
    __syncthreads();
    for (int i = 0; i < 32; i += 8) dst[(size_t)(c0 + y + i) * R + r0 + x] = __float2bfloat16(t[x][y + i]);
}

// ---------------- V plane transpose: g_vt[z][j][m] = g_v[z][m][j] ----------------
__global__ void vt_kernel()
{
    __shared__ bf16 t[32][34];
    int z = blockIdx.z;
    int m0 = blockIdx.x * 32, j0 = blockIdx.y * 32;
    int x = threadIdx.x, y = threadIdx.y;
    for (int i = 0; i < 32; i += 8)
        t[y + i][x] = g_v[((size_t)z * SEQ + m0 + y + i) * DH + j0 + x];
    __syncthreads();
    for (int i = 0; i < 32; i += 8)
        g_vt[((size_t)z * DH + j0 + y + i) * SEQ + m0 + x] = t[x][y + i];
}

// ---------------- softmax in-place on bf16 S ----------------
__global__ __launch_bounds__(256) void softmax_kernel(const float* __restrict__ mask)
{
    int m = blockIdx.x, z = blockIdx.y;
    int b = z / NHEAD;
    bf162* row = (bf162*)(g_S + ((size_t)z * SEQ + m) * SEQ);
    const float* mrow = mask + (size_t)b * SEQ;
    int t = threadIdx.x;
    float v[8];
    float mx = -1e30f;
#pragma unroll
    for (int i = 0; i < 4; i++) {
        int p = t + i * 256;
        bf162 d = row[p];
        float lo = __bfloat162float(d.x) * 0.125f + mrow[2 * p];
        float hi = __bfloat162float(d.y) * 0.125f + mrow[2 * p + 1];
        v[2 * i] = lo; v[2 * i + 1] = hi;
        mx = fmaxf(mx, fmaxf(lo, hi));
    }
    __shared__ float red[8];
#pragma unroll
    for (int o = 16; o > 0; o >>= 1) mx = fmaxf(mx, __shfl_xor_sync(0xffffffffu, mx, o));
    if ((t & 31) == 0) red[t >> 5] = mx;
    __syncthreads();
    mx = red[0];
#pragma unroll
    for (int w = 1; w < 8; w++) mx = fmaxf(mx, red[w]);
    float s = 0.f;
#pragma unroll
    for (int i = 0; i < 8; i++) { float e = __expf(v[i] - mx); v[i] = e; s += e; }
#pragma unroll
    for (int o = 16; o > 0; o >>= 1) s += __shfl_xor_sync(0xffffffffu, s, o);
    __syncthreads();
    if ((t & 31) == 0) red[t >> 5] = s;
    __syncthreads();
    s = 0.f;
#pragma unroll
    for (int w = 0; w < 8; w++) s += red[w];
    float inv = 1.f / s;
#pragma unroll
    for (int i = 0; i < 4; i++) {
        int p = t + i * 256;
        row[p] = __floats2bfloat162_rn(v[2 * i] * inv, v[2 * i + 1] * inv);
    }
}

// ---------------- LayerNorm (fp32 out + optional bf16 out) ----------------
__global__ __launch_bounds__(256) void ln_kernel(const float* __restrict__ in,
                                                 const float* __restrict__ gam,
                                                 const float* __restrict__ bet,
                                                 float* __restrict__ outF,
                                                 bf16* __restrict__ outB)
{
    int row = blockIdx.x;
    int t = threadIdx.x;
    const float* ip = in + (size_t)row * DMODEL;
    float x0 = ip[t], x1 = ip[t + 256], x2 = ip[t + 512];
    __shared__ float rs[256], rq[256];
    rs[t] = x0 + x1 + x2;
    rq[t] = x0 * x0 + x1 * x1 + x2 * x2;
    __syncthreads();
    for (int off = 128; off > 0; off >>= 1) {
        if (t < off) { rs[t] += rs[t + off]; rq[t] += rq[t + off]; }
        __syncthreads();
    }
    float mu = rs[0] * (1.f / 768.f);
    float var = rq[0] * (1.f / 768.f) - mu * mu;
    float rstd = rsqrtf(var + 1e-12f);
    float y0 = (x0 - mu) * rstd * gam[t] + bet[t];
    float y1 = (x1 - mu) * rstd * gam[t + 256] + bet[t + 256];
    float y2 = (x2 - mu) * rstd * gam[t + 512] + bet[t + 512];
    float* op = outF + (size_t)row * DMODEL;
    op[t] = y0; op[t + 256] = y1; op[t + 512] = y2;
    if (outB) {
        bf16* ob = outB + (size_t)row * DMODEL;
        ob[t] = __float2bfloat16(y0);
        ob[t + 256] = __float2bfloat16(y1);
        ob[t + 512] = __float2bfloat16(y2);
    }
}

// ---------------- launch ----------------
extern "C" void kernel_launch(void* const* d_in, const int* in_sizes, int n_in,
                              void* d_out, int out_size)
{
    const float* x    = (const float*)d_in[0];
    const float* mask = (const float*)d_in[1];
    const float* Pq = (const float*)d_in[2];
    const float* Vq = (const float*)d_in[3];
    const float* bq = (const float*)d_in[4];
    const float* Pk = (const float*)d_in[5];
    const float* Vk = (const float*)d_in[6];
    const float* bk = (const float*)d_in[7];
    const float* Pv = (const float*)d_in[8];
    const float* Vv = (const float*)d_in[9];
    const float* bv = (const float*)d_in[10];
    const float* Uo = (const float*)d_in[11];
    const float* Vo = (const float*)d_in[12];
    const float* bo = (const float*)d_in[13];
    const float* U1 = (const float*)d_in[14];
    const float* V1 = (const float*)d_in[15];
    const float* b1 = (const float*)d_in[16];
    const float* U2 = (const float*)d_in[17];
    const float* V2 = (const float*)d_in[18];
    const float* b2 = (const float*)d_in[19];
    const float* g1 = (const float*)d_in[20];
    const float* be1 = (const float*)d_in[21];
    const float* g2 = (const float*)d_in[22];
    const float* be2 = (const float*)d_in[23];

    float *bqkv, *pre, *x1f;
    bf16 *xb, *Wtb, *q, *k, *vt, *S, *attnb, *t256b, *mid, *x1b;
    bf16 *Uot, *Vot, *U1t, *V1t, *U2t, *V2t;
    cudaGetSymbolAddress((void**)&xb,    g_xb);
    cudaGetSymbolAddress((void**)&Wtb,   g_Wtb);
    cudaGetSymbolAddress((void**)&bqkv,  g_bqkv);
    cudaGetSymbolAddress((void**)&q,     g_q);
    cudaGetSymbolAddress((void**)&k,     g_k);
    cudaGetSymbolAddress((void**)&vt,    g_vt);
    cudaGetSymbolAddress((void**)&S,     g_S);
    cudaGetSymbolAddress((void**)&attnb, g_attnb);
    cudaGetSymbolAddress((void**)&t256b, g_t256b);
    cudaGetSymbolAddress((void**)&mid,   g_mid);
    cudaGetSymbolAddress((void**)&pre,   g_pre);
    cudaGetSymbolAddress((void**)&x1f,   g_x1);
    cudaGetSymbolAddress((void**)&x1b,   g_x1b);
    cudaGetSymbolAddress((void**)&Uot,   g_Uot);
    cudaGetSymbolAddress((void**)&Vot,   g_Vot);
    cudaGetSymbolAddress((void**)&U1t,   g_U1t);
    cudaGetSymbolAddress((void**)&V1t,   g_V1t);
    cudaGetSymbolAddress((void**)&U2t,   g_U2t);
    cudaGetSymbolAddress((void**)&V2t,   g_V2t);

    dim3 tb(32, 8);
    const long long SS2 = (long long)SEQ * SEQ;

    // prep
    f2b_kernel<<<(NTOK * DMODEL / 2 + 255) / 256, 256>>>(x, xb, (long long)NTOK * DMODEL / 2);
    fuse_w_kernel<<<(DMODEL * QKVN + 255) / 256, 256>>>(Pq, Vq, bq, Pk, Vk, bk, Pv, Vv, bv);
    transpose_b16<<<dim3(256 / 32, DMODEL / 32), tb>>>(Uo, Uot, DMODEL, 256);
    transpose_b16<<<dim3(DMODEL / 32, 256 / 32), tb>>>(Vo, Vot, 256, DMODEL);
    transpose_b16<<<dim3(256 / 32, DMODEL / 32), tb>>>(U1, U1t, DMODEL, 256);
    transpose_b16<<<dim3(FDIM / 32, 256 / 32), tb>>>(V1, V1t, 256, FDIM);
    transpose_b16<<<dim3(256 / 32, FDIM / 32), tb>>>(U2, U2t, FDIM, 256);
    transpose_b16<<<dim3(DMODEL / 32, 256 / 32), tb>>>(V2, V2t, 256, DMODEL);

    // 1) QKV = xb @ Wtb^T + bias -> q/k/v planes (bf16)
    bmma_gemm<128, 3><<<dim3(QKVN / 128, NTOK / 128, 1), 256>>>(
        xb, Wtb, DMODEL, DMODEL, DMODEL, 0, 0,
        nullptr, nullptr, bqkv, nullptr, 0, 0);

    // 2) V^T plane
    vt_kernel<<<dim3(SEQ / 32, DH / 32, BH), tb>>>();

    // 3) S = q @ k^T (bf16 out, batched)
    bmma_gemm<128, 0><<<dim3(SEQ / 128, SEQ / 128, BH), 256>>>(
        q, k, DH, DH, DH, (long long)SEQ * DH, (long long)SEQ * DH,
        nullptr, S, nullptr, nullptr, SEQ, SS2);

    // 4) softmax in place (S -> P)
    softmax_kernel<<<dim3(SEQ, BH), 256>>>(mask);

    // 5) attn = P @ V -> g_attnb scatter
    bmma_gemm<64, 4><<<dim3(1, SEQ / 128, BH), 256>>>(
        S, vt, SEQ, SEQ, SEQ, SS2, (long long)DH * SEQ,
        nullptr, nullptr, nullptr, nullptr, 0, 0);

    // 6) t = attn @ Uo
    bmma_gemm<128, 0><<<dim3(2, NTOK / 128, 1), 256>>>(
        attnb, Uot, DMODEL, DMODEL, DMODEL, 0, 0,
        nullptr, t256b, nullptr, nullptr, 256, 0);
    // 7) pre1 = t @ Vo + bo + x
    bmma_gemm<128, 1><<<dim3(DMODEL / 128, NTOK / 128, 1), 256>>>(
        t256b, Vot, 256, 256, 256, 0, 0,
        pre, nullptr, bo, x, DMODEL, 0);
    // 8) LN1 -> x1 (fp32 + bf16)
    ln_kernel<<<NTOK, 256>>>(pre, g1, be1, x1f, x1b);
    // 9) t = x1 @ U1
    bmma_gemm<128, 0><<<dim3(2, NTOK / 128, 1), 256>>>(
        x1b, U1t, DMODEL, DMODEL, DMODEL, 0, 0,
        nullptr, t256b, nullptr, nullptr, 256, 0);
    // 10) mid = gelu(t @ V1 + b1) -> bf16
    bmma_gemm<128, 2><<<dim3(FDIM / 128, NTOK / 128, 1), 256>>>(
        t256b, V1t, 256, 256, 256, 0, 0,
        nullptr, mid, b1, nullptr, FDIM, 0);
    // 11) t = mid @ U2
    bmma_gemm<128, 0><<<dim3(2, NTOK / 128, 1), 256>>>(
        mid, U2t, FDIM, FDIM, FDIM, 0, 0,
        nullptr, t256b, nullptr, nullptr, 256, 0);
    // 12) pre2 = t @ V2 + b2 + x1
    bmma_gemm<128, 1><<<dim3(DMODEL / 128, NTOK / 128, 1), 256>>>(
        t256b, V2t, 256, 256, 256, 0, 0,
        pre, nullptr, b2, x1f, DMODEL, 0);
    // 13) LN2 -> out (fp32)
    ln_kernel<<<NTOK, 256>>>(pre, g2, be2, (float*)d_out, nullptr);
}

// round 8
// speedup vs baseline: 8.0747x; 1.3128x over previous
#include <cuda_runtime.h>
#include <cuda_bf16.h>
#include <math.h>
#include <stdint.h>

// ---------------- problem constants ----------------
#define BATCH 4
#define SEQ   2048
#define DMODEL 768
#define NHEAD 12
#define DH    64
#define NTOK  (BATCH*SEQ)          // 8192
#define QKVN  (3*DMODEL)           // 2304
#define FDIM  3072
#define BH    (BATCH*NHEAD)        // 48

typedef __nv_bfloat16 bf16;
typedef __nv_bfloat162 bf162;

// ---------------- scratch (__device__ globals; no allocation) ----------------
__device__ bf16 g_xb[(size_t)NTOK*DMODEL];
__device__ bf16 g_Wtb[(size_t)QKVN*DMODEL];            // [2304][768]
__device__ float g_bqkv[QKVN];
__device__ bf16 g_q[(size_t)BH*SEQ*DH];                // [48][2048][64]
__device__ bf16 g_k[(size_t)BH*SEQ*DH];
__device__ bf16 g_v[(size_t)BH*SEQ*DH];
__device__ bf16 g_attnb[(size_t)NTOK*DMODEL];
__device__ bf16 g_t256b[(size_t)NTOK*256];
__device__ bf16 g_mid[(size_t)NTOK*FDIM];
__device__ float g_pre[(size_t)NTOK*DMODEL];
__device__ float g_x1[(size_t)NTOK*DMODEL];
__device__ bf16 g_x1b[(size_t)NTOK*DMODEL];
__device__ bf16 g_Uot[256*DMODEL];
__device__ bf16 g_Vot[DMODEL*256];
__device__ bf16 g_U1t[256*DMODEL];
__device__ bf16 g_V1t[FDIM*256];
__device__ bf16 g_U2t[256*FDIM];
__device__ bf16 g_V2t[DMODEL*256];

// ---------------- PTX helpers (base ISA only: sm_80-compatible) ----------------
__device__ __forceinline__ uint32_t smem_u32(const void* p) {
    uint32_t a;
    asm("{ .reg .u64 t; cvta.to.shared.u64 t, %1; cvt.u32.u64 %0, t; }" : "=r"(a) : "l"(p));
    return a;
}
__device__ __forceinline__ uint32_t pack_bf16x2(float lo, float hi) {
    uint32_t r;
    asm("cvt.rn.bf16x2.f32 %0, %1, %2;" : "=r"(r) : "f"(hi), "f"(lo));
    return r;
}
#define CPASYNC16(dst, src) asm volatile("cp.async.cg.shared.global [%0], [%1], 16;" :: "r"(dst), "l"(src))
#define CPCOMMIT()          asm volatile("cp.async.commit_group;" ::: "memory")
#define CPWAIT(n)           asm volatile("cp.async.wait_group %0;" :: "n"(n) : "memory")

__device__ __forceinline__ void ldsm4(uint32_t* r, uint32_t a) {
    asm volatile("ldmatrix.sync.aligned.m8n8.x4.shared.b16 {%0,%1,%2,%3}, [%4];"
        : "=r"(r[0]), "=r"(r[1]), "=r"(r[2]), "=r"(r[3]) : "r"(a));
}
__device__ __forceinline__ void ldsm2(uint32_t* r, uint32_t a) {
    asm volatile("ldmatrix.sync.aligned.m8n8.x2.shared.b16 {%0,%1}, [%2];"
        : "=r"(r[0]), "=r"(r[1]) : "r"(a));
}
__device__ __forceinline__ void ldsm2t(uint32_t* r, uint32_t a) {
    asm volatile("ldmatrix.sync.aligned.m8n8.x2.trans.shared.b16 {%0,%1}, [%2];"
        : "=r"(r[0]), "=r"(r[1]) : "r"(a));
}
__device__ __forceinline__ void mma16816(float* c, const uint32_t* a, const uint32_t* b) {
    asm volatile("mma.sync.aligned.m16n8k16.row.col.f32.bf16.bf16.f32 "
        "{%0,%1,%2,%3}, {%4,%5,%6,%7}, {%8,%9}, {%0,%1,%2,%3};"
        : "+f"(c[0]), "+f"(c[1]), "+f"(c[2]), "+f"(c[3])
        : "r"(a[0]), "r"(a[1]), "r"(a[2]), "r"(a[3]), "r"(b[0]), "r"(b[1]));
}

__device__ __forceinline__ float gelu_exact(float a) {
    return 0.5f * a * (1.f + erff(a * 0.70710678118654752f));
}

// ---------------- generic bf16 mma GEMM: C[128 x BN] = A[M,K] @ B[N,K]^T ----------------
// EPI: 0 = bf16 out
//      1 = f32 out = v + bias[gn] + res[...]
//      2 = bf16 out = gelu(v + bias[gn])
//      3 = QKV scatter (+bias) into g_q/g_k/g_v planes
#define BM 128
#define BK 32
#define RST 40

template<int BN, int EPI>
__global__ __launch_bounds__(256) void bmma_gemm(
    const bf16* __restrict__ A, const bf16* __restrict__ B,
    int K, int ldA, int ldB, long long sA, long long sB,
    float* __restrict__ outF, bf16* __restrict__ outB,
    const float* __restrict__ bias, const float* __restrict__ res,
    int ldC, long long sC)
{
    constexpr int NT = BN / 32;
    constexpr int ACH = BM * 4;
    constexpr int TCH = (BM + BN) * 4;
    constexpr int SSA = BM * RST;
    constexpr int SS  = (BM + BN) * RST;

    __shared__ bf16 sm[2 * SS];

    int tid = threadIdx.x;
    int z = blockIdx.z;
    const bf16* Ab = A + (long long)z * sA + (long long)blockIdx.y * BM * ldA;
    const bf16* Bb = B + (long long)z * sB + (long long)blockIdx.x * BN * ldB;
    uint32_t smu = smem_u32(sm);

    float acc[4][NT][4];
#pragma unroll
    for (int i = 0; i < 4; i++)
#pragma unroll
        for (int j = 0; j < NT; j++)
#pragma unroll
            for (int k = 0; k < 4; k++) acc[i][j][k] = 0.f;

    int wid = tid >> 5, lane = tid & 31;
    int wm = (wid >> 2) * 64;
    int wn = (wid & 3) * (BN / 4);

    int nch = K / BK;

    {
        uint32_t base = smu;
        for (int i = tid; i < TCH; i += 256) {
            if (i < ACH) {
                int row = i >> 2, c16 = i & 3;
                CPASYNC16(base + (uint32_t)(row * RST + c16 * 8) * 2,
                          Ab + (long long)row * ldA + c16 * 8);
            } else {
                int j = i - ACH;
                int row = j >> 2, c16 = j & 3;
                CPASYNC16(base + (uint32_t)(SSA + row * RST + c16 * 8) * 2,
                          Bb + (long long)row * ldB + c16 * 8);
            }
        }
        CPCOMMIT();
    }

    for (int c = 0; c < nch; c++) {
        int s = c & 1;
        if (c + 1 < nch) {
            int kof = (c + 1) * BK;
            uint32_t base = smu + (uint32_t)((s ^ 1) * SS) * 2;
            for (int i = tid; i < TCH; i += 256) {
                if (i < ACH) {
                    int row = i >> 2, c16 = i & 3;
                    CPASYNC16(base + (uint32_t)(row * RST + c16 * 8) * 2,
                              Ab + (long long)row * ldA + kof + c16 * 8);
                } else {
                    int j = i - ACH;
                    int row = j >> 2, c16 = j & 3;
                    CPASYNC16(base + (uint32_t)(SSA + row * RST + c16 * 8) * 2,
                              Bb + (long long)row * ldB + kof + c16 * 8);
                }
            }
            CPCOMMIT();
            CPWAIT(1);
        } else {
            CPWAIT(0);
        }
        __syncthreads();

        uint32_t Abase = smu + (uint32_t)(s * SS) * 2;
        uint32_t Bbase = Abase + (uint32_t)SSA * 2;
#pragma unroll
        for (int ks = 0; ks < 2; ks++) {
            uint32_t a[4][4], b[NT][2];
#pragma unroll
            for (int mt = 0; mt < 4; mt++) {
                uint32_t ad = Abase + (uint32_t)((wm + mt * 16 + (lane & 15)) * RST + ks * 16 + (lane >> 4) * 8) * 2;
                ldsm4(a[mt], ad);
            }
#pragma unroll
            for (int nt = 0; nt < NT; nt++) {
                int l = lane & 15;
                uint32_t bd = Bbase + (uint32_t)((wn + nt * 8 + (l & 7)) * RST + ks * 16 + ((l >> 3) & 1) * 8) * 2;
                ldsm2(b[nt], bd);
            }
#pragma unroll
            for (int mt = 0; mt < 4; mt++)
#pragma unroll
                for (int nt = 0; nt < NT; nt++)
                    mma16816(acc[mt][nt], a[mt], b[nt]);
        }
        __syncthreads();
    }

    int m0 = blockIdx.y * BM, n0 = blockIdx.x * BN;
#pragma unroll
    for (int mt = 0; mt < 4; mt++)
#pragma unroll
        for (int nt = 0; nt < NT; nt++)
#pragma unroll
            for (int h2 = 0; h2 < 2; h2++) {
                int gm = m0 + wm + mt * 16 + (lane >> 2) + h2 * 8;
                int gn = n0 + wn + nt * 8 + ((lane & 3) << 1);
                float v0 = acc[mt][nt][h2 * 2];
                float v1 = acc[mt][nt][h2 * 2 + 1];
                if (EPI == 0) {
                    bf16* p = outB + (long long)z * sC + (long long)gm * ldC + gn;
                    *(uint32_t*)p = pack_bf16x2(v0, v1);
                } else if (EPI == 1) {
                    long long o = (long long)gm * ldC + gn;
                    outF[o]     = v0 + bias[gn]     + res[o];
                    outF[o + 1] = v1 + bias[gn + 1] + res[o + 1];
                } else if (EPI == 2) {
                    float a0 = gelu_exact(v0 + bias[gn]);
                    float a1 = gelu_exact(v1 + bias[gn + 1]);
                    bf16* p = outB + (long long)gm * ldC + gn;
                    *(uint32_t*)p = pack_bf16x2(a0, a1);
                } else if (EPI == 3) {
                    float a0 = v0 + bias[gn];
                    float a1 = v1 + bias[gn + 1];
                    int pp = gn / DMODEL;
                    int c2 = gn - pp * DMODEL;
                    int h = c2 >> 6, j = c2 & 63;
                    int b_ = gm >> 11, m = gm & 2047;
                    bf16* pl = (pp == 0 ? g_q : (pp == 1 ? g_k : g_v))
                             + (((long long)(b_ * NHEAD + h) << 11) + m) * DH + j;
                    *(uint32_t*)pl = pack_bf16x2(a0, a1);
                }
            }
}

// ---------------- flash attention: 128 Q rows/CTA, KV tiles of 64, online softmax ----------------
#define FBN 64
#define KVP 72   // smem pitch (elems)

__global__ __launch_bounds__(256) void flash_kernel(const float* __restrict__ mask)
{
    __shared__ bf16 Ks[2][FBN * KVP];
    __shared__ bf16 Vs[2][FBN * KVP];
    __shared__ float Ms[2][FBN];

    int z = blockIdx.y;
    int bq = z / NHEAD, h = z - bq * NHEAD;
    int m0 = blockIdx.x * 128;
    int tid = threadIdx.x, wid = tid >> 5, lane = tid & 31;
    int wm = wid * 16;

    const bf16* Qg = g_q + ((size_t)z * SEQ + m0) * DH;
    const bf16* Kg = g_k + (size_t)z * SEQ * DH;
    const bf16* Vg = g_v + (size_t)z * SEQ * DH;
    const float* mg = mask + (size_t)bq * SEQ;

    uint32_t ks0 = smem_u32(Ks), vs0 = smem_u32(Vs), ms0 = smem_u32(Ms);

    // Q a-fragments straight from gmem (one-time)
    uint32_t qa[4][4];
    {
        const bf16* q0 = Qg + (size_t)(wm + (lane >> 2)) * DH + ((lane & 3) << 1);
#pragma unroll
        for (int t = 0; t < 4; t++) {
            qa[t][0] = *(const uint32_t*)(q0 + t * 16);
            qa[t][1] = *(const uint32_t*)(q0 + 8 * DH + t * 16);
            qa[t][2] = *(const uint32_t*)(q0 + t * 16 + 8);
            qa[t][3] = *(const uint32_t*)(q0 + 8 * DH + t * 16 + 8);
        }
    }

    // prefetch helper
    auto prefetch = [&](int s, int n0) {
        uint32_t kb = ks0 + (uint32_t)(s * FBN * KVP) * 2;
        uint32_t vb = vs0 + (uint32_t)(s * FBN * KVP) * 2;
        for (int i = tid; i < FBN * 8; i += 256) {
            int r = i >> 3, c = (i & 7) << 3;
            CPASYNC16(kb + (uint32_t)(r * KVP + c) * 2, Kg + (size_t)(n0 + r) * DH + c);
            CPASYNC16(vb + (uint32_t)(r * KVP + c) * 2, Vg + (size_t)(n0 + r) * DH + c);
        }
        if (tid < 16)
            CPASYNC16(ms0 + (uint32_t)(s * FBN + tid * 4) * 4, mg + n0 + tid * 4);
    };

    prefetch(0, 0);
    CPCOMMIT();

    float o[8][4];
#pragma unroll
    for (int i = 0; i < 8; i++)
#pragma unroll
        for (int j = 0; j < 4; j++) o[i][j] = 0.f;
    float mi0 = -1e30f, mi1 = -1e30f, li0 = 0.f, li1 = 0.f;

    for (int s = 0; s < SEQ / FBN; s++) {
        int buf = s & 1;
        if (s + 1 < SEQ / FBN) {
            prefetch(buf ^ 1, (s + 1) * FBN);
            CPCOMMIT();
            CPWAIT(1);
        } else {
            CPWAIT(0);
        }
        __syncthreads();

        uint32_t kb = ks0 + (uint32_t)(buf * FBN * KVP) * 2;
        uint32_t vb = vs0 + (uint32_t)(buf * FBN * KVP) * 2;

        // S = Q @ K^T  (16 x 64 per warp, fp32)
        float c[8][4];
#pragma unroll
        for (int nt = 0; nt < 8; nt++)
#pragma unroll
            for (int i = 0; i < 4; i++) c[nt][i] = 0.f;
        int l = lane & 15;
#pragma unroll
        for (int t = 0; t < 4; t++) {
#pragma unroll
            for (int nt = 0; nt < 8; nt++) {
                uint32_t b[2];
                ldsm2(b, kb + (uint32_t)((nt * 8 + (l & 7)) * KVP + t * 16 + ((l >> 3) & 1) * 8) * 2);
                mma16816(c[nt], qa[t], b);
            }
        }

        // scale + mask + online softmax
        float mx0 = -1e30f, mx1 = -1e30f;
#pragma unroll
        for (int nt = 0; nt < 8; nt++) {
            int col = nt * 8 + ((lane & 3) << 1);
            float mk0 = Ms[buf][col], mk1 = Ms[buf][col + 1];
            c[nt][0] = c[nt][0] * 0.125f + mk0;
            c[nt][1] = c[nt][1] * 0.125f + mk1;
            c[nt][2] = c[nt][2] * 0.125f + mk0;
            c[nt][3] = c[nt][3] * 0.125f + mk1;
            mx0 = fmaxf(mx0, fmaxf(c[nt][0], c[nt][1]));
            mx1 = fmaxf(mx1, fmaxf(c[nt][2], c[nt][3]));
        }
        mx0 = fmaxf(mx0, __shfl_xor_sync(0xffffffffu, mx0, 1));
        mx0 = fmaxf(mx0, __shfl_xor_sync(0xffffffffu, mx0, 2));
        mx1 = fmaxf(mx1, __shfl_xor_sync(0xffffffffu, mx1, 1));
        mx1 = fmaxf(mx1, __shfl_xor_sync(0xffffffffu, mx1, 2));
        float nm0 = fmaxf(mi0, mx0), nm1 = fmaxf(mi1, mx1);
        float a0 = __expf(mi0 - nm0), a1 = __expf(mi1 - nm1);
        float s0 = 0.f, s1 = 0.f;
#pragma unroll
        for (int nt = 0; nt < 8; nt++) {
            c[nt][0] = __expf(c[nt][0] - nm0);
            c[nt][1] = __expf(c[nt][1] - nm0);
            c[nt][2] = __expf(c[nt][2] - nm1);
            c[nt][3] = __expf(c[nt][3] - nm1);
            s0 += c[nt][0] + c[nt][1];
            s1 += c[nt][2] + c[nt][3];
        }
        s0 += __shfl_xor_sync(0xffffffffu, s0, 1);
        s0 += __shfl_xor_sync(0xffffffffu, s0, 2);
        s1 += __shfl_xor_sync(0xffffffffu, s1, 1);
        s1 += __shfl_xor_sync(0xffffffffu, s1, 2);
        li0 = li0 * a0 + s0;
        li1 = li1 * a1 + s1;
        mi0 = nm0; mi1 = nm1;
#pragma unroll
        for (int dt = 0; dt < 8; dt++) {
            o[dt][0] *= a0; o[dt][1] *= a0;
            o[dt][2] *= a1; o[dt][3] *= a1;
        }

        // O += P @ V   (P packed bf16 from c, V b-frags via trans ldmatrix)
#pragma unroll
        for (int t = 0; t < 4; t++) {
            uint32_t pa[4];
            pa[0] = pack_bf16x2(c[2 * t][0], c[2 * t][1]);
            pa[1] = pack_bf16x2(c[2 * t][2], c[2 * t][3]);
            pa[2] = pack_bf16x2(c[2 * t + 1][0], c[2 * t + 1][1]);
            pa[3] = pack_bf16x2(c[2 * t + 1][2], c[2 * t + 1][3]);
#pragma unroll
            for (int dt = 0; dt < 8; dt++) {
                uint32_t b[2];
                ldsm2t(b, vb + (uint32_t)((t * 16 + l) * KVP + dt * 8) * 2);
                mma16816(o[dt], pa, b);
            }
        }
        __syncthreads();
    }

    // epilogue
    float inv0 = 1.f / li0, inv1 = 1.f / li1;
    int r0 = m0 + wm + (lane >> 2);
    bf16* out0 = g_attnb + ((size_t)(bq * SEQ + r0)) * DMODEL + h * DH;
    bf16* out1 = out0 + (size_t)8 * DMODEL;
#pragma unroll
    for (int dt = 0; dt < 8; dt++) {
        int col = dt * 8 + ((lane & 3) << 1);
        *(uint32_t*)(out0 + col) = pack_bf16x2(o[dt][0] * inv0, o[dt][1] * inv0);
        *(uint32_t*)(out1 + col) = pack_bf16x2(o[dt][2] * inv1, o[dt][3] * inv1);
    }
}

// ---------------- fp32 -> bf16 convert ----------------
__global__ void f2b_kernel(const float* __restrict__ src, bf16* __restrict__ dst, long long n2)
{
    long long i = (long long)blockIdx.x * blockDim.x + threadIdx.x;
    if (i >= n2) return;
    float2 v = ((const float2*)src)[i];
    ((uint32_t*)dst)[i] = pack_bf16x2(v.x, v.y);
}

// ---------------- fuse low-rank QKV weights (transposed, bf16) ----------------
__global__ void fuse_w_kernel(const float* __restrict__ Pq, const float* __restrict__ Vq, const float* __restrict__ bq,
                              const float* __restrict__ Pk, const float* __restrict__ Vk, const float* __restrict__ bk,
                              const float* __restrict__ Pv, const float* __restrict__ Vv, const float* __restrict__ bv)
{
    int idx = blockIdx.x * blockDim.x + threadIdx.x;
    if (idx >= DMODEL * QKVN) return;
    int c = idx / DMODEL;
    int d = idx - c * DMODEL;
    int p = c / DMODEL;
    int c2 = c - p * DMODEL;
    int h = c2 >> 6, j = c2 & 63;
    const float* P = (p == 0) ? Pq : (p == 1) ? Pk : Pv;
    const float* V = (p == 0) ? Vq : (p == 1) ? Vk : Vv;
    const float* Bv_ = (p == 0) ? bq : (p == 1) ? bk : bv;
    const float* Ph = P + (size_t)h * DMODEL * 32 + (size_t)d * 32;
    const float* Vh = V + (size_t)h * 32 * DH + j;
    float s = 0.f;
#pragma unroll
    for (int r = 0; r < 32; r++) s += Ph[r] * Vh[(size_t)r * DH];
    g_Wtb[(size_t)c * DMODEL + d] = __float2bfloat16(s);
    if (d == 0) g_bqkv[c] = Bv_[h * DH + j];
}

// ---------------- weight transpose fp32 -> bf16 ----------------
__global__ void transpose_b16(const float* __restrict__ src, bf16* __restrict__ dst, int R, int C)
{
    __shared__ float t[32][33];
    int c0 = blockIdx.x * 32, r0 = blockIdx.y * 32;
    int x = threadIdx.x, y = threadIdx.y;
    for (int i = 0; i < 32; i += 8) t[y + i][x] = src[(size_t)(r0 + y + i) * C + c0 + x];
    __syncthreads();
    for (int i = 0; i < 32; i += 8) dst[(size_t)(c0 + y + i) * R + r0 + x] = __float2bfloat16(t[x][y + i]);
}

// ---------------- LayerNorm (fp32 out + optional bf16 out) ----------------
__global__ __launch_bounds__(256) void ln_kernel(const float* __restrict__ in,
                                                 const float* __restrict__ gam,
                                                 const float* __restrict__ bet,
                                                 float* __restrict__ outF,
                                                 bf16* __restrict__ outB)
{
    int row = blockIdx.x;
    int t = threadIdx.x;
    const float* ip = in + (size_t)row * DMODEL;
    float x0 = ip[t], x1 = ip[t + 256], x2 = ip[t + 512];
    __shared__ float rs[256], rq[256];
    rs[t] = x0 + x1 + x2;
    rq[t] = x0 * x0 + x1 * x1 + x2 * x2;
    __syncthreads();
    for (int off = 128; off > 0; off >>= 1) {
        if (t < off) { rs[t] += rs[t + off]; rq[t] += rq[t + off]; }
        __syncthreads();
    }
    float mu = rs[0] * (1.f / 768.f);
    float var = rq[0] * (1.f / 768.f) - mu * mu;
    float rstd = rsqrtf(var + 1e-12f);
    float y0 = (x0 - mu) * rstd * gam[t] + bet[t];
    float y1 = (x1 - mu) * rstd * gam[t + 256] + bet[t + 256];
    float y2 = (x2 - mu) * rstd * gam[t + 512] + bet[t + 512];
    float* op = outF + (size_t)row * DMODEL;
    op[t] = y0; op[t + 256] = y1; op[t + 512] = y2;
    if (outB) {
        bf16* ob = outB + (size_t)row * DMODEL;
        ob[t] = __float2bfloat16(y0);
        ob[t + 256] = __float2bfloat16(y1);
        ob[t + 512] = __float2bfloat16(y2);
    }
}

// ---------------- launch ----------------
extern "C" void kernel_launch(void* const* d_in, const int* in_sizes, int n_in,
                              void* d_out, int out_size)
{
    const float* x    = (const float*)d_in[0];
    const float* mask = (const float*)d_in[1];
    const float* Pq = (const float*)d_in[2];
    const float* Vq = (const float*)d_in[3];
    const float* bq = (const float*)d_in[4];
    const float* Pk = (const float*)d_in[5];
    const float* Vk = (const float*)d_in[6];
    const float* bk = (const float*)d_in[7];
    const float* Pv = (const float*)d_in[8];
    const float* Vv = (const float*)d_in[9];
    const float* bv = (const float*)d_in[10];
    const float* Uo = (const float*)d_in[11];
    const float* Vo = (const float*)d_in[12];
    const float* bo = (const float*)d_in[13];
    const float* U1 = (const float*)d_in[14];
    const float* V1 = (const float*)d_in[15];
    const float* b1 = (const float*)d_in[16];
    const float* U2 = (const float*)d_in[17];
    const float* V2 = (const float*)d_in[18];
    const float* b2 = (const float*)d_in[19];
    const float* g1 = (const float*)d_in[20];
    const float* be1 = (const float*)d_in[21];
    const float* g2 = (const float*)d_in[22];
    const float* be2 = (const float*)d_in[23];

    float *bqkv, *pre, *x1f;
    bf16 *xb, *Wtb, *attnb, *t256b, *mid, *x1b;
    bf16 *Uot, *Vot, *U1t, *V1t, *U2t, *V2t;
    cudaGetSymbolAddress((void**)&xb,    g_xb);
    cudaGetSymbolAddress((void**)&Wtb,   g_Wtb);
    cudaGetSymbolAddress((void**)&bqkv,  g_bqkv);
    cudaGetSymbolAddress((void**)&attnb, g_attnb);
    cudaGetSymbolAddress((void**)&t256b, g_t256b);
    cudaGetSymbolAddress((void**)&mid,   g_mid);
    cudaGetSymbolAddress((void**)&pre,   g_pre);
    cudaGetSymbolAddress((void**)&x1f,   g_x1);
    cudaGetSymbolAddress((void**)&x1b,   g_x1b);
    cudaGetSymbolAddress((void**)&Uot,   g_Uot);
    cudaGetSymbolAddress((void**)&Vot,   g_Vot);
    cudaGetSymbolAddress((void**)&U1t,   g_U1t);
    cudaGetSymbolAddress((void**)&V1t,   g_V1t);
    cudaGetSymbolAddress((void**)&U2t,   g_U2t);
    cudaGetSymbolAddress((void**)&V2t,   g_V2t);

    dim3 tb(32, 8);

    // prep
    f2b_kernel<<<(NTOK * DMODEL / 2 + 255) / 256, 256>>>(x, xb, (long long)NTOK * DMODEL / 2);
    fuse_w_kernel<<<(DMODEL * QKVN + 255) / 256, 256>>>(Pq, Vq, bq, Pk, Vk, bk, Pv, Vv, bv);
    transpose_b16<<<dim3(256 / 32, DMODEL / 32), tb>>>(Uo, Uot, DMODEL, 256);
    transpose_b16<<<dim3(DMODEL / 32, 256 / 32), tb>>>(Vo, Vot, 256, DMODEL);
    transpose_b16<<<dim3(256 / 32, DMODEL / 32), tb>>>(U1, U1t, DMODEL, 256);
    transpose_b16<<<dim3(FDIM / 32, 256 / 32), tb>>>(V1, V1t, 256, FDIM);
    transpose_b16<<<dim3(256 / 32, FDIM / 32), tb>>>(U2, U2t, FDIM, 256);
    transpose_b16<<<dim3(DMODEL / 32, 256 / 32), tb>>>(V2, V2t, 256, DMODEL);

    // 1) QKV = xb @ Wtb^T + bias -> q/k/v planes (bf16)
    bmma_gemm<128, 3><<<dim3(QKVN / 128, NTOK / 128, 1), 256>>>(
        xb, Wtb, DMODEL, DMODEL, DMODEL, 0, 0,
        nullptr, nullptr, bqkv, nullptr, 0, 0);

    // 2) fused flash attention -> g_attnb [B*M, 768]
    flash_kernel<<<dim3(SEQ / 128, BH), 256>>>(mask);

    // 3) t = attn @ Uo
    bmma_gemm<128, 0><<<dim3(2, NTOK / 128, 1), 256>>>(
        attnb, Uot, DMODEL, DMODEL, DMODEL, 0, 0,
        nullptr, t256b, nullptr, nullptr, 256, 0);
    // 4) pre1 = t @ Vo + bo + x
    bmma_gemm<128, 1><<<dim3(DMODEL / 128, NTOK / 128, 1), 256>>>(
        t256b, Vot, 256, 256, 256, 0, 0,
        pre, nullptr, bo, x, DMODEL, 0);
    // 5) LN1 -> x1 (fp32 + bf16)
    ln_kernel<<<NTOK, 256>>>(pre, g1, be1, x1f, x1b);
    // 6) t = x1 @ U1
    bmma_gemm<128, 0><<<dim3(2, NTOK / 128, 1), 256>>>(
        x1b, U1t, DMODEL, DMODEL, DMODEL, 0, 0,
        nullptr, t256b, nullptr, nullptr, 256, 0);
    // 7) mid = gelu(t @ V1 + b1) -> bf16
    bmma_gemm<128, 2><<<dim3(FDIM / 128, NTOK / 128, 1), 256>>>(
        t256b, V1t, 256, 256, 256, 0, 0,
        nullptr, mid, b1, nullptr, FDIM, 0);
    // 8) t = mid @ U2
    bmma_gemm<128, 0><<<dim3(2, NTOK / 128, 1), 256>>>(
        mid, U2t, FDIM, FDIM, FDIM, 0, 0,
        nullptr, t256b, nullptr, nullptr, 256, 0);
    // 9) pre2 = t @ V2 + b2 + x1
    bmma_gemm<128, 1><<<dim3(DMODEL / 128, NTOK / 128, 1), 256>>>(
        t256b, V2t, 256, 256, 256, 0, 0,
        pre, nullptr, b2, x1f, DMODEL, 0);
    // 10) LN2 -> out (fp32)
    ln_kernel<<<NTOK, 256>>>(pre, g2, be2, (float*)d_out, nullptr);
}

// round 10
// speedup vs baseline: 8.2729x; 1.0246x over previous
#include <cuda_runtime.h>
#include <cuda_bf16.h>
#include <math.h>
#include <stdint.h>

// ---------------- problem constants ----------------
#define BATCH 4
#define SEQ   2048
#define DMODEL 768
#define NHEAD 12
#define DH    64
#define NTOK  (BATCH*SEQ)          // 8192
#define QKVN  (3*DMODEL)           // 2304
#define FDIM  3072
#define BH    (BATCH*NHEAD)        // 48

typedef __nv_bfloat16 bf16;
typedef __nv_bfloat162 bf162;

// ---------------- scratch (__device__ globals; no allocation) ----------------
__device__ bf16 g_xb[(size_t)NTOK*DMODEL];
__device__ bf16 g_Wtb[(size_t)QKVN*DMODEL];            // [2304][768]
__device__ float g_bqkv[QKVN];
__device__ bf16 g_q[(size_t)BH*SEQ*DH];                // [48][2048][64]
__device__ bf16 g_k[(size_t)BH*SEQ*DH];
__device__ bf16 g_v[(size_t)BH*SEQ*DH];
__device__ bf16 g_attnb[(size_t)NTOK*DMODEL];
__device__ bf16 g_t256b[(size_t)NTOK*256];
__device__ bf16 g_mid[(size_t)NTOK*FDIM];
__device__ float g_part[2][(size_t)NTOK*256];          // split-K fp32 partials
__device__ float g_pre[(size_t)NTOK*DMODEL];
__device__ float g_x1[(size_t)NTOK*DMODEL];
__device__ bf16 g_x1b[(size_t)NTOK*DMODEL];
__device__ bf16 g_Uot[256*DMODEL];
__device__ bf16 g_Vot[DMODEL*256];
__device__ bf16 g_U1t[256*DMODEL];
__device__ bf16 g_V1t[FDIM*256];
__device__ bf16 g_U2t[256*FDIM];
__device__ bf16 g_V2t[DMODEL*256];

// ---------------- PTX helpers (base ISA only: sm_80-compatible) ----------------
__device__ __forceinline__ uint32_t smem_u32(const void* p) {
    uint32_t a;
    asm("{ .reg .u64 t; cvta.to.shared.u64 t, %1; cvt.u32.u64 %0, t; }" : "=r"(a) : "l"(p));
    return a;
}
__device__ __forceinline__ uint32_t pack_bf16x2(float lo, float hi) {
    uint32_t r;
    asm("cvt.rn.bf16x2.f32 %0, %1, %2;" : "=r"(r) : "f"(hi), "f"(lo));
    return r;
}
#define CPASYNC16(dst, src) asm volatile("cp.async.cg.shared.global [%0], [%1], 16;" :: "r"(dst), "l"(src))
#define CPCOMMIT()          asm volatile("cp.async.commit_group;" ::: "memory")
#define CPWAIT(n)           asm volatile("cp.async.wait_group %0;" :: "n"(n) : "memory")

__device__ __forceinline__ void ldsm4(uint32_t* r, uint32_t a) {
    asm volatile("ldmatrix.sync.aligned.m8n8.x4.shared.b16 {%0,%1,%2,%3}, [%4];"
        : "=r"(r[0]), "=r"(r[1]), "=r"(r[2]), "=r"(r[3]) : "r"(a));
}
__device__ __forceinline__ void ldsm2(uint32_t* r, uint32_t a) {
    asm volatile("ldmatrix.sync.aligned.m8n8.x2.shared.b16 {%0,%1}, [%2];"
        : "=r"(r[0]), "=r"(r[1]) : "r"(a));
}
__device__ __forceinline__ void ldsm2t(uint32_t* r, uint32_t a) {
    asm volatile("ldmatrix.sync.aligned.m8n8.x2.trans.shared.b16 {%0,%1}, [%2];"
        : "=r"(r[0]), "=r"(r[1]) : "r"(a));
}
__device__ __forceinline__ void mma16816(float* c, const uint32_t* a, const uint32_t* b) {
    asm volatile("mma.sync.aligned.m16n8k16.row.col.f32.bf16.bf16.f32 "
        "{%0,%1,%2,%3}, {%4,%5,%6,%7}, {%8,%9}, {%0,%1,%2,%3};"
        : "+f"(c[0]), "+f"(c[1]), "+f"(c[2]), "+f"(c[3])
        : "r"(a[0]), "r"(a[1]), "r"(a[2]), "r"(a[3]), "r"(b[0]), "r"(b[1]));
}

__device__ __forceinline__ float gelu_exact(float a) {
    return 0.5f * a * (1.f + erff(a * 0.70710678118654752f));
}

// ---------------- generic bf16 mma GEMM: C[128 x BN] = A[M,K] @ B[N,K]^T ----------------
// EPI: 0 = bf16 out
//      1 = f32 out = v + bias[gn] + res[...]
//      2 = bf16 out = gelu(v + bias[gn])
//      3 = QKV scatter (+bias) into g_q/g_k/g_v planes
//      5 = f32 partial out at z-indexed buffer (split-K)
#define BM 128
#define BK 32
#define RST 40

template<int BN, int EPI>
__global__ __launch_bounds__(256) void bmma_gemm(
    const bf16* __restrict__ A, const bf16* __restrict__ B,
    int K, int ldA, int ldB, long long sA, long long sB,
    float* __restrict__ outF, bf16* __restrict__ outB,
    const float* __restrict__ bias, const float* __restrict__ res,
    int ldC, long long sC)
{
    constexpr int NT = BN / 32;
    constexpr int ACH = BM * 4;
    constexpr int TCH = (BM + BN) * 4;
    constexpr int SSA = BM * RST;
    constexpr int SS  = (BM + BN) * RST;

    __shared__ bf16 sm[2 * SS];

    int tid = threadIdx.x;
    int z = blockIdx.z;
    const bf16* Ab = A + (long long)z * sA + (long long)blockIdx.y * BM * ldA;
    const bf16* Bb = B + (long long)z * sB + (long long)blockIdx.x * BN * ldB;
    uint32_t smu = smem_u32(sm);

    float acc[4][NT][4];
#pragma unroll
    for (int i = 0; i < 4; i++)
#pragma unroll
        for (int j = 0; j < NT; j++)
#pragma unroll
            for (int k = 0; k < 4; k++) acc[i][j][k] = 0.f;

    int wid = tid >> 5, lane = tid & 31;
    int wm = (wid >> 2) * 64;
    int wn = (wid & 3) * (BN / 4);

    int nch = K / BK;

    {
        uint32_t base = smu;
        for (int i = tid; i < TCH; i += 256) {
            if (i < ACH) {
                int row = i >> 2, c16 = i & 3;
                CPASYNC16(base + (uint32_t)(row * RST + c16 * 8) * 2,
                          Ab + (long long)row * ldA + c16 * 8);
            } else {
                int j = i - ACH;
                int row = j >> 2, c16 = j & 3;
                CPASYNC16(base + (uint32_t)(SSA + row * RST + c16 * 8) * 2,
                          Bb + (long long)row * ldB + c16 * 8);
            }
        }
        CPCOMMIT();
    }

    for (int c = 0; c < nch; c++) {
        int s = c & 1;
        if (c + 1 < nch) {
            int kof = (c + 1) * BK;
            uint32_t base = smu + (uint32_t)((s ^ 1) * SS) * 2;
            for (int i = tid; i < TCH; i += 256) {
                if (i < ACH) {
                    int row = i >> 2, c16 = i & 3;
                    CPASYNC16(base + (uint32_t)(row * RST + c16 * 8) * 2,
                              Ab + (long long)row * ldA + kof + c16 * 8);
                } else {
                    int j = i - ACH;
                    int row = j >> 2, c16 = j & 3;
                    CPASYNC16(base + (uint32_t)(SSA + row * RST + c16 * 8) * 2,
                              Bb + (long long)row * ldB + kof + c16 * 8);
                }
            }
            CPCOMMIT();
            CPWAIT(1);
        } else {
            CPWAIT(0);
        }
        __syncthreads();

        uint32_t Abase = smu + (uint32_t)(s * SS) * 2;
        uint32_t Bbase = Abase + (uint32_t)SSA * 2;
#pragma unroll
        for (int ks = 0; ks < 2; ks++) {
            uint32_t a[4][4], b[NT][2];
#pragma unroll
            for (int mt = 0; mt < 4; mt++) {
                uint32_t ad = Abase + (uint32_t)((wm + mt * 16 + (lane & 15)) * RST + ks * 16 + (lane >> 4) * 8) * 2;
                ldsm4(a[mt], ad);
            }
#pragma unroll
            for (int nt = 0; nt < NT; nt++) {
                int l = lane & 15;
                uint32_t bd = Bbase + (uint32_t)((wn + nt * 8 + (l & 7)) * RST + ks * 16 + ((l >> 3) & 1) * 8) * 2;
                ldsm2(b[nt], bd);
            }
#pragma unroll
            for (int mt = 0; mt < 4; mt++)
#pragma unroll
                for (int nt = 0; nt < NT; nt++)
                    mma16816(acc[mt][nt], a[mt], b[nt]);
        }
        __syncthreads();
    }

    int m0 = blockIdx.y * BM, n0 = blockIdx.x * BN;
#pragma unroll
    for (int mt = 0; mt < 4; mt++)
#pragma unroll
        for (int nt = 0; nt < NT; nt++)
#pragma unroll
            for (int h2 = 0; h2 < 2; h2++) {
                int gm = m0 + wm + mt * 16 + (lane >> 2) + h2 * 8;
                int gn = n0 + wn + nt * 8 + ((lane & 3) << 1);
                float v0 = acc[mt][nt][h2 * 2];
                float v1 = acc[mt][nt][h2 * 2 + 1];
                if (EPI == 0) {
                    bf16* p = outB + (long long)z * sC + (long long)gm * ldC + gn;
                    *(uint32_t*)p = pack_bf16x2(v0, v1);
                } else if (EPI == 1) {
                    long long o = (long long)gm * ldC + gn;
                    outF[o]     = v0 + bias[gn]     + res[o];
                    outF[o + 1] = v1 + bias[gn + 1] + res[o + 1];
                } else if (EPI == 2) {
                    float a0 = gelu_exact(v0 + bias[gn]);
                    float a1 = gelu_exact(v1 + bias[gn + 1]);
                    bf16* p = outB + (long long)gm * ldC + gn;
                    *(uint32_t*)p = pack_bf16x2(a0, a1);
                } else if (EPI == 3) {
                    float a0 = v0 + bias[gn];
                    float a1 = v1 + bias[gn + 1];
                    int pp = gn / DMODEL;
                    int c2 = gn - pp * DMODEL;
                    int h = c2 >> 6, j = c2 & 63;
                    int b_ = gm >> 11, m = gm & 2047;
                    bf16* pl = (pp == 0 ? g_q : (pp == 1 ? g_k : g_v))
                             + (((long long)(b_ * NHEAD + h) << 11) + m) * DH + j;
                    *(uint32_t*)pl = pack_bf16x2(a0, a1);
                } else if (EPI == 5) {
                    float* op = outF + (long long)z * sC + (long long)gm * ldC + gn;
                    *(float2*)op = make_float2(v0, v1);
                }
            }
}

// ---------------- split-K combine: t256b = bf16(part0 + part1) ----------------
__global__ void combine_kernel(bf16* __restrict__ dst)
{
    long long i = (long long)blockIdx.x * blockDim.x + threadIdx.x;
    if (i >= (long long)NTOK * 256 / 2) return;
    float2 a = ((const float2*)g_part[0])[i];
    float2 b = ((const float2*)g_part[1])[i];
    ((uint32_t*)dst)[i] = pack_bf16x2(a.x + b.x, a.y + b.y);
}

// ---------------- flash attention: 128 Q rows/CTA, KV tiles of 64, online softmax (log2 domain) ----------------
#define FBN 64
#define KVP 72   // smem pitch (elems)
#define L2E 1.4426950408889634f

__global__ __launch_bounds__(256) void flash_kernel(const float* __restrict__ mask)
{
    __shared__ bf16 Ks[2][FBN * KVP];
    __shared__ bf16 Vs[2][FBN * KVP];
    __shared__ float Ms[2][FBN];

    int z = blockIdx.y;
    int bq = z / NHEAD, h = z - bq * NHEAD;
    int m0 = blockIdx.x * 128;
    int tid = threadIdx.x, wid = tid >> 5, lane = tid & 31;
    int wm = wid * 16;

    const bf16* Qg = g_q + ((size_t)z * SEQ + m0) * DH;
    const bf16* Kg = g_k + (size_t)z * SEQ * DH;
    const bf16* Vg = g_v + (size_t)z * SEQ * DH;
    const float* mg = mask + (size_t)bq * SEQ;

    uint32_t ks0 = smem_u32(Ks), vs0 = smem_u32(Vs), ms0 = smem_u32(Ms);

    // Q a-fragments straight from gmem (one-time)
    uint32_t qa[4][4];
    {
        const bf16* q0 = Qg + (size_t)(wm + (lane >> 2)) * DH + ((lane & 3) << 1);
#pragma unroll
        for (int t = 0; t < 4; t++) {
            qa[t][0] = *(const uint32_t*)(q0 + t * 16);
            qa[t][1] = *(const uint32_t*)(q0 + 8 * DH + t * 16);
            qa[t][2] = *(const uint32_t*)(q0 + t * 16 + 8);
            qa[t][3] = *(const uint32_t*)(q0 + 8 * DH + t * 16 + 8);
        }
    }

    // prefetch helper
    auto prefetch = [&](int s, int n0) {
        uint32_t kb = ks0 + (uint32_t)(s * FBN * KVP) * 2;
        uint32_t vb = vs0 + (uint32_t)(s * FBN * KVP) * 2;
        for (int i = tid; i < FBN * 8; i += 256) {
            int r = i >> 3, c = (i & 7) << 3;
            CPASYNC16(kb + (uint32_t)(r * KVP + c) * 2, Kg + (size_t)(n0 + r) * DH + c);
            CPASYNC16(vb + (uint32_t)(r * KVP + c) * 2, Vg + (size_t)(n0 + r) * DH + c);
        }
        if (tid < 16)
            CPASYNC16(ms0 + (uint32_t)(s * FBN + tid * 4) * 4, mg + n0 + tid * 4);
    };

    prefetch(0, 0);
    CPCOMMIT();

    float o[8][4];
#pragma unroll
    for (int i = 0; i < 8; i++)
#pragma unroll
        for (int j = 0; j < 4; j++) o[i][j] = 0.f;
    float mi0 = -1e30f, mi1 = -1e30f, li0 = 0.f, li1 = 0.f;

    const float SCL = 0.125f * L2E;   // S scale folded with log2e

    for (int s = 0; s < SEQ / FBN; s++) {
        int buf = s & 1;
        if (s + 1 < SEQ / FBN) {
            prefetch(buf ^ 1, (s + 1) * FBN);
            CPCOMMIT();
            CPWAIT(1);
        } else {
            CPWAIT(0);
        }
        __syncthreads();

        uint32_t kb = ks0 + (uint32_t)(buf * FBN * KVP) * 2;
        uint32_t vb = vs0 + (uint32_t)(buf * FBN * KVP) * 2;

        // S = Q @ K^T  (16 x 64 per warp, fp32)
        float c[8][4];
#pragma unroll
        for (int nt = 0; nt < 8; nt++)
#pragma unroll
            for (int i = 0; i < 4; i++) c[nt][i] = 0.f;
        int l = lane & 15;
#pragma unroll
        for (int t = 0; t < 4; t++) {
#pragma unroll
            for (int nt = 0; nt < 8; nt++) {
                uint32_t b[2];
                ldsm2(b, kb + (uint32_t)((nt * 8 + (l & 7)) * KVP + t * 16 + ((l >> 3) & 1) * 8) * 2);
                mma16816(c[nt], qa[t], b);
            }
        }

        // scale + mask + online softmax (all in log2 domain)
        float mx0 = -1e30f, mx1 = -1e30f;
#pragma unroll
        for (int nt = 0; nt < 8; nt++) {
            int col = nt * 8 + ((lane & 3) << 1);
            float mk0 = Ms[buf][col] * L2E, mk1 = Ms[buf][col + 1] * L2E;
            c[nt][0] = c[nt][0] * SCL + mk0;
            c[nt][1] = c[nt][1] * SCL + mk1;
            c[nt][2] = c[nt][2] * SCL + mk0;
            c[nt][3] = c[nt][3] * SCL + mk1;
            mx0 = fmaxf(mx0, fmaxf(c[nt][0], c[nt][1]));
            mx1 = fmaxf(mx1, fmaxf(c[nt][2], c[nt][3]));
        }
        mx0 = fmaxf(mx0, __shfl_xor_sync(0xffffffffu, mx0, 1));
        mx0 = fmaxf(mx0, __shfl_xor_sync(0xffffffffu, mx0, 2));
        mx1 = fmaxf(mx1, __shfl_xor_sync(0xffffffffu, mx1, 1));
        mx1 = fmaxf(mx1, __shfl_xor_sync(0xffffffffu, mx1, 2));
        float nm0 = fmaxf(mi0, mx0), nm1 = fmaxf(mi1, mx1);
        float a0 = exp2f(mi0 - nm0), a1 = exp2f(mi1 - nm1);
        float s0 = 0.f, s1 = 0.f;
#pragma unroll
        for (int nt = 0; nt < 8; nt++) {
            c[nt][0] = exp2f(c[nt][0] - nm0);
            c[nt][1] = exp2f(c[nt][1] - nm0);
            c[nt][2] = exp2f(c[nt][2] - nm1);
            c[nt][3] = exp2f(c[nt][3] - nm1);
            s0 += c[nt][0] + c[nt][1];
            s1 += c[nt][2] + c[nt][3];
        }
        s0 += __shfl_xor_sync(0xffffffffu, s0, 1);
        s0 += __shfl_xor_sync(0xffffffffu, s0, 2);
        s1 += __shfl_xor_sync(0xffffffffu, s1, 1);
        s1 += __shfl_xor_sync(0xffffffffu, s1, 2);
        li0 = li0 * a0 + s0;
        li1 = li1 * a1 + s1;
        mi0 = nm0; mi1 = nm1;
#pragma unroll
        for (int dt = 0; dt < 8; dt++) {
            o[dt][0] *= a0; o[dt][1] *= a0;
            o[dt][2] *= a1; o[dt][3] *= a1;
        }

        // O += P @ V   (P packed bf16 from c, V b-frags via trans ldmatrix)
#pragma unroll
        for (int t = 0; t < 4; t++) {
            uint32_t pa[4];
            pa[0] = pack_bf16x2(c[2 * t][0], c[2 * t][1]);
            pa[1] = pack_bf16x2(c[2 * t][2], c[2 * t][3]);
            pa[2] = pack_bf16x2(c[2 * t + 1][0], c[2 * t + 1][1]);
            pa[3] = pack_bf16x2(c[2 * t + 1][2], c[2 * t + 1][3]);
#pragma unroll
            for (int dt = 0; dt < 8; dt++) {
                uint32_t b[2];
                ldsm2t(b, vb + (uint32_t)((t * 16 + l) * KVP + dt * 8) * 2);
                mma16816(o[dt], pa, b);
            }
        }
        __syncthreads();
    }

    // epilogue
    float inv0 = 1.f / li0, inv1 = 1.f / li1;
    int r0 = m0 + wm + (lane >> 2);
    bf16* out0 = g_attnb + ((size_t)(bq * SEQ + r0)) * DMODEL + h * DH;
    bf16* out1 = out0 + (size_t)8 * DMODEL;
#pragma unroll
    for (int dt = 0; dt < 8; dt++) {
        int col = dt * 8 + ((lane & 3) << 1);
        *(uint32_t*)(out0 + col) = pack_bf16x2(o[dt][0] * inv0, o[dt][1] * inv0);
        *(uint32_t*)(out1 + col) = pack_bf16x2(o[dt][2] * inv1, o[dt][3] * inv1);
    }
}

// ---------------- fp32 -> bf16 convert ----------------
__global__ void f2b_kernel(const float* __restrict__ src, bf16* __restrict__ dst, long long n2)
{
    long long i = (long long)blockIdx.x * blockDim.x + threadIdx.x;
    if (i >= n2) return;
    float2 v = ((const float2*)src)[i];
    ((uint32_t*)dst)[i] = pack_bf16x2(v.x, v.y);
}

// ---------------- fuse low-rank QKV weights (transposed, bf16) ----------------
__global__ void fuse_w_kernel(const float* __restrict__ Pq, const float* __restrict__ Vq, const float* __restrict__ bq,
                              const float* __restrict__ Pk, const float* __restrict__ Vk, const float* __restrict__ bk,
                              const float* __restrict__ Pv, const float* __restrict__ Vv, const float* __restrict__ bv)
{
    int idx = blockIdx.x * blockDim.x + threadIdx.x;
    if (idx >= DMODEL * QKVN) return;
    int c = idx / DMODEL;
    int d = idx - c * DMODEL;
    int p = c / DMODEL;
    int c2 = c - p * DMODEL;
    int h = c2 >> 6, j = c2 & 63;
    const float* P = (p == 0) ? Pq : (p == 1) ? Pk : Pv;
    const float* V = (p == 0) ? Vq : (p == 1) ? Vk : Vv;
    const float* Bv_ = (p == 0) ? bq : (p == 1) ? bk : bv;
    const float* Ph = P + (size_t)h * DMODEL * 32 + (size_t)d * 32;
    const float* Vh = V + (size_t)h * 32 * DH + j;
    float s = 0.f;
#pragma unroll
    for (int r = 0; r < 32; r++) s += Ph[r] * Vh[(size_t)r * DH];
    g_Wtb[(size_t)c * DMODEL + d] = __float2bfloat16(s);
    if (d == 0) g_bqkv[c] = Bv_[h * DH + j];
}

// ---------------- weight transpose fp32 -> bf16 ----------------
__global__ void transpose_b16(const float* __restrict__ src, bf16* __restrict__ dst, int R, int C)
{
    __shared__ float t[32][33];
    int c0 = blockIdx.x * 32, r0 = blockIdx.y * 32;
    int x = threadIdx.x, y = threadIdx.y;
    for (int i = 0; i < 32; i += 8) t[y + i][x] = src[(size_t)(r0 + y + i) * C + c0 + x];
    __syncthreads();
    for (int i = 0; i < 32; i += 8) dst[(size_t)(c0 + y + i) * R + r0 + x] = __float2bfloat16(t[x][y + i]);
}

// ---------------- LayerNorm (fp32 out + optional bf16 out) ----------------
__global__ __launch_bounds__(256) void ln_kernel(const float* __restrict__ in,
                                                 const float* __restrict__ gam,
                                                 const float* __restrict__ bet,
                                                 float* __restrict__ outF,
                                                 bf16* __restrict__ outB)
{
    int row = blockIdx.x;
    int t = threadIdx.x;
    const float* ip = in + (size_t)row * DMODEL;
    float x0 = ip[t], x1 = ip[t + 256], x2 = ip[t + 512];
    __shared__ float rs[256], rq[256];
    rs[t] = x0 + x1 + x2;
    rq[t] = x0 * x0 + x1 * x1 + x2 * x2;
    __syncthreads();
    for (int off = 128; off > 0; off >>= 1) {
        if (t < off) { rs[t] += rs[t + off]; rq[t] += rq[t + off]; }
        __syncthreads();
    }
    float mu = rs[0] * (1.f / 768.f);
    float var = rq[0] * (1.f / 768.f) - mu * mu;
    float rstd = rsqrtf(var + 1e-12f);
    float y0 = (x0 - mu) * rstd * gam[t] + bet[t];
    float y1 = (x1 - mu) * rstd * gam[t + 256] + bet[t + 256];
    float y2 = (x2 - mu) * rstd * gam[t + 512] + bet[t + 512];
    float* op = outF + (size_t)row * DMODEL;
    op[t] = y0; op[t + 256] = y1; op[t + 512] = y2;
    if (outB) {
        bf16* ob = outB + (size_t)row * DMODEL;
        ob[t] = __float2bfloat16(y0);
        ob[t + 256] = __float2bfloat16(y1);
        ob[t + 512] = __float2bfloat16(y2);
    }
}

// ---------------- launch ----------------
extern "C" void kernel_launch(void* const* d_in, const int* in_sizes, int n_in,
                              void* d_out, int out_size)
{
    const float* x    = (const float*)d_in[0];
    const float* mask = (const float*)d_in[1];
    const float* Pq = (const float*)d_in[2];
    const float* Vq = (const float*)d_in[3];
    const float* bq = (const float*)d_in[4];
    const float* Pk = (const float*)d_in[5];
    const float* Vk = (const float*)d_in[6];
    const float* bk = (const float*)d_in[7];
    const float* Pv = (const float*)d_in[8];
    const float* Vv = (const float*)d_in[9];
    const float* bv = (const float*)d_in[10];
    const float* Uo = (const float*)d_in[11];
    const float* Vo = (const float*)d_in[12];
    const float* bo = (const float*)d_in[13];
    const float* U1 = (const float*)d_in[14];
    const float* V1 = (const float*)d_in[15];
    const float* b1 = (const float*)d_in[16];
    const float* U2 = (const float*)d_in[17];
    const float* V2 = (const float*)d_in[18];
    const float* b2 = (const float*)d_in[19];
    const float* g1 = (const float*)d_in[20];
    const float* be1 = (const float*)d_in[21];
    const float* g2 = (const float*)d_in[22];
    const float* be2 = (const float*)d_in[23];

    float *bqkv, *pre, *x1f, *part;
    bf16 *xb, *Wtb, *attnb, *t256b, *mid, *x1b;
    bf16 *Uot, *Vot, *U1t, *V1t, *U2t, *V2t;
    cudaGetSymbolAddress((void**)&xb,    g_xb);
    cudaGetSymbolAddress((void**)&Wtb,   g_Wtb);
    cudaGetSymbolAddress((void**)&bqkv,  g_bqkv);
    cudaGetSymbolAddress((void**)&attnb, g_attnb);
    cudaGetSymbolAddress((void**)&t256b, g_t256b);
    cudaGetSymbolAddress((void**)&mid,   g_mid);
    cudaGetSymbolAddress((void**)&part,  g_part);
    cudaGetSymbolAddress((void**)&pre,   g_pre);
    cudaGetSymbolAddress((void**)&x1f,   g_x1);
    cudaGetSymbolAddress((void**)&x1b,   g_x1b);
    cudaGetSymbolAddress((void**)&Uot,   g_Uot);
    cudaGetSymbolAddress((void**)&Vot,   g_Vot);
    cudaGetSymbolAddress((void**)&U1t,   g_U1t);
    cudaGetSymbolAddress((void**)&V1t,   g_V1t);
    cudaGetSymbolAddress((void**)&U2t,   g_U2t);
    cudaGetSymbolAddress((void**)&V2t,   g_V2t);

    dim3 tb(32, 8);

    // launches 0..3 (prep needed before QKV/flash)
    f2b_kernel<<<(NTOK * DMODEL / 2 + 255) / 256, 256>>>(x, xb, (long long)NTOK * DMODEL / 2);   // 0
    fuse_w_kernel<<<(DMODEL * QKVN + 255) / 256, 256>>>(Pq, Vq, bq, Pk, Vk, bk, Pv, Vv, bv);     // 1
    transpose_b16<<<dim3(256 / 32, DMODEL / 32), tb>>>(Uo, Uot, DMODEL, 256);                    // 2
    transpose_b16<<<dim3(DMODEL / 32, 256 / 32), tb>>>(Vo, Vot, 256, DMODEL);                    // 3

    // 4) QKV = xb @ Wtb^T + bias -> q/k/v planes (bf16)
    bmma_gemm<128, 3><<<dim3(QKVN / 128, NTOK / 128, 1), 256>>>(
        xb, Wtb, DMODEL, DMODEL, DMODEL, 0, 0,
        nullptr, nullptr, bqkv, nullptr, 0, 0);

    // 5) fused flash attention -> g_attnb [B*M, 768]    <-- ncu -s 5 profiles this
    flash_kernel<<<dim3(SEQ / 128, BH), 256>>>(mask);

    // remaining weight transposes (6..9)
    transpose_b16<<<dim3(256 / 32, DMODEL / 32), tb>>>(U1, U1t, DMODEL, 256);
    transpose_b16<<<dim3(FDIM / 32, 256 / 32), tb>>>(V1, V1t, 256, FDIM);
    transpose_b16<<<dim3(256 / 32, FDIM / 32), tb>>>(U2, U2t, FDIM, 256);
    transpose_b16<<<dim3(DMODEL / 32, 256 / 32), tb>>>(V2, V2t, 256, DMODEL);

    // 10) t = attn @ Uo
    bmma_gemm<128, 0><<<dim3(2, NTOK / 128, 1), 256>>>(
        attnb, Uot, DMODEL, DMODEL, DMODEL, 0, 0,
        nullptr, t256b, nullptr, nullptr, 256, 0);
    // 11) pre1 = t @ Vo + bo + x
    bmma_gemm<128, 1><<<dim3(DMODEL / 128, NTOK / 128, 1), 256>>>(
        t256b, Vot, 256, 256, 256, 0, 0,
        pre, nullptr, bo, x, DMODEL, 0);
    // 12) LN1 -> x1 (fp32 + bf16)
    ln_kernel<<<NTOK, 256>>>(pre, g1, be1, x1f, x1b);
    // 13) t = x1 @ U1
    bmma_gemm<128, 0><<<dim3(2, NTOK / 128, 1), 256>>>(
        x1b, U1t, DMODEL, DMODEL, DMODEL, 0, 0,
        nullptr, t256b, nullptr, nullptr, 256, 0);
    // 14) mid = gelu(t @ V1 + b1) -> bf16
    bmma_gemm<128, 2><<<dim3(FDIM / 128, NTOK / 128, 1), 256>>>(
        t256b, V1t, 256, 256, 256, 0, 0,
        nullptr, mid, b1, nullptr, FDIM, 0);
    // 15) t_part[z] = mid[:, z*1536:(z+1)*1536] @ U2t[:, z*1536:...]  (split-K, fp32 partials)
    bmma_gemm<128, 5><<<dim3(2, NTOK / 128, 2), 256>>>(
        mid, U2t, FDIM / 2, FDIM, FDIM, FDIM / 2, FDIM / 2,
        part, nullptr, nullptr, nullptr, 256, (long long)NTOK * 256);
    // 16) combine partials -> t256b
    combine_kernel<<<(NTOK * 256 / 2 + 255) / 256, 256>>>(t256b);
    // 17) pre2 = t @ V2 + b2 + x1
    bmma_gemm<128, 1><<<dim3(DMODEL / 128, NTOK / 128, 1), 256>>>(
        t256b, V2t, 256, 256, 256, 0, 0,
        pre, nullptr, b2, x1f, DMODEL, 0);
    // 18) LN2 -> out (fp32)
    ln_kernel<<<NTOK, 256>>>(pre, g2, be2, (float*)d_out, nullptr);
}

// round 11
// speedup vs baseline: 8.3773x; 1.0126x over previous
#include <cuda_runtime.h>
#include <cuda_bf16.h>
#include <math.h>
#include <stdint.h>

// ---------------- problem constants ----------------
#define BATCH 4
#define SEQ   2048
#define DMODEL 768
#define NHEAD 12
#define DH    64
#define NTOK  (BATCH*SEQ)          // 8192
#define QKVN  (3*DMODEL)           // 2304
#define FDIM  3072
#define BH    (BATCH*NHEAD)        // 48

typedef __nv_bfloat16 bf16;
typedef __nv_bfloat162 bf162;

// ---------------- scratch (__device__ globals; no allocation) ----------------
__device__ bf16 g_xb[(size_t)NTOK*DMODEL];
__device__ bf16 g_Wtb[(size_t)QKVN*DMODEL];            // [2304][768]
__device__ float g_bqkv[QKVN];
__device__ bf16 g_q[(size_t)BH*SEQ*DH];                // [48][2048][64]
__device__ bf16 g_k[(size_t)BH*SEQ*DH];
__device__ bf16 g_v[(size_t)BH*SEQ*DH];
__device__ bf16 g_attnb[(size_t)NTOK*DMODEL];
__device__ bf16 g_t256b[(size_t)NTOK*256];
__device__ bf16 g_mid[(size_t)NTOK*FDIM];
__device__ float g_part[2][(size_t)NTOK*256];          // split-K fp32 partials
__device__ float g_pre[(size_t)NTOK*DMODEL];
__device__ float g_x1[(size_t)NTOK*DMODEL];
__device__ bf16 g_x1b[(size_t)NTOK*DMODEL];
__device__ bf16 g_Uot[256*DMODEL];
__device__ bf16 g_Vot[DMODEL*256];
__device__ bf16 g_U1t[256*DMODEL];
__device__ bf16 g_V1t[FDIM*256];
__device__ bf16 g_U2t[256*FDIM];
__device__ bf16 g_V2t[DMODEL*256];

// ---------------- PTX helpers (base ISA only: sm_80-compatible) ----------------
__device__ __forceinline__ uint32_t smem_u32(const void* p) {
    uint32_t a;
    asm("{ .reg .u64 t; cvta.to.shared.u64 t, %1; cvt.u32.u64 %0, t; }" : "=r"(a) : "l"(p));
    return a;
}
__device__ __forceinline__ uint32_t pack_bf16x2(float lo, float hi) {
    uint32_t r;
    asm("cvt.rn.bf16x2.f32 %0, %1, %2;" : "=r"(r) : "f"(hi), "f"(lo));
    return r;
}
#define CPASYNC16(dst, src) asm volatile("cp.async.cg.shared.global [%0], [%1], 16;" :: "r"(dst), "l"(src))
#define CPCOMMIT()          asm volatile("cp.async.commit_group;" ::: "memory")
#define CPWAIT(n)           asm volatile("cp.async.wait_group %0;" :: "n"(n) : "memory")

__device__ __forceinline__ void ldsm4(uint32_t* r, uint32_t a) {
    asm volatile("ldmatrix.sync.aligned.m8n8.x4.shared.b16 {%0,%1,%2,%3}, [%4];"
        : "=r"(r[0]), "=r"(r[1]), "=r"(r[2]), "=r"(r[3]) : "r"(a));
}
__device__ __forceinline__ void ldsm2(uint32_t* r, uint32_t a) {
    asm volatile("ldmatrix.sync.aligned.m8n8.x2.shared.b16 {%0,%1}, [%2];"
        : "=r"(r[0]), "=r"(r[1]) : "r"(a));
}
__device__ __forceinline__ void ldsm2t(uint32_t* r, uint32_t a) {
    asm volatile("ldmatrix.sync.aligned.m8n8.x2.trans.shared.b16 {%0,%1}, [%2];"
        : "=r"(r[0]), "=r"(r[1]) : "r"(a));
}
__device__ __forceinline__ void mma16816(float* c, const uint32_t* a, const uint32_t* b) {
    asm volatile("mma.sync.aligned.m16n8k16.row.col.f32.bf16.bf16.f32 "
        "{%0,%1,%2,%3}, {%4,%5,%6,%7}, {%8,%9}, {%0,%1,%2,%3};"
        : "+f"(c[0]), "+f"(c[1]), "+f"(c[2]), "+f"(c[3])
        : "r"(a[0]), "r"(a[1]), "r"(a[2]), "r"(a[3]), "r"(b[0]), "r"(b[1]));
}

__device__ __forceinline__ float gelu_exact(float a) {
    return 0.5f * a * (1.f + erff(a * 0.70710678118654752f));
}

// ---------------- generic bf16 mma GEMM: C[128 x BN] = A[M,K] @ B[N,K]^T ----------------
// EPI: 0 = bf16 out
//      1 = f32 out = v + bias[gn] + res[...]
//      2 = bf16 out = gelu(v + bias[gn])
//      3 = QKV scatter (+bias) into g_q/g_k/g_v planes
//      5 = f32 partial out at z-indexed buffer (split-K; z also offsets A,B by sA,sB)
#define BM 128
#define BK 32
#define RST 40

template<int BN, int EPI>
__global__ __launch_bounds__(256) void bmma_gemm(
    const bf16* __restrict__ A, const bf16* __restrict__ B,
    int K, int ldA, int ldB, long long sA, long long sB,
    float* __restrict__ outF, bf16* __restrict__ outB,
    const float* __restrict__ bias, const float* __restrict__ res,
    int ldC, long long sC)
{
    constexpr int NT = BN / 32;
    constexpr int ACH = BM * 4;
    constexpr int TCH = (BM + BN) * 4;
    constexpr int SSA = BM * RST;
    constexpr int SS  = (BM + BN) * RST;

    __shared__ bf16 sm[2 * SS];

    int tid = threadIdx.x;
    int z = blockIdx.z;
    const bf16* Ab = A + (long long)z * sA + (long long)blockIdx.y * BM * ldA;
    const bf16* Bb = B + (long long)z * sB + (long long)blockIdx.x * BN * ldB;
    uint32_t smu = smem_u32(sm);

    float acc[4][NT][4];
#pragma unroll
    for (int i = 0; i < 4; i++)
#pragma unroll
        for (int j = 0; j < NT; j++)
#pragma unroll
            for (int k = 0; k < 4; k++) acc[i][j][k] = 0.f;

    int wid = tid >> 5, lane = tid & 31;
    int wm = (wid >> 2) * 64;
    int wn = (wid & 3) * (BN / 4);

    int nch = K / BK;

    {
        uint32_t base = smu;
        for (int i = tid; i < TCH; i += 256) {
            if (i < ACH) {
                int row = i >> 2, c16 = i & 3;
                CPASYNC16(base + (uint32_t)(row * RST + c16 * 8) * 2,
                          Ab + (long long)row * ldA + c16 * 8);
            } else {
                int j = i - ACH;
                int row = j >> 2, c16 = j & 3;
                CPASYNC16(base + (uint32_t)(SSA + row * RST + c16 * 8) * 2,
                          Bb + (long long)row * ldB + c16 * 8);
            }
        }
        CPCOMMIT();
    }

    for (int c = 0; c < nch; c++) {
        int s = c & 1;
        if (c + 1 < nch) {
            int kof = (c + 1) * BK;
            uint32_t base = smu + (uint32_t)((s ^ 1) * SS) * 2;
            for (int i = tid; i < TCH; i += 256) {
                if (i < ACH) {
                    int row = i >> 2, c16 = i & 3;
                    CPASYNC16(base + (uint32_t)(row * RST + c16 * 8) * 2,
                              Ab + (long long)row * ldA + kof + c16 * 8);
                } else {
                    int j = i - ACH;
                    int row = j >> 2, c16 = j & 3;
                    CPASYNC16(base + (uint32_t)(SSA + row * RST + c16 * 8) * 2,
                              Bb + (long long)row * ldB + kof + c16 * 8);
                }
            }
            CPCOMMIT();
            CPWAIT(1);
        } else {
            CPWAIT(0);
        }
        __syncthreads();

        uint32_t Abase = smu + (uint32_t)(s * SS) * 2;
        uint32_t Bbase = Abase + (uint32_t)SSA * 2;
#pragma unroll
        for (int ks = 0; ks < 2; ks++) {
            uint32_t a[4][4], b[NT][2];
#pragma unroll
            for (int mt = 0; mt < 4; mt++) {
                uint32_t ad = Abase + (uint32_t)((wm + mt * 16 + (lane & 15)) * RST + ks * 16 + (lane >> 4) * 8) * 2;
                ldsm4(a[mt], ad);
            }
#pragma unroll
            for (int nt = 0; nt < NT; nt++) {
                int l = lane & 15;
                uint32_t bd = Bbase + (uint32_t)((wn + nt * 8 + (l & 7)) * RST + ks * 16 + ((l >> 3) & 1) * 8) * 2;
                ldsm2(b[nt], bd);
            }
#pragma unroll
            for (int mt = 0; mt < 4; mt++)
#pragma unroll
                for (int nt = 0; nt < NT; nt++)
                    mma16816(acc[mt][nt], a[mt], b[nt]);
        }
        __syncthreads();
    }

    int m0 = blockIdx.y * BM, n0 = blockIdx.x * BN;
#pragma unroll
    for (int mt = 0; mt < 4; mt++)
#pragma unroll
        for (int nt = 0; nt < NT; nt++)
#pragma unroll
            for (int h2 = 0; h2 < 2; h2++) {
                int gm = m0 + wm + mt * 16 + (lane >> 2) + h2 * 8;
                int gn = n0 + wn + nt * 8 + ((lane & 3) << 1);
                float v0 = acc[mt][nt][h2 * 2];
                float v1 = acc[mt][nt][h2 * 2 + 1];
                if (EPI == 0) {
                    bf16* p = outB + (long long)z * sC + (long long)gm * ldC + gn;
                    *(uint32_t*)p = pack_bf16x2(v0, v1);
                } else if (EPI == 1) {
                    long long o = (long long)gm * ldC + gn;
                    outF[o]     = v0 + bias[gn]     + res[o];
                    outF[o + 1] = v1 + bias[gn + 1] + res[o + 1];
                } else if (EPI == 2) {
                    float a0 = gelu_exact(v0 + bias[gn]);
                    float a1 = gelu_exact(v1 + bias[gn + 1]);
                    bf16* p = outB + (long long)gm * ldC + gn;
                    *(uint32_t*)p = pack_bf16x2(a0, a1);
                } else if (EPI == 3) {
                    float a0 = v0 + bias[gn];
                    float a1 = v1 + bias[gn + 1];
                    int pp = gn / DMODEL;
                    int c2 = gn - pp * DMODEL;
                    int h = c2 >> 6, j = c2 & 63;
                    int b_ = gm >> 11, m = gm & 2047;
                    bf16* pl = (pp == 0 ? g_q : (pp == 1 ? g_k : g_v))
                             + (((long long)(b_ * NHEAD + h) << 11) + m) * DH + j;
                    *(uint32_t*)pl = pack_bf16x2(a0, a1);
                } else if (EPI == 5) {
                    float* op = outF + (long long)z * sC + (long long)gm * ldC + gn;
                    *(float2*)op = make_float2(v0, v1);
                }
            }
}

// ---------------- split-K combine: t256b = bf16(part0 + part1) ----------------
__global__ void combine_kernel(bf16* __restrict__ dst)
{
    long long i = (long long)blockIdx.x * blockDim.x + threadIdx.x;
    if (i >= (long long)NTOK * 256 / 2) return;
    float2 a = ((const float2*)g_part[0])[i];
    float2 b = ((const float2*)g_part[1])[i];
    ((uint32_t*)dst)[i] = pack_bf16x2(a.x + b.x, a.y + b.y);
}

// ---------------- flash attention: 128 Q rows/CTA, KV tiles of 64, online softmax (log2 domain) ----------------
#define FBN 64
#define KVP 72   // smem pitch (elems)
#define L2E 1.4426950408889634f

__global__ __launch_bounds__(256) void flash_kernel(const float* __restrict__ mask)
{
    __shared__ bf16 Ks[2][FBN * KVP];
    __shared__ bf16 Vs[2][FBN * KVP];
    __shared__ float Ms[2][FBN];

    int z = blockIdx.y;
    int bq = z / NHEAD, h = z - bq * NHEAD;
    int m0 = blockIdx.x * 128;
    int tid = threadIdx.x, wid = tid >> 5, lane = tid & 31;
    int wm = wid * 16;

    const bf16* Qg = g_q + ((size_t)z * SEQ + m0) * DH;
    const bf16* Kg = g_k + (size_t)z * SEQ * DH;
    const bf16* Vg = g_v + (size_t)z * SEQ * DH;
    const float* mg = mask + (size_t)bq * SEQ;

    uint32_t ks0 = smem_u32(Ks), vs0 = smem_u32(Vs), ms0 = smem_u32(Ms);

    // Q a-fragments straight from gmem (one-time)
    uint32_t qa[4][4];
    {
        const bf16* q0 = Qg + (size_t)(wm + (lane >> 2)) * DH + ((lane & 3) << 1);
#pragma unroll
        for (int t = 0; t < 4; t++) {
            qa[t][0] = *(const uint32_t*)(q0 + t * 16);
            qa[t][1] = *(const uint32_t*)(q0 + 8 * DH + t * 16);
            qa[t][2] = *(const uint32_t*)(q0 + t * 16 + 8);
            qa[t][3] = *(const uint32_t*)(q0 + 8 * DH + t * 16 + 8);
        }
    }

    // prefetch helper
    auto prefetch = [&](int s, int n0) {
        uint32_t kb = ks0 + (uint32_t)(s * FBN * KVP) * 2;
        uint32_t vb = vs0 + (uint32_t)(s * FBN * KVP) * 2;
        for (int i = tid; i < FBN * 8; i += 256) {
            int r = i >> 3, c = (i & 7) << 3;
            CPASYNC16(kb + (uint32_t)(r * KVP + c) * 2, Kg + (size_t)(n0 + r) * DH + c);
            CPASYNC16(vb + (uint32_t)(r * KVP + c) * 2, Vg + (size_t)(n0 + r) * DH + c);
        }
        if (tid < 16)
            CPASYNC16(ms0 + (uint32_t)(s * FBN + tid * 4) * 4, mg + n0 + tid * 4);
    };

    prefetch(0, 0);
    CPCOMMIT();

    float o[8][4];
#pragma unroll
    for (int i = 0; i < 8; i++)
#pragma unroll
        for (int j = 0; j < 4; j++) o[i][j] = 0.f;
    float mi0 = -1e30f, mi1 = -1e30f, li0 = 0.f, li1 = 0.f;

    const float SCL = 0.125f * L2E;   // S scale folded with log2e

    for (int s = 0; s < SEQ / FBN; s++) {
        int buf = s & 1;
        if (s + 1 < SEQ / FBN) {
            prefetch(buf ^ 1, (s + 1) * FBN);
            CPCOMMIT();
            CPWAIT(1);
        } else {
            CPWAIT(0);
        }
        __syncthreads();

        uint32_t kb = ks0 + (uint32_t)(buf * FBN * KVP) * 2;
        uint32_t vb = vs0 + (uint32_t)(buf * FBN * KVP) * 2;

        // S = Q @ K^T  (16 x 64 per warp, fp32)
        float c[8][4];
#pragma unroll
        for (int nt = 0; nt < 8; nt++)
#pragma unroll
            for (int i = 0; i < 4; i++) c[nt][i] = 0.f;
        int l = lane & 15;
#pragma unroll
        for (int t = 0; t < 4; t++) {
#pragma unroll
            for (int nt = 0; nt < 8; nt++) {
                uint32_t b[2];
                ldsm2(b, kb + (uint32_t)((nt * 8 + (l & 7)) * KVP + t * 16 + ((l >> 3) & 1) * 8) * 2);
                mma16816(c[nt], qa[t], b);
            }
        }

        // scale + mask + online softmax (all in log2 domain)
        float mx0 = -1e30f, mx1 = -1e30f;
#pragma unroll
        for (int nt = 0; nt < 8; nt++) {
            int col = nt * 8 + ((lane & 3) << 1);
            float mk0 = Ms[buf][col] * L2E, mk1 = Ms[buf][col + 1] * L2E;
            c[nt][0] = c[nt][0] * SCL + mk0;
            c[nt][1] = c[nt][1] * SCL + mk1;
            c[nt][2] = c[nt][2] * SCL + mk0;
            c[nt][3] = c[nt][3] * SCL + mk1;
            mx0 = fmaxf(mx0, fmaxf(c[nt][0], c[nt][1]));
            mx1 = fmaxf(mx1, fmaxf(c[nt][2], c[nt][3]));
        }
        mx0 = fmaxf(mx0, __shfl_xor_sync(0xffffffffu, mx0, 1));
        mx0 = fmaxf(mx0, __shfl_xor_sync(0xffffffffu, mx0, 2));
        mx1 = fmaxf(mx1, __shfl_xor_sync(0xffffffffu, mx1, 1));
        mx1 = fmaxf(mx1, __shfl_xor_sync(0xffffffffu, mx1, 2));
        float nm0 = fmaxf(mi0, mx0), nm1 = fmaxf(mi1, mx1);
        float a0 = exp2f(mi0 - nm0), a1 = exp2f(mi1 - nm1);
        float s0 = 0.f, s1 = 0.f;
#pragma unroll
        for (int nt = 0; nt < 8; nt++) {
            c[nt][0] = exp2f(c[nt][0] - nm0);
            c[nt][1] = exp2f(c[nt][1] - nm0);
            c[nt][2] = exp2f(c[nt][2] - nm1);
            c[nt][3] = exp2f(c[nt][3] - nm1);
            s0 += c[nt][0] + c[nt][1];
            s1 += c[nt][2] + c[nt][3];
        }
        s0 += __shfl_xor_sync(0xffffffffu, s0, 1);
        s0 += __shfl_xor_sync(0xffffffffu, s0, 2);
        s1 += __shfl_xor_sync(0xffffffffu, s1, 1);
        s1 += __shfl_xor_sync(0xffffffffu, s1, 2);
        li0 = li0 * a0 + s0;
        li1 = li1 * a1 + s1;
        mi0 = nm0; mi1 = nm1;
#pragma unroll
        for (int dt = 0; dt < 8; dt++) {
            o[dt][0] *= a0; o[dt][1] *= a0;
            o[dt][2] *= a1; o[dt][3] *= a1;
        }

        // O += P @ V   (P packed bf16 from c, V b-frags via trans ldmatrix)
#pragma unroll
        for (int t = 0; t < 4; t++) {
            uint32_t pa[4];
            pa[0] = pack_bf16x2(c[2 * t][0], c[2 * t][1]);
            pa[1] = pack_bf16x2(c[2 * t][2], c[2 * t][3]);
            pa[2] = pack_bf16x2(c[2 * t + 1][0], c[2 * t + 1][1]);
            pa[3] = pack_bf16x2(c[2 * t + 1][2], c[2 * t + 1][3]);
#pragma unroll
            for (int dt = 0; dt < 8; dt++) {
                uint32_t b[2];
                ldsm2t(b, vb + (uint32_t)((t * 16 + l) * KVP + dt * 8) * 2);
                mma16816(o[dt], pa, b);
            }
        }
        __syncthreads();
    }

    // epilogue
    float inv0 = 1.f / li0, inv1 = 1.f / li1;
    int r0 = m0 + wm + (lane >> 2);
    bf16* out0 = g_attnb + ((size_t)(bq * SEQ + r0)) * DMODEL + h * DH;
    bf16* out1 = out0 + (size_t)8 * DMODEL;
#pragma unroll
    for (int dt = 0; dt < 8; dt++) {
        int col = dt * 8 + ((lane & 3) << 1);
        *(uint32_t*)(out0 + col) = pack_bf16x2(o[dt][0] * inv0, o[dt][1] * inv0);
        *(uint32_t*)(out1 + col) = pack_bf16x2(o[dt][2] * inv1, o[dt][3] * inv1);
    }
}

// ---------------- fp32 -> bf16 convert ----------------
__global__ void f2b_kernel(const float* __restrict__ src, bf16* __restrict__ dst, long long n2)
{
    long long i = (long long)blockIdx.x * blockDim.x + threadIdx.x;
    if (i >= n2) return;
    float2 v = ((const float2*)src)[i];
    ((uint32_t*)dst)[i] = pack_bf16x2(v.x, v.y);
}

// ---------------- fuse low-rank QKV weights (transposed, bf16) ----------------
__global__ void fuse_w_kernel(const float* __restrict__ Pq, const float* __restrict__ Vq, const float* __restrict__ bq,
                              const float* __restrict__ Pk, const float* __restrict__ Vk, const float* __restrict__ bk,
                              const float* __restrict__ Pv, const float* __restrict__ Vv, const float* __restrict__ bv)
{
    int idx = blockIdx.x * blockDim.x + threadIdx.x;
    if (idx >= DMODEL * QKVN) return;
    int c = idx / DMODEL;
    int d = idx - c * DMODEL;
    int p = c / DMODEL;
    int c2 = c - p * DMODEL;
    int h = c2 >> 6, j = c2 & 63;
    const float* P = (p == 0) ? Pq : (p == 1) ? Pk : Pv;
    const float* V = (p == 0) ? Vq : (p == 1) ? Vk : Vv;
    const float* Bv_ = (p == 0) ? bq : (p == 1) ? bk : bv;
    const float* Ph = P + (size_t)h * DMODEL * 32 + (size_t)d * 32;
    const float* Vh = V + (size_t)h * 32 * DH + j;
    float s = 0.f;
#pragma unroll
    for (int r = 0; r < 32; r++) s += Ph[r] * Vh[(size_t)r * DH];
    g_Wtb[(size_t)c * DMODEL + d] = __float2bfloat16(s);
    if (d == 0) g_bqkv[c] = Bv_[h * DH + j];
}

// ---------------- batched weight transpose fp32 -> bf16 (all 6 in one launch) ----------------
// tile counts: Uo 192, Vo 192, U1 192, V1 768, U2 768, V2 192  (total 2304)
__global__ void transpose_all(const float* __restrict__ Uo, const float* __restrict__ Vo,
                              const float* __restrict__ U1, const float* __restrict__ V1,
                              const float* __restrict__ U2, const float* __restrict__ V2)
{
    __shared__ float t[32][33];
    int tidx = blockIdx.x;
    const float* src; bf16* dst; int R, C, local;
    if (tidx < 192)        { src = Uo; dst = g_Uot; R = DMODEL; C = 256;  local = tidx; }
    else if (tidx < 384)   { src = Vo; dst = g_Vot; R = 256; C = DMODEL;  local = tidx - 192; }
    else if (tidx < 576)   { src = U1; dst = g_U1t; R = DMODEL; C = 256;  local = tidx - 384; }
    else if (tidx < 1344)  { src = V1; dst = g_V1t; R = 256; C = FDIM;    local = tidx - 576; }
    else if (tidx < 2112)  { src = U2; dst = g_U2t; R = FDIM; C = 256;    local = tidx - 1344; }
    else                   { src = V2; dst = g_V2t; R = 256; C = DMODEL;  local = tidx - 2112; }
    int tilesX = C / 32;
    int tx = local % tilesX, ty = local / tilesX;
    int c0 = tx * 32, r0 = ty * 32;
    int x = threadIdx.x, y = threadIdx.y;
    for (int i = 0; i < 32; i += 8) t[y + i][x] = src[(size_t)(r0 + y + i) * C + c0 + x];
    __syncthreads();
    for (int i = 0; i < 32; i += 8) dst[(size_t)(c0 + y + i) * R + r0 + x] = __float2bfloat16(t[x][y + i]);
}

// ---------------- LayerNorm (fp32 out + optional bf16 out) ----------------
__global__ __launch_bounds__(256) void ln_kernel(const float* __restrict__ in,
                                                 const float* __restrict__ gam,
                                                 const float* __restrict__ bet,
                                                 float* __restrict__ outF,
                                                 bf16* __restrict__ outB)
{
    int row = blockIdx.x;
    int t = threadIdx.x;
    const float* ip = in + (size_t)row * DMODEL;
    float x0 = ip[t], x1 = ip[t + 256], x2 = ip[t + 512];
    __shared__ float rs[256], rq[256];
    rs[t] = x0 + x1 + x2;
    rq[t] = x0 * x0 + x1 * x1 + x2 * x2;
    __syncthreads();
    for (int off = 128; off > 0; off >>= 1) {
        if (t < off) { rs[t] += rs[t + off]; rq[t] += rq[t + off]; }
        __syncthreads();
    }
    float mu = rs[0] * (1.f / 768.f);
    float var = rq[0] * (1.f / 768.f) - mu * mu;
    float rstd = rsqrtf(var + 1e-12f);
    float y0 = (x0 - mu) * rstd * gam[t] + bet[t];
    float y1 = (x1 - mu) * rstd * gam[t + 256] + bet[t + 256];
    float y2 = (x2 - mu) * rstd * gam[t + 512] + bet[t + 512];
    float* op = outF + (size_t)row * DMODEL;
    op[t] = y0; op[t + 256] = y1; op[t + 512] = y2;
    if (outB) {
        bf16* ob = outB + (size_t)row * DMODEL;
        ob[t] = __float2bfloat16(y0);
        ob[t + 256] = __float2bfloat16(y1);
        ob[t + 512] = __float2bfloat16(y2);
    }
}

// ---------------- launch ----------------
extern "C" void kernel_launch(void* const* d_in, const int* in_sizes, int n_in,
                              void* d_out, int out_size)
{
    const float* x    = (const float*)d_in[0];
    const float* mask = (const float*)d_in[1];
    const float* Pq = (const float*)d_in[2];
    const float* Vq = (const float*)d_in[3];
    const float* bq = (const float*)d_in[4];
    const float* Pk = (const float*)d_in[5];
    const float* Vk = (const float*)d_in[6];
    const float* bk = (const float*)d_in[7];
    const float* Pv = (const float*)d_in[8];
    const float* Vv = (const float*)d_in[9];
    const float* bv = (const float*)d_in[10];
    const float* Uo = (const float*)d_in[11];
    const float* Vo = (const float*)d_in[12];
    const float* bo = (const float*)d_in[13];
    const float* U1 = (const float*)d_in[14];
    const float* V1 = (const float*)d_in[15];
    const float* b1 = (const float*)d_in[16];
    const float* U2 = (const float*)d_in[17];
    const float* V2 = (const float*)d_in[18];
    const float* b2 = (const float*)d_in[19];
    const float* g1 = (const float*)d_in[20];
    const float* be1 = (const float*)d_in[21];
    const float* g2 = (const float*)d_in[22];
    const float* be2 = (const float*)d_in[23];

    float *bqkv, *pre, *x1f, *part;
    bf16 *xb, *Wtb, *attnb, *t256b, *mid, *x1b;
    bf16 *Uot, *Vot, *U1t, *V1t, *U2t, *V2t;
    cudaGetSymbolAddress((void**)&xb,    g_xb);
    cudaGetSymbolAddress((void**)&Wtb,   g_Wtb);
    cudaGetSymbolAddress((void**)&bqkv,  g_bqkv);
    cudaGetSymbolAddress((void**)&attnb, g_attnb);
    cudaGetSymbolAddress((void**)&t256b, g_t256b);
    cudaGetSymbolAddress((void**)&mid,   g_mid);
    cudaGetSymbolAddress((void**)&part,  g_part);
    cudaGetSymbolAddress((void**)&pre,   g_pre);
    cudaGetSymbolAddress((void**)&x1f,   g_x1);
    cudaGetSymbolAddress((void**)&x1b,   g_x1b);
    cudaGetSymbolAddress((void**)&Uot,   g_Uot);
    cudaGetSymbolAddress((void**)&Vot,   g_Vot);
    cudaGetSymbolAddress((void**)&U1t,   g_U1t);
    cudaGetSymbolAddress((void**)&V1t,   g_V1t);
    cudaGetSymbolAddress((void**)&U2t,   g_U2t);
    cudaGetSymbolAddress((void**)&V2t,   g_V2t);

    dim3 tb(32, 8);

    // 0) x -> bf16
    f2b_kernel<<<(NTOK * DMODEL / 2 + 255) / 256, 256>>>(x, xb, (long long)NTOK * DMODEL / 2);
    // 1) fold low-rank QKV weights
    fuse_w_kernel<<<(DMODEL * QKVN + 255) / 256, 256>>>(Pq, Vq, bq, Pk, Vk, bk, Pv, Vv, bv);
    // 2) all six weight transposes in one launch
    transpose_all<<<2304, tb>>>(Uo, Vo, U1, V1, U2, V2);

    // 3) QKV = xb @ Wtb^T + bias -> q/k/v planes (bf16)
    bmma_gemm<128, 3><<<dim3(QKVN / 128, NTOK / 128, 1), 256>>>(
        xb, Wtb, DMODEL, DMODEL, DMODEL, 0, 0,
        nullptr, nullptr, bqkv, nullptr, 0, 0);

    // 4) fused flash attention -> g_attnb [B*M, 768]
    flash_kernel<<<dim3(SEQ / 128, BH), 256>>>(mask);

    // 5) t_part[z] = attn[:, z*384:] @ Uot[:, z*384:]  (split-K x2)
    bmma_gemm<128, 5><<<dim3(2, NTOK / 128, 2), 256>>>(
        attnb, Uot, DMODEL / 2, DMODEL, DMODEL, DMODEL / 2, DMODEL / 2,
        part, nullptr, nullptr, nullptr, 256, (long long)NTOK * 256);
    // 6) combine -> t256b
    combine_kernel<<<(NTOK * 256 / 2 + 255) / 256, 256>>>(t256b);
    // 7) pre1 = t @ Vo + bo + x
    bmma_gemm<128, 1><<<dim3(DMODEL / 128, NTOK / 128, 1), 256>>>(
        t256b, Vot, 256, 256, 256, 0, 0,
        pre, nullptr, bo, x, DMODEL, 0);
    // 8) LN1 -> x1 (fp32 + bf16)
    ln_kernel<<<NTOK, 256>>>(pre, g1, be1, x1f, x1b);
    // 9) t_part[z] = x1[:, z*384:] @ U1t[:, z*384:]  (split-K x2)
    bmma_gemm<128, 5><<<dim3(2, NTOK / 128, 2), 256>>>(
        x1b, U1t, DMODEL / 2, DMODEL, DMODEL, DMODEL / 2, DMODEL / 2,
        part, nullptr, nullptr, nullptr, 256, (long long)NTOK * 256);
    // 10) combine -> t256b
    combine_kernel<<<(NTOK * 256 / 2 + 255) / 256, 256>>>(t256b);
    // 11) mid = gelu(t @ V1 + b1) -> bf16
    bmma_gemm<128, 2><<<dim3(FDIM / 128, NTOK / 128, 1), 256>>>(
        t256b, V1t, 256, 256, 256, 0, 0,
        nullptr, mid, b1, nullptr, FDIM, 0);
    // 12) t_part[z] = mid[:, z*1536:] @ U2t[:, z*1536:]  (split-K x2)
    bmma_gemm<128, 5><<<dim3(2, NTOK / 128, 2), 256>>>(
        mid, U2t, FDIM / 2, FDIM, FDIM, FDIM / 2, FDIM / 2,
        part, nullptr, nullptr, nullptr, 256, (long long)NTOK * 256);
    // 13) combine -> t256b
    combine_kernel<<<(NTOK * 256 / 2 + 255) / 256, 256>>>(t256b);
    // 14) pre2 = t @ V2 + b2 + x1
    bmma_gemm<128, 1><<<dim3(DMODEL / 128, NTOK / 128, 1), 256>>>(
        t256b, V2t, 256, 256, 256, 0, 0,
        pre, nullptr, b2, x1f, DMODEL, 0);
    // 15) LN2 -> out (fp32)
    ln_kernel<<<NTOK, 256>>>(pre, g2, be2, (float*)d_out, nullptr);
}

// round 12
// speedup vs baseline: 8.6804x; 1.0362x over previous
#include <cuda_runtime.h>
#include <cuda_bf16.h>
#include <math.h>
#include <stdint.h>

// ---------------- problem constants ----------------
#define BATCH 4
#define SEQ   2048
#define DMODEL 768
#define NHEAD 12
#define DH    64
#define NTOK  (BATCH*SEQ)          // 8192
#define QKVN  (3*DMODEL)           // 2304
#define FDIM  3072
#define BH    (BATCH*NHEAD)        // 48

typedef __nv_bfloat16 bf16;
typedef __nv_bfloat162 bf162;

// ---------------- scratch (__device__ globals; no allocation) ----------------
__device__ bf16 g_xb[(size_t)NTOK*DMODEL];
__device__ bf16 g_Wtb[(size_t)QKVN*DMODEL];            // [2304][768]
__device__ float g_bqkv[QKVN];
__device__ bf16 g_q[(size_t)BH*SEQ*DH];                // [48][2048][64]
__device__ bf16 g_k[(size_t)BH*SEQ*DH];
__device__ bf16 g_v[(size_t)BH*SEQ*DH];
__device__ bf16 g_attnb[(size_t)NTOK*DMODEL];
__device__ bf16 g_t256b[(size_t)NTOK*256];
__device__ bf16 g_mid[(size_t)NTOK*FDIM];
__device__ float g_part[2][(size_t)NTOK*256];          // split-K fp32 partials
__device__ float g_pre[(size_t)NTOK*DMODEL];
__device__ float g_x1[(size_t)NTOK*DMODEL];
__device__ bf16 g_x1b[(size_t)NTOK*DMODEL];
__device__ bf16 g_Uot[256*DMODEL];
__device__ bf16 g_Vot[DMODEL*256];
__device__ bf16 g_U1t[256*DMODEL];
__device__ bf16 g_V1t[FDIM*256];
__device__ bf16 g_U2t[256*FDIM];
__device__ bf16 g_V2t[DMODEL*256];

// ---------------- PTX helpers (base ISA only: sm_80-compatible) ----------------
__device__ __forceinline__ uint32_t smem_u32(const void* p) {
    uint32_t a;
    asm("{ .reg .u64 t; cvta.to.shared.u64 t, %1; cvt.u32.u64 %0, t; }" : "=r"(a) : "l"(p));
    return a;
}
__device__ __forceinline__ uint32_t pack_bf16x2(float lo, float hi) {
    uint32_t r;
    asm("cvt.rn.bf16x2.f32 %0, %1, %2;" : "=r"(r) : "f"(hi), "f"(lo));
    return r;
}
#define CPASYNC16(dst, src) asm volatile("cp.async.cg.shared.global [%0], [%1], 16;" :: "r"(dst), "l"(src))
#define CPCOMMIT()          asm volatile("cp.async.commit_group;" ::: "memory")
#define CPWAIT(n)           asm volatile("cp.async.wait_group %0;" :: "n"(n) : "memory")

__device__ __forceinline__ void ldsm4(uint32_t* r, uint32_t a) {
    asm volatile("ldmatrix.sync.aligned.m8n8.x4.shared.b16 {%0,%1,%2,%3}, [%4];"
        : "=r"(r[0]), "=r"(r[1]), "=r"(r[2]), "=r"(r[3]) : "r"(a));
}
__device__ __forceinline__ void ldsm2(uint32_t* r, uint32_t a) {
    asm volatile("ldmatrix.sync.aligned.m8n8.x2.shared.b16 {%0,%1}, [%2];"
        : "=r"(r[0]), "=r"(r[1]) : "r"(a));
}
__device__ __forceinline__ void ldsm2t(uint32_t* r, uint32_t a) {
    asm volatile("ldmatrix.sync.aligned.m8n8.x2.trans.shared.b16 {%0,%1}, [%2];"
        : "=r"(r[0]), "=r"(r[1]) : "r"(a));
}
__device__ __forceinline__ void mma16816(float* c, const uint32_t* a, const uint32_t* b) {
    asm volatile("mma.sync.aligned.m16n8k16.row.col.f32.bf16.bf16.f32 "
        "{%0,%1,%2,%3}, {%4,%5,%6,%7}, {%8,%9}, {%0,%1,%2,%3};"
        : "+f"(c[0]), "+f"(c[1]), "+f"(c[2]), "+f"(c[3])
        : "r"(a[0]), "r"(a[1]), "r"(a[2]), "r"(a[3]), "r"(b[0]), "r"(b[1]));
}

__device__ __forceinline__ float gelu_exact(float a) {
    return 0.5f * a * (1.f + erff(a * 0.70710678118654752f));
}

// ---------------- generic bf16 mma GEMM: C[128 x BN] = A[M,K] @ B[N,K]^T ----------------
// 3-stage cp.async pipeline, dynamic smem.
// EPI: 0 = bf16 out
//      1 = f32 out = v + bias[gn] + res[...]
//      2 = bf16 out = gelu(v + bias[gn])
//      3 = QKV scatter (+bias) into g_q/g_k/g_v planes
//      5 = f32 partial out at z-indexed buffer (split-K; z also offsets A,B by sA,sB)
#define BM 128
#define BK 32
#define RST 40
#define STG 3

template<int BN, int EPI>
__global__ __launch_bounds__(256) void bmma_gemm(
    const bf16* __restrict__ A, const bf16* __restrict__ B,
    int K, int ldA, int ldB, long long sA, long long sB,
    float* __restrict__ outF, bf16* __restrict__ outB,
    const float* __restrict__ bias, const float* __restrict__ res,
    int ldC, long long sC)
{
    constexpr int NT = BN / 32;
    constexpr int ACH = BM * 4;
    constexpr int TCH = (BM + BN) * 4;
    constexpr int SSA = BM * RST;
    constexpr int SS  = (BM + BN) * RST;

    extern __shared__ bf16 sm[];

    int tid = threadIdx.x;
    int z = blockIdx.z;
    const bf16* Ab = A + (long long)z * sA + (long long)blockIdx.y * BM * ldA;
    const bf16* Bb = B + (long long)z * sB + (long long)blockIdx.x * BN * ldB;
    uint32_t smu = smem_u32(sm);

    float acc[4][NT][4];
#pragma unroll
    for (int i = 0; i < 4; i++)
#pragma unroll
        for (int j = 0; j < NT; j++)
#pragma unroll
            for (int k = 0; k < 4; k++) acc[i][j][k] = 0.f;

    int wid = tid >> 5, lane = tid & 31;
    int wm = (wid >> 2) * 64;
    int wn = (wid & 3) * (BN / 4);

    int nch = K / BK;

    auto prefetch = [&](int c) {
        uint32_t base = smu + (uint32_t)((c % STG) * SS) * 2;
        long long kof = (long long)c * BK;
        for (int i = tid; i < TCH; i += 256) {
            if (i < ACH) {
                int row = i >> 2, c16 = i & 3;
                CPASYNC16(base + (uint32_t)(row * RST + c16 * 8) * 2,
                          Ab + (long long)row * ldA + kof + c16 * 8);
            } else {
                int j = i - ACH;
                int row = j >> 2, c16 = j & 3;
                CPASYNC16(base + (uint32_t)(SSA + row * RST + c16 * 8) * 2,
                          Bb + (long long)row * ldB + kof + c16 * 8);
            }
        }
        CPCOMMIT();
    };

    prefetch(0);
    if (nch > 1) prefetch(1);

    for (int c = 0; c < nch; c++) {
        if (c + 2 < nch) { prefetch(c + 2); CPWAIT(2); }
        else if (c + 1 < nch) { CPWAIT(1); }
        else { CPWAIT(0); }
        __syncthreads();

        uint32_t Abase = smu + (uint32_t)((c % STG) * SS) * 2;
        uint32_t Bbase = Abase + (uint32_t)SSA * 2;
#pragma unroll
        for (int ks = 0; ks < 2; ks++) {
            uint32_t a[4][4], b[NT][2];
#pragma unroll
            for (int mt = 0; mt < 4; mt++) {
                uint32_t ad = Abase + (uint32_t)((wm + mt * 16 + (lane & 15)) * RST + ks * 16 + (lane >> 4) * 8) * 2;
                ldsm4(a[mt], ad);
            }
#pragma unroll
            for (int nt = 0; nt < NT; nt++) {
                int l = lane & 15;
                uint32_t bd = Bbase + (uint32_t)((wn + nt * 8 + (l & 7)) * RST + ks * 16 + ((l >> 3) & 1) * 8) * 2;
                ldsm2(b[nt], bd);
            }
#pragma unroll
            for (int mt = 0; mt < 4; mt++)
#pragma unroll
                for (int nt = 0; nt < NT; nt++)
                    mma16816(acc[mt][nt], a[mt], b[nt]);
        }
        __syncthreads();
    }

    int m0 = blockIdx.y * BM, n0 = blockIdx.x * BN;
#pragma unroll
    for (int mt = 0; mt < 4; mt++)
#pragma unroll
        for (int nt = 0; nt < NT; nt++)
#pragma unroll
            for (int h2 = 0; h2 < 2; h2++) {
                int gm = m0 + wm + mt * 16 + (lane >> 2) + h2 * 8;
                int gn = n0 + wn + nt * 8 + ((lane & 3) << 1);
                float v0 = acc[mt][nt][h2 * 2];
                float v1 = acc[mt][nt][h2 * 2 + 1];
                if (EPI == 0) {
                    bf16* p = outB + (long long)z * sC + (long long)gm * ldC + gn;
                    *(uint32_t*)p = pack_bf16x2(v0, v1);
                } else if (EPI == 1) {
                    long long o = (long long)gm * ldC + gn;
                    outF[o]     = v0 + bias[gn]     + res[o];
                    outF[o + 1] = v1 + bias[gn + 1] + res[o + 1];
                } else if (EPI == 2) {
                    float a0 = gelu_exact(v0 + bias[gn]);
                    float a1 = gelu_exact(v1 + bias[gn + 1]);
                    bf16* p = outB + (long long)gm * ldC + gn;
                    *(uint32_t*)p = pack_bf16x2(a0, a1);
                } else if (EPI == 3) {
                    float a0 = v0 + bias[gn];
                    float a1 = v1 + bias[gn + 1];
                    int pp = gn / DMODEL;
                    int c2 = gn - pp * DMODEL;
                    int h = c2 >> 6, j = c2 & 63;
                    int b_ = gm >> 11, m = gm & 2047;
                    bf16* pl = (pp == 0 ? g_q : (pp == 1 ? g_k : g_v))
                             + (((long long)(b_ * NHEAD + h) << 11) + m) * DH + j;
                    *(uint32_t*)pl = pack_bf16x2(a0, a1);
                } else if (EPI == 5) {
                    float* op = outF + (long long)z * sC + (long long)gm * ldC + gn;
                    *(float2*)op = make_float2(v0, v1);
                }
            }
}

// ---------------- split-K combine: t256b = bf16(part0 + part1) ----------------
__global__ void combine_kernel(bf16* __restrict__ dst)
{
    long long i = (long long)blockIdx.x * blockDim.x + threadIdx.x;
    if (i >= (long long)NTOK * 256 / 2) return;
    float2 a = ((const float2*)g_part[0])[i];
    float2 b = ((const float2*)g_part[1])[i];
    ((uint32_t*)dst)[i] = pack_bf16x2(a.x + b.x, a.y + b.y);
}

// ---------------- flash attention: 128 Q rows/CTA, KV tiles of 64, online softmax (log2 domain) ----------------
#define FBN 64
#define KVP 72   // smem pitch (elems)
#define L2E 1.4426950408889634f

__global__ __launch_bounds__(256) void flash_kernel(const float* __restrict__ mask)
{
    __shared__ bf16 Ks[2][FBN * KVP];
    __shared__ bf16 Vs[2][FBN * KVP];
    __shared__ float Ms[2][FBN];

    int z = blockIdx.y;
    int bq = z / NHEAD, h = z - bq * NHEAD;
    int m0 = blockIdx.x * 128;
    int tid = threadIdx.x, wid = tid >> 5, lane = tid & 31;
    int wm = wid * 16;

    const bf16* Qg = g_q + ((size_t)z * SEQ + m0) * DH;
    const bf16* Kg = g_k + (size_t)z * SEQ * DH;
    const bf16* Vg = g_v + (size_t)z * SEQ * DH;
    const float* mg = mask + (size_t)bq * SEQ;

    uint32_t ks0 = smem_u32(Ks), vs0 = smem_u32(Vs), ms0 = smem_u32(Ms);

    // Q a-fragments straight from gmem (one-time)
    uint32_t qa[4][4];
    {
        const bf16* q0 = Qg + (size_t)(wm + (lane >> 2)) * DH + ((lane & 3) << 1);
#pragma unroll
        for (int t = 0; t < 4; t++) {
            qa[t][0] = *(const uint32_t*)(q0 + t * 16);
            qa[t][1] = *(const uint32_t*)(q0 + 8 * DH + t * 16);
            qa[t][2] = *(const uint32_t*)(q0 + t * 16 + 8);
            qa[t][3] = *(const uint32_t*)(q0 + 8 * DH + t * 16 + 8);
        }
    }

    // prefetch helper
    auto prefetch = [&](int s, int n0) {
        uint32_t kb = ks0 + (uint32_t)(s * FBN * KVP) * 2;
        uint32_t vb = vs0 + (uint32_t)(s * FBN * KVP) * 2;
        for (int i = tid; i < FBN * 8; i += 256) {
            int r = i >> 3, c = (i & 7) << 3;
            CPASYNC16(kb + (uint32_t)(r * KVP + c) * 2, Kg + (size_t)(n0 + r) * DH + c);
            CPASYNC16(vb + (uint32_t)(r * KVP + c) * 2, Vg + (size_t)(n0 + r) * DH + c);
        }
        if (tid < 16)
            CPASYNC16(ms0 + (uint32_t)(s * FBN + tid * 4) * 4, mg + n0 + tid * 4);
    };

    prefetch(0, 0);
    CPCOMMIT();

    float o[8][4];
#pragma unroll
    for (int i = 0; i < 8; i++)
#pragma unroll
        for (int j = 0; j < 4; j++) o[i][j] = 0.f;
    float mi0 = -1e30f, mi1 = -1e30f, li0 = 0.f, li1 = 0.f;

    const float SCL = 0.125f * L2E;   // S scale folded with log2e

    for (int s = 0; s < SEQ / FBN; s++) {
        int buf = s & 1;
        if (s + 1 < SEQ / FBN) {
            prefetch(buf ^ 1, (s + 1) * FBN);
            CPCOMMIT();
            CPWAIT(1);
        } else {
            CPWAIT(0);
        }
        __syncthreads();

        uint32_t kb = ks0 + (uint32_t)(buf * FBN * KVP) * 2;
        uint32_t vb = vs0 + (uint32_t)(buf * FBN * KVP) * 2;

        // S = Q @ K^T  (16 x 64 per warp, fp32)
        float c[8][4];
#pragma unroll
        for (int nt = 0; nt < 8; nt++)
#pragma unroll
            for (int i = 0; i < 4; i++) c[nt][i] = 0.f;
        int l = lane & 15;
#pragma unroll
        for (int t = 0; t < 4; t++) {
#pragma unroll
            for (int nt = 0; nt < 8; nt++) {
                uint32_t b[2];
                ldsm2(b, kb + (uint32_t)((nt * 8 + (l & 7)) * KVP + t * 16 + ((l >> 3) & 1) * 8) * 2);
                mma16816(c[nt], qa[t], b);
            }
        }

        // scale + mask + online softmax (all in log2 domain)
        float mx0 = -1e30f, mx1 = -1e30f;
#pragma unroll
        for (int nt = 0; nt < 8; nt++) {
            int col = nt * 8 + ((lane & 3) << 1);
            float mk0 = Ms[buf][col] * L2E, mk1 = Ms[buf][col + 1] * L2E;
            c[nt][0] = c[nt][0] * SCL + mk0;
            c[nt][1] = c[nt][1] * SCL + mk1;
            c[nt][2] = c[nt][2] * SCL + mk0;
            c[nt][3] = c[nt][3] * SCL + mk1;
            mx0 = fmaxf(mx0, fmaxf(c[nt][0], c[nt][1]));
            mx1 = fmaxf(mx1, fmaxf(c[nt][2], c[nt][3]));
        }
        mx0 = fmaxf(mx0, __shfl_xor_sync(0xffffffffu, mx0, 1));
        mx0 = fmaxf(mx0, __shfl_xor_sync(0xffffffffu, mx0, 2));
        mx1 = fmaxf(mx1, __shfl_xor_sync(0xffffffffu, mx1, 1));
        mx1 = fmaxf(mx1, __shfl_xor_sync(0xffffffffu, mx1, 2));
        float nm0 = fmaxf(mi0, mx0), nm1 = fmaxf(mi1, mx1);
        float a0 = exp2f(mi0 - nm0), a1 = exp2f(mi1 - nm1);
        float s0 = 0.f, s1 = 0.f;
#pragma unroll
        for (int nt = 0; nt < 8; nt++) {
            c[nt][0] = exp2f(c[nt][0] - nm0);
            c[nt][1] = exp2f(c[nt][1] - nm0);
            c[nt][2] = exp2f(c[nt][2] - nm1);
            c[nt][3] = exp2f(c[nt][3] - nm1);
            s0 += c[nt][0] + c[nt][1];
            s1 += c[nt][2] + c[nt][3];
        }
        s0 += __shfl_xor_sync(0xffffffffu, s0, 1);
        s0 += __shfl_xor_sync(0xffffffffu, s0, 2);
        s1 += __shfl_xor_sync(0xffffffffu, s1, 1);
        s1 += __shfl_xor_sync(0xffffffffu, s1, 2);
        li0 = li0 * a0 + s0;
        li1 = li1 * a1 + s1;
        mi0 = nm0; mi1 = nm1;
#pragma unroll
        for (int dt = 0; dt < 8; dt++) {
            o[dt][0] *= a0; o[dt][1] *= a0;
            o[dt][2] *= a1; o[dt][3] *= a1;
        }

        // O += P @ V   (P packed bf16 from c, V b-frags via trans ldmatrix)
#pragma unroll
        for (int t = 0; t < 4; t++) {
            uint32_t pa[4];
            pa[0] = pack_bf16x2(c[2 * t][0], c[2 * t][1]);
            pa[1] = pack_bf16x2(c[2 * t][2], c[2 * t][3]);
            pa[2] = pack_bf16x2(c[2 * t + 1][0], c[2 * t + 1][1]);
            pa[3] = pack_bf16x2(c[2 * t + 1][2], c[2 * t + 1][3]);
#pragma unroll
            for (int dt = 0; dt < 8; dt++) {
                uint32_t b[2];
                ldsm2t(b, vb + (uint32_t)((t * 16 + l) * KVP + dt * 8) * 2);
                mma16816(o[dt], pa, b);
            }
        }
        __syncthreads();
    }

    // epilogue
    float inv0 = 1.f / li0, inv1 = 1.f / li1;
    int r0 = m0 + wm + (lane >> 2);
    bf16* out0 = g_attnb + ((size_t)(bq * SEQ + r0)) * DMODEL + h * DH;
    bf16* out1 = out0 + (size_t)8 * DMODEL;
#pragma unroll
    for (int dt = 0; dt < 8; dt++) {
        int col = dt * 8 + ((lane & 3) << 1);
        *(uint32_t*)(out0 + col) = pack_bf16x2(o[dt][0] * inv0, o[dt][1] * inv0);
        *(uint32_t*)(out1 + col) = pack_bf16x2(o[dt][2] * inv1, o[dt][3] * inv1);
    }
}

// ---------------- fp32 -> bf16 convert ----------------
__global__ void f2b_kernel(const float* __restrict__ src, bf16* __restrict__ dst, long long n2)
{
    long long i = (long long)blockIdx.x * blockDim.x + threadIdx.x;
    if (i >= n2) return;
    float2 v = ((const float2*)src)[i];
    ((uint32_t*)dst)[i] = pack_bf16x2(v.x, v.y);
}

// ---------------- fuse low-rank QKV weights (transposed, bf16) ----------------
__global__ void fuse_w_kernel(const float* __restrict__ Pq, const float* __restrict__ Vq, const float* __restrict__ bq,
                              const float* __restrict__ Pk, const float* __restrict__ Vk, const float* __restrict__ bk,
                              const float* __restrict__ Pv, const float* __restrict__ Vv, const float* __restrict__ bv)
{
    int idx = blockIdx.x * blockDim.x + threadIdx.x;
    if (idx >= DMODEL * QKVN) return;
    int c = idx / DMODEL;
    int d = idx - c * DMODEL;
    int p = c / DMODEL;
    int c2 = c - p * DMODEL;
    int h = c2 >> 6, j = c2 & 63;
    const float* P = (p == 0) ? Pq : (p == 1) ? Pk : Pv;
    const float* V = (p == 0) ? Vq : (p == 1) ? Vk : Vv;
    const float* Bv_ = (p == 0) ? bq : (p == 1) ? bk : bv;
    const float* Ph = P + (size_t)h * DMODEL * 32 + (size_t)d * 32;
    const float* Vh = V + (size_t)h * 32 * DH + j;
    float s = 0.f;
#pragma unroll
    for (int r = 0; r < 32; r++) s += Ph[r] * Vh[(size_t)r * DH];
    g_Wtb[(size_t)c * DMODEL + d] = __float2bfloat16(s);
    if (d == 0) g_bqkv[c] = Bv_[h * DH + j];
}

// ---------------- batched weight transpose fp32 -> bf16 (all 6 in one launch) ----------------
__global__ void transpose_all(const float* __restrict__ Uo, const float* __restrict__ Vo,
                              const float* __restrict__ U1, const float* __restrict__ V1,
                              const float* __restrict__ U2, const float* __restrict__ V2)
{
    __shared__ float t[32][33];
    int tidx = blockIdx.x;
    const float* src; bf16* dst; int R, C, local;
    if (tidx < 192)        { src = Uo; dst = g_Uot; R = DMODEL; C = 256;  local = tidx; }
    else if (tidx < 384)   { src = Vo; dst = g_Vot; R = 256; C = DMODEL;  local = tidx - 192; }
    else if (tidx < 576)   { src = U1; dst = g_U1t; R = DMODEL; C = 256;  local = tidx - 384; }
    else if (tidx < 1344)  { src = V1; dst = g_V1t; R = 256; C = FDIM;    local = tidx - 576; }
    else if (tidx < 2112)  { src = U2; dst = g_U2t; R = FDIM; C = 256;    local = tidx - 1344; }
    else                   { src = V2; dst = g_V2t; R = 256; C = DMODEL;  local = tidx - 2112; }
    int tilesX = C / 32;
    int tx = local % tilesX, ty = local / tilesX;
    int c0 = tx * 32, r0 = ty * 32;
    int x = threadIdx.x, y = threadIdx.y;
    for (int i = 0; i < 32; i += 8) t[y + i][x] = src[(size_t)(r0 + y + i) * C + c0 + x];
    __syncthreads();
    for (int i = 0; i < 32; i += 8) dst[(size_t)(c0 + y + i) * R + r0 + x] = __float2bfloat16(t[x][y + i]);
}

// ---------------- LayerNorm (fp32 out + optional bf16 out) ----------------
__global__ __launch_bounds__(256) void ln_kernel(const float* __restrict__ in,
                                                 const float* __restrict__ gam,
                                                 const float* __restrict__ bet,
                                                 float* __restrict__ outF,
                                                 bf16* __restrict__ outB)
{
    int row = blockIdx.x;
    int t = threadIdx.x;
    const float* ip = in + (size_t)row * DMODEL;
    float x0 = ip[t], x1 = ip[t + 256], x2 = ip[t + 512];
    __shared__ float rs[256], rq[256];
    rs[t] = x0 + x1 + x2;
    rq[t] = x0 * x0 + x1 * x1 + x2 * x2;
    __syncthreads();
    for (int off = 128; off > 0; off >>= 1) {
        if (t < off) { rs[t] += rs[t + off]; rq[t] += rq[t + off]; }
        __syncthreads();
    }
    float mu = rs[0] * (1.f / 768.f);
    float var = rq[0] * (1.f / 768.f) - mu * mu;
    float rstd = rsqrtf(var + 1e-12f);
    float y0 = (x0 - mu) * rstd * gam[t] + bet[t];
    float y1 = (x1 - mu) * rstd * gam[t + 256] + bet[t + 256];
    float y2 = (x2 - mu) * rstd * gam[t + 512] + bet[t + 512];
    float* op = outF + (size_t)row * DMODEL;
    op[t] = y0; op[t + 256] = y1; op[t + 512] = y2;
    if (outB) {
        bf16* ob = outB + (size_t)row * DMODEL;
        ob[t] = __float2bfloat16(y0);
        ob[t + 256] = __float2bfloat16(y1);
        ob[t + 512] = __float2bfloat16(y2);
    }
}

// ---------------- launch ----------------
#define GEMM_SMEM (STG * (BM + 128) * RST * 2)   // 61440 bytes for BN=128

extern "C" void kernel_launch(void* const* d_in, const int* in_sizes, int n_in,
                              void* d_out, int out_size)
{
    const float* x    = (const float*)d_in[0];
    const float* mask = (const float*)d_in[1];
    const float* Pq = (const float*)d_in[2];
    const float* Vq = (const float*)d_in[3];
    const float* bq = (const float*)d_in[4];
    const float* Pk = (const float*)d_in[5];
    const float* Vk = (const float*)d_in[6];
    const float* bk = (const float*)d_in[7];
    const float* Pv = (const float*)d_in[8];
    const float* Vv = (const float*)d_in[9];
    const float* bv = (const float*)d_in[10];
    const float* Uo = (const float*)d_in[11];
    const float* Vo = (const float*)d_in[12];
    const float* bo = (const float*)d_in[13];
    const float* U1 = (const float*)d_in[14];
    const float* V1 = (const float*)d_in[15];
    const float* b1 = (const float*)d_in[16];
    const float* U2 = (const float*)d_in[17];
    const float* V2 = (const float*)d_in[18];
    const float* b2 = (const float*)d_in[19];
    const float* g1 = (const float*)d_in[20];
    const float* be1 = (const float*)d_in[21];
    const float* g2 = (const float*)d_in[22];
    const float* be2 = (const float*)d_in[23];

    float *bqkv, *pre, *x1f, *part;
    bf16 *xb, *Wtb, *attnb, *t256b, *mid, *x1b;
    bf16 *Uot, *Vot, *U1t, *V1t, *U2t, *V2t;
    cudaGetSymbolAddress((void**)&xb,    g_xb);
    cudaGetSymbolAddress((void**)&Wtb,   g_Wtb);
    cudaGetSymbolAddress((void**)&bqkv,  g_bqkv);
    cudaGetSymbolAddress((void**)&attnb, g_attnb);
    cudaGetSymbolAddress((void**)&t256b, g_t256b);
    cudaGetSymbolAddress((void**)&mid,   g_mid);
    cudaGetSymbolAddress((void**)&part,  g_part);
    cudaGetSymbolAddress((void**)&pre,   g_pre);
    cudaGetSymbolAddress((void**)&x1f,   g_x1);
    cudaGetSymbolAddress((void**)&x1b,   g_x1b);
    cudaGetSymbolAddress((void**)&Uot,   g_Uot);
    cudaGetSymbolAddress((void**)&Vot,   g_Vot);
    cudaGetSymbolAddress((void**)&U1t,   g_U1t);
    cudaGetSymbolAddress((void**)&V1t,   g_V1t);
    cudaGetSymbolAddress((void**)&U2t,   g_U2t);
    cudaGetSymbolAddress((void**)&V2t,   g_V2t);

    // opt-in to >48KB dynamic smem (idempotent)
    cudaFuncSetAttribute(bmma_gemm<128, 0>, cudaFuncAttributeMaxDynamicSharedMemorySize, GEMM_SMEM);
    cudaFuncSetAttribute(bmma_gemm<128, 1>, cudaFuncAttributeMaxDynamicSharedMemorySize, GEMM_SMEM);
    cudaFuncSetAttribute(bmma_gemm<128, 2>, cudaFuncAttributeMaxDynamicSharedMemorySize, GEMM_SMEM);
    cudaFuncSetAttribute(bmma_gemm<128, 3>, cudaFuncAttributeMaxDynamicSharedMemorySize, GEMM_SMEM);
    cudaFuncSetAttribute(bmma_gemm<128, 5>, cudaFuncAttributeMaxDynamicSharedMemorySize, GEMM_SMEM);

    dim3 tb(32, 8);

    // 0) x -> bf16
    f2b_kernel<<<(NTOK * DMODEL / 2 + 255) / 256, 256>>>(x, xb, (long long)NTOK * DMODEL / 2);
    // 1) fold low-rank QKV weights
    fuse_w_kernel<<<(DMODEL * QKVN + 255) / 256, 256>>>(Pq, Vq, bq, Pk, Vk, bk, Pv, Vv, bv);
    // 2) all six weight transposes in one launch
    transpose_all<<<2304, tb>>>(Uo, Vo, U1, V1, U2, V2);

    // 3) QKV = xb @ Wtb^T + bias -> q/k/v planes (bf16)
    bmma_gemm<128, 3><<<dim3(QKVN / 128, NTOK / 128, 1), 256, GEMM_SMEM>>>(
        xb, Wtb, DMODEL, DMODEL, DMODEL, 0, 0,
        nullptr, nullptr, bqkv, nullptr, 0, 0);

    // 4) fused flash attention -> g_attnb [B*M, 768]
    flash_kernel<<<dim3(SEQ / 128, BH), 256>>>(mask);

    // 5) t_part[z] = attn[:, z*384:] @ Uot[:, z*384:]  (split-K x2)
    bmma_gemm<128, 5><<<dim3(2, NTOK / 128, 2), 256, GEMM_SMEM>>>(
        attnb, Uot, DMODEL / 2, DMODEL, DMODEL, DMODEL / 2, DMODEL / 2,
        part, nullptr, nullptr, nullptr, 256, (long long)NTOK * 256);
    // 6) combine -> t256b
    combine_kernel<<<(NTOK * 256 / 2 + 255) / 256, 256>>>(t256b);
    // 7) pre1 = t @ Vo + bo + x
    bmma_gemm<128, 1><<<dim3(DMODEL / 128, NTOK / 128, 1), 256, GEMM_SMEM>>>(
        t256b, Vot, 256, 256, 256, 0, 0,
        pre, nullptr, bo, x, DMODEL, 0);
    // 8) LN1 -> x1 (fp32 + bf16)
    ln_kernel<<<NTOK, 256>>>(pre, g1, be1, x1f, x1b);
    // 9) t_part[z] = x1[:, z*384:] @ U1t[:, z*384:]  (split-K x2)
    bmma_gemm<128, 5><<<dim3(2, NTOK / 128, 2), 256, GEMM_SMEM>>>(
        x1b, U1t, DMODEL / 2, DMODEL, DMODEL, DMODEL / 2, DMODEL / 2,
        part, nullptr, nullptr, nullptr, 256, (long long)NTOK * 256);
    // 10) combine -> t256b
    combine_kernel<<<(NTOK * 256 / 2 + 255) / 256, 256>>>(t256b);
    // 11) mid = gelu(t @ V1 + b1) -> bf16
    bmma_gemm<128, 2><<<dim3(FDIM / 128, NTOK / 128, 1), 256, GEMM_SMEM>>>(
        t256b, V1t, 256, 256, 256, 0, 0,
        nullptr, mid, b1, nullptr, FDIM, 0);
    // 12) t_part[z] = mid[:, z*1536:] @ U2t[:, z*1536:]  (split-K x2)
    bmma_gemm<128, 5><<<dim3(2, NTOK / 128, 2), 256, GEMM_SMEM>>>(
        mid, U2t, FDIM / 2, FDIM, FDIM, FDIM / 2, FDIM / 2,
        part, nullptr, nullptr, nullptr, 256, (long long)NTOK * 256);
    // 13) combine -> t256b
    combine_kernel<<<(NTOK * 256 / 2 + 255) / 256, 256>>>(t256b);
    // 14) pre2 = t @ V2 + b2 + x1
    bmma_gemm<128, 1><<<dim3(DMODEL / 128, NTOK / 128, 1), 256, GEMM_SMEM>>>(
        t256b, V2t, 256, 256, 256, 0, 0,
        pre, nullptr, b2, x1f, DMODEL, 0);
    // 15) LN2 -> out (fp32)
    ln_kernel<<<NTOK, 256>>>(pre, g2, be2, (float*)d_out, nullptr);
}

// round 13
// speedup vs baseline: 8.7629x; 1.0095x over previous
#include <cuda_runtime.h>
#include <cuda_bf16.h>
#include <math.h>
#include <stdint.h>

// ---------------- problem constants ----------------
#define BATCH 4
#define SEQ   2048
#define DMODEL 768
#define NHEAD 12
#define DH    64
#define NTOK  (BATCH*SEQ)          // 8192
#define QKVN  (3*DMODEL)           // 2304
#define FDIM  3072
#define BH    (BATCH*NHEAD)        // 48

typedef __nv_bfloat16 bf16;
typedef __nv_bfloat162 bf162;

// ---------------- scratch (__device__ globals; no allocation) ----------------
__device__ bf16 g_xb[(size_t)NTOK*DMODEL];
__device__ bf16 g_Wtb[(size_t)QKVN*DMODEL];            // [2304][768]
__device__ float g_bqkv[QKVN];
__device__ bf16 g_q[(size_t)BH*SEQ*DH];                // [48][2048][64]
__device__ bf16 g_k[(size_t)BH*SEQ*DH];
__device__ bf16 g_v[(size_t)BH*SEQ*DH];
__device__ bf16 g_attnb[(size_t)NTOK*DMODEL];
__device__ bf16 g_t256b[(size_t)NTOK*256];
__device__ bf16 g_mid[(size_t)NTOK*FDIM];
__device__ float g_part[2][(size_t)NTOK*256];          // split-K fp32 partials
__device__ float g_pre[(size_t)NTOK*DMODEL];
__device__ float g_x1[(size_t)NTOK*DMODEL];
__device__ bf16 g_x1b[(size_t)NTOK*DMODEL];
__device__ bf16 g_Uot[256*DMODEL];
__device__ bf16 g_Vot[DMODEL*256];
__device__ bf16 g_U1t[256*DMODEL];
__device__ bf16 g_V1t[FDIM*256];
__device__ bf16 g_U2t[256*FDIM];
__device__ bf16 g_V2t[DMODEL*256];

// ---------------- PTX helpers (base ISA only: sm_80-compatible) ----------------
__device__ __forceinline__ uint32_t smem_u32(const void* p) {
    uint32_t a;
    asm("{ .reg .u64 t; cvta.to.shared.u64 t, %1; cvt.u32.u64 %0, t; }" : "=r"(a) : "l"(p));
    return a;
}
__device__ __forceinline__ uint32_t pack_bf16x2(float lo, float hi) {
    uint32_t r;
    asm("cvt.rn.bf16x2.f32 %0, %1, %2;" : "=r"(r) : "f"(hi), "f"(lo));
    return r;
}
#define CPASYNC16(dst, src) asm volatile("cp.async.cg.shared.global [%0], [%1], 16;" :: "r"(dst), "l"(src))
#define CPCOMMIT()          asm volatile("cp.async.commit_group;" ::: "memory")
#define CPWAIT(n)           asm volatile("cp.async.wait_group %0;" :: "n"(n) : "memory")

__device__ __forceinline__ void ldsm4(uint32_t* r, uint32_t a) {
    asm volatile("ldmatrix.sync.aligned.m8n8.x4.shared.b16 {%0,%1,%2,%3}, [%4];"
        : "=r"(r[0]), "=r"(r[1]), "=r"(r[2]), "=r"(r[3]) : "r"(a));
}
__device__ __forceinline__ void ldsm2(uint32_t* r, uint32_t a) {
    asm volatile("ldmatrix.sync.aligned.m8n8.x2.shared.b16 {%0,%1}, [%2];"
        : "=r"(r[0]), "=r"(r[1]) : "r"(a));
}
__device__ __forceinline__ void ldsm2t(uint32_t* r, uint32_t a) {
    asm volatile("ldmatrix.sync.aligned.m8n8.x2.trans.shared.b16 {%0,%1}, [%2];"
        : "=r"(r[0]), "=r"(r[1]) : "r"(a));
}
__device__ __forceinline__ void mma16816(float* c, const uint32_t* a, const uint32_t* b) {
    asm volatile("mma.sync.aligned.m16n8k16.row.col.f32.bf16.bf16.f32 "
        "{%0,%1,%2,%3}, {%4,%5,%6,%7}, {%8,%9}, {%0,%1,%2,%3};"
        : "+f"(c[0]), "+f"(c[1]), "+f"(c[2]), "+f"(c[3])
        : "r"(a[0]), "r"(a[1]), "r"(a[2]), "r"(a[3]), "r"(b[0]), "r"(b[1]));
}

__device__ __forceinline__ float gelu_exact(float a) {
    return 0.5f * a * (1.f + erff(a * 0.70710678118654752f));
}

// ---------------- generic bf16 mma GEMM: C[128 x BN] = A[M,K] @ B[N,K]^T ----------------
// 3-stage cp.async pipeline, ONE __syncthreads per K-chunk.
// EPI: 0 = bf16 out
//      1 = f32 out = v + bias[gn] + res[...]
//      2 = bf16 out = gelu(v + bias[gn])
//      3 = QKV scatter (+bias) into g_q/g_k/g_v planes (n0 plane-aligned)
//      5 = f32 partial out at z-indexed buffer (split-K; z also offsets A,B by sA,sB)
#define BM 128
#define BK 32
#define RST 40
#define STG 3

template<int BN, int EPI>
__global__ __launch_bounds__(256) void bmma_gemm(
    const bf16* __restrict__ A, const bf16* __restrict__ B,
    int K, int ldA, int ldB, long long sA, long long sB,
    float* __restrict__ outF, bf16* __restrict__ outB,
    const float* __restrict__ bias, const float* __restrict__ res,
    int ldC, long long sC)
{
    constexpr int NT = BN / 32;
    constexpr int ACH = BM * 4;
    constexpr int TCH = (BM + BN) * 4;
    constexpr int SSA = BM * RST;
    constexpr int SS  = (BM + BN) * RST;

    extern __shared__ bf16 sm[];

    int tid = threadIdx.x;
    int z = blockIdx.z;
    const bf16* Ab = A + (long long)z * sA + (long long)blockIdx.y * BM * ldA;
    const bf16* Bb = B + (long long)z * sB + (long long)blockIdx.x * BN * ldB;
    uint32_t smu = smem_u32(sm);

    float acc[4][NT][4];
#pragma unroll
    for (int i = 0; i < 4; i++)
#pragma unroll
        for (int j = 0; j < NT; j++)
#pragma unroll
            for (int k = 0; k < 4; k++) acc[i][j][k] = 0.f;

    int wid = tid >> 5, lane = tid & 31;
    int wm = (wid >> 2) * 64;
    int wn = (wid & 3) * (BN / 4);

    int nch = K / BK;

    auto prefetch = [&](int c) {
        uint32_t base = smu + (uint32_t)((c % STG) * SS) * 2;
        long long kof = (long long)c * BK;
        for (int i = tid; i < TCH; i += 256) {
            if (i < ACH) {
                int row = i >> 2, c16 = i & 3;
                CPASYNC16(base + (uint32_t)(row * RST + c16 * 8) * 2,
                          Ab + (long long)row * ldA + kof + c16 * 8);
            } else {
                int j = i - ACH;
                int row = j >> 2, c16 = j & 3;
                CPASYNC16(base + (uint32_t)(SSA + row * RST + c16 * 8) * 2,
                          Bb + (long long)row * ldB + kof + c16 * 8);
            }
        }
        CPCOMMIT();
    };

    prefetch(0);
    if (nch > 1) prefetch(1);

    for (int c = 0; c < nch; c++) {
        if (c + 1 < nch) { CPWAIT(1); } else { CPWAIT(0); }
        __syncthreads();
        // write target (c+2)%3 == (c-1)%3, whose reads finished before this barrier
        if (c + 2 < nch) prefetch(c + 2);

        uint32_t Abase = smu + (uint32_t)((c % STG) * SS) * 2;
        uint32_t Bbase = Abase + (uint32_t)SSA * 2;
#pragma unroll
        for (int ks = 0; ks < 2; ks++) {
            uint32_t a[4][4], b[NT][2];
#pragma unroll
            for (int mt = 0; mt < 4; mt++) {
                uint32_t ad = Abase + (uint32_t)((wm + mt * 16 + (lane & 15)) * RST + ks * 16 + (lane >> 4) * 8) * 2;
                ldsm4(a[mt], ad);
            }
#pragma unroll
            for (int nt = 0; nt < NT; nt++) {
                int l = lane & 15;
                uint32_t bd = Bbase + (uint32_t)((wn + nt * 8 + (l & 7)) * RST + ks * 16 + ((l >> 3) & 1) * 8) * 2;
                ldsm2(b[nt], bd);
            }
#pragma unroll
            for (int mt = 0; mt < 4; mt++)
#pragma unroll
                for (int nt = 0; nt < NT; nt++)
                    mma16816(acc[mt][nt], a[mt], b[nt]);
        }
    }

    int m0 = blockIdx.y * BM, n0 = blockIdx.x * BN;
    // EPI==3 hoists: n0 is plane-aligned (768 = 6*128)
    bf16* plane = nullptr;
    int nloc0 = 0;
    if (EPI == 3) {
        int pp = n0 / DMODEL;
        plane = (pp == 0 ? g_q : (pp == 1 ? g_k : g_v));
        nloc0 = n0 - pp * DMODEL;
    }
#pragma unroll
    for (int mt = 0; mt < 4; mt++)
#pragma unroll
        for (int nt = 0; nt < NT; nt++)
#pragma unroll
            for (int h2 = 0; h2 < 2; h2++) {
                int gm = m0 + wm + mt * 16 + (lane >> 2) + h2 * 8;
                int gn = n0 + wn + nt * 8 + ((lane & 3) << 1);
                float v0 = acc[mt][nt][h2 * 2];
                float v1 = acc[mt][nt][h2 * 2 + 1];
                if (EPI == 0) {
                    bf16* p = outB + (long long)z * sC + (long long)gm * ldC + gn;
                    *(uint32_t*)p = pack_bf16x2(v0, v1);
                } else if (EPI == 1) {
                    long long o = (long long)gm * ldC + gn;
                    outF[o]     = v0 + bias[gn]     + res[o];
                    outF[o + 1] = v1 + bias[gn + 1] + res[o + 1];
                } else if (EPI == 2) {
                    float a0 = gelu_exact(v0 + bias[gn]);
                    float a1 = gelu_exact(v1 + bias[gn + 1]);
                    bf16* p = outB + (long long)gm * ldC + gn;
                    *(uint32_t*)p = pack_bf16x2(a0, a1);
                } else if (EPI == 3) {
                    float a0 = v0 + bias[gn];
                    float a1 = v1 + bias[gn + 1];
                    int c2 = nloc0 + wn + nt * 8 + ((lane & 3) << 1);
                    int h = c2 >> 6, j = c2 & 63;
                    int b_ = gm >> 11, m = gm & 2047;
                    bf16* pl = plane + (((long long)(b_ * NHEAD + h) << 11) + m) * DH + j;
                    *(uint32_t*)pl = pack_bf16x2(a0, a1);
                } else if (EPI == 5) {
                    float* op = outF + (long long)z * sC + (long long)gm * ldC + gn;
                    *(float2*)op = make_float2(v0, v1);
                }
            }
}

// ---------------- split-K combine: t256b = bf16(part0 + part1) ----------------
__global__ void combine_kernel(bf16* __restrict__ dst)
{
    long long i = (long long)blockIdx.x * blockDim.x + threadIdx.x;
    if (i >= (long long)NTOK * 256 / 2) return;
    float2 a = ((const float2*)g_part[0])[i];
    float2 b = ((const float2*)g_part[1])[i];
    ((uint32_t*)dst)[i] = pack_bf16x2(a.x + b.x, a.y + b.y);
}

// ---------------- flash attention: 128 Q rows/CTA, KV tiles of 64, online softmax (log2 domain) ----------------
#define FBN 64
#define KVP 72   // smem pitch (elems)
#define L2E 1.4426950408889634f

__global__ __launch_bounds__(256) void flash_kernel(const float* __restrict__ mask)
{
    __shared__ bf16 Ks[2][FBN * KVP];
    __shared__ bf16 Vs[2][FBN * KVP];
    __shared__ float Ms[2][FBN];

    int z = blockIdx.y;
    int bq = z / NHEAD, h = z - bq * NHEAD;
    int m0 = blockIdx.x * 128;
    int tid = threadIdx.x, wid = tid >> 5, lane = tid & 31;
    int wm = wid * 16;

    const bf16* Qg = g_q + ((size_t)z * SEQ + m0) * DH;
    const bf16* Kg = g_k + (size_t)z * SEQ * DH;
    const bf16* Vg = g_v + (size_t)z * SEQ * DH;
    const float* mg = mask + (size_t)bq * SEQ;

    uint32_t ks0 = smem_u32(Ks), vs0 = smem_u32(Vs), ms0 = smem_u32(Ms);

    // Q a-fragments straight from gmem (one-time)
    uint32_t qa[4][4];
    {
        const bf16* q0 = Qg + (size_t)(wm + (lane >> 2)) * DH + ((lane & 3) << 1);
#pragma unroll
        for (int t = 0; t < 4; t++) {
            qa[t][0] = *(const uint32_t*)(q0 + t * 16);
            qa[t][1] = *(const uint32_t*)(q0 + 8 * DH + t * 16);
            qa[t][2] = *(const uint32_t*)(q0 + t * 16 + 8);
            qa[t][3] = *(const uint32_t*)(q0 + 8 * DH + t * 16 + 8);
        }
    }

    // prefetch helper
    auto prefetch = [&](int s, int n0) {
        uint32_t kb = ks0 + (uint32_t)(s * FBN * KVP) * 2;
        uint32_t vb = vs0 + (uint32_t)(s * FBN * KVP) * 2;
        for (int i = tid; i < FBN * 8; i += 256) {
            int r = i >> 3, c = (i & 7) << 3;
            CPASYNC16(kb + (uint32_t)(r * KVP + c) * 2, Kg + (size_t)(n0 + r) * DH + c);
            CPASYNC16(vb + (uint32_t)(r * KVP + c) * 2, Vg + (size_t)(n0 + r) * DH + c);
        }
        if (tid < 16)
            CPASYNC16(ms0 + (uint32_t)(s * FBN + tid * 4) * 4, mg + n0 + tid * 4);
        CPCOMMIT();
    };

    prefetch(0, 0);

    float o[8][4];
#pragma unroll
    for (int i = 0; i < 8; i++)
#pragma unroll
        for (int j = 0; j < 4; j++) o[i][j] = 0.f;
    float mi0 = -1e30f, mi1 = -1e30f, li0 = 0.f, li1 = 0.f;

    const float SCL = 0.125f * L2E;   // S scale folded with log2e

    for (int s = 0; s < SEQ / FBN; s++) {
        int buf = s & 1;
        CPWAIT(0);
        __syncthreads();
        // buf^1 was fully read before this barrier; safe to overwrite
        if (s + 1 < SEQ / FBN) prefetch(buf ^ 1, (s + 1) * FBN);

        uint32_t kb = ks0 + (uint32_t)(buf * FBN * KVP) * 2;
        uint32_t vb = vs0 + (uint32_t)(buf * FBN * KVP) * 2;

        // S = Q @ K^T  (16 x 64 per warp, fp32)
        float c[8][4];
#pragma unroll
        for (int nt = 0; nt < 8; nt++)
#pragma unroll
            for (int i = 0; i < 4; i++) c[nt][i] = 0.f;
        int l = lane & 15;
#pragma unroll
        for (int t = 0; t < 4; t++) {
#pragma unroll
            for (int nt = 0; nt < 8; nt++) {
                uint32_t b[2];
                ldsm2(b, kb + (uint32_t)((nt * 8 + (l & 7)) * KVP + t * 16 + ((l >> 3) & 1) * 8) * 2);
                mma16816(c[nt], qa[t], b);
            }
        }

        // scale + mask + online softmax (all in log2 domain)
        float mx0 = -1e30f, mx1 = -1e30f;
#pragma unroll
        for (int nt = 0; nt < 8; nt++) {
            int col = nt * 8 + ((lane & 3) << 1);
            float mk0 = Ms[buf][col] * L2E, mk1 = Ms[buf][col + 1] * L2E;
            c[nt][0] = c[nt][0] * SCL + mk0;
            c[nt][1] = c[nt][1] * SCL + mk1;
            c[nt][2] = c[nt][2] * SCL + mk0;
            c[nt][3] = c[nt][3] * SCL + mk1;
            mx0 = fmaxf(mx0, fmaxf(c[nt][0], c[nt][1]));
            mx1 = fmaxf(mx1, fmaxf(c[nt][2], c[nt][3]));
        }
        mx0 = fmaxf(mx0, __shfl_xor_sync(0xffffffffu, mx0, 1));
        mx0 = fmaxf(mx0, __shfl_xor_sync(0xffffffffu, mx0, 2));
        mx1 = fmaxf(mx1, __shfl_xor_sync(0xffffffffu, mx1, 1));
        mx1 = fmaxf(mx1, __shfl_xor_sync(0xffffffffu, mx1, 2));
        float nm0 = fmaxf(mi0, mx0), nm1 = fmaxf(mi1, mx1);
        float a0 = exp2f(mi0 - nm0), a1 = exp2f(mi1 - nm1);
        float s0 = 0.f, s1 = 0.f;
#pragma unroll
        for (int nt = 0; nt < 8; nt++) {
            c[nt][0] = exp2f(c[nt][0] - nm0);
            c[nt][1] = exp2f(c[nt][1] - nm0);
            c[nt][2] = exp2f(c[nt][2] - nm1);
            c[nt][3] = exp2f(c[nt][3] - nm1);
            s0 += c[nt][0] + c[nt][1];
            s1 += c[nt][2] + c[nt][3];
        }
        s0 += __shfl_xor_sync(0xffffffffu, s0, 1);
        s0 += __shfl_xor_sync(0xffffffffu, s0, 2);
        s1 += __shfl_xor_sync(0xffffffffu, s1, 1);
        s1 += __shfl_xor_sync(0xffffffffu, s1, 2);
        li0 = li0 * a0 + s0;
        li1 = li1 * a1 + s1;
        mi0 = nm0; mi1 = nm1;
#pragma unroll
        for (int dt = 0; dt < 8; dt++) {
            o[dt][0] *= a0; o[dt][1] *= a0;
            o[dt][2] *= a1; o[dt][3] *= a1;
        }

        // O += P @ V   (P packed bf16 from c, V b-frags via trans ldmatrix)
#pragma unroll
        for (int t = 0; t < 4; t++) {
            uint32_t pa[4];
            pa[0] = pack_bf16x2(c[2 * t][0], c[2 * t][1]);
            pa[1] = pack_bf16x2(c[2 * t][2], c[2 * t][3]);
            pa[2] = pack_bf16x2(c[2 * t + 1][0], c[2 * t + 1][1]);
            pa[3] = pack_bf16x2(c[2 * t + 1][2], c[2 * t + 1][3]);
#pragma unroll
            for (int dt = 0; dt < 8; dt++) {
                uint32_t b[2];
                ldsm2t(b, vb + (uint32_t)((t * 16 + l) * KVP + dt * 8) * 2);
                mma16816(o[dt], pa, b);
            }
        }
    }

    // epilogue
    float inv0 = 1.f / li0, inv1 = 1.f / li1;
    int r0 = m0 + wm + (lane >> 2);
    bf16* out0 = g_attnb + ((size_t)(bq * SEQ + r0)) * DMODEL + h * DH;
    bf16* out1 = out0 + (size_t)8 * DMODEL;
#pragma unroll
    for (int dt = 0; dt < 8; dt++) {
        int col = dt * 8 + ((lane & 3) << 1);
        *(uint32_t*)(out0 + col) = pack_bf16x2(o[dt][0] * inv0, o[dt][1] * inv0);
        *(uint32_t*)(out1 + col) = pack_bf16x2(o[dt][2] * inv1, o[dt][3] * inv1);
    }
}

// ---------------- fp32 -> bf16 convert ----------------
__global__ void f2b_kernel(const float* __restrict__ src, bf16* __restrict__ dst, long long n2)
{
    long long i = (long long)blockIdx.x * blockDim.x + threadIdx.x;
    if (i >= n2) return;
    float2 v = ((const float2*)src)[i];
    ((uint32_t*)dst)[i] = pack_bf16x2(v.x, v.y);
}

// ---------------- fuse low-rank QKV weights (transposed, bf16) ----------------
__global__ void fuse_w_kernel(const float* __restrict__ Pq, const float* __restrict__ Vq, const float* __restrict__ bq,
                              const float* __restrict__ Pk, const float* __restrict__ Vk, const float* __restrict__ bk,
                              const float* __restrict__ Pv, const float* __restrict__ Vv, const float* __restrict__ bv)
{
    int idx = blockIdx.x * blockDim.x + threadIdx.x;
    if (idx >= DMODEL * QKVN) return;
    int c = idx / DMODEL;
    int d = idx - c * DMODEL;
    int p = c / DMODEL;
    int c2 = c - p * DMODEL;
    int h = c2 >> 6, j = c2 & 63;
    const float* P = (p == 0) ? Pq : (p == 1) ? Pk : Pv;
    const float* V = (p == 0) ? Vq : (p == 1) ? Vk : Vv;
    const float* Bv_ = (p == 0) ? bq : (p == 1) ? bk : bv;
    const float* Ph = P + (size_t)h * DMODEL * 32 + (size_t)d * 32;
    const float* Vh = V + (size_t)h * 32 * DH + j;
    float s = 0.f;
#pragma unroll
    for (int r = 0; r < 32; r++) s += Ph[r] * Vh[(size_t)r * DH];
    g_Wtb[(size_t)c * DMODEL + d] = __float2bfloat16(s);
    if (d == 0) g_bqkv[c] = Bv_[h * DH + j];
}

// ---------------- batched weight transpose fp32 -> bf16 (all 6 in one launch) ----------------
__global__ void transpose_all(const float* __restrict__ Uo, const float* __restrict__ Vo,
                              const float* __restrict__ U1, const float* __restrict__ V1,
                              const float* __restrict__ U2, const float* __restrict__ V2)
{
    __shared__ float t[32][33];
    int tidx = blockIdx.x;
    const float* src; bf16* dst; int R, C, local;
    if (tidx < 192)        { src = Uo; dst = g_Uot; R = DMODEL; C = 256;  local = tidx; }
    else if (tidx < 384)   { src = Vo; dst = g_Vot; R = 256; C = DMODEL;  local = tidx - 192; }
    else if (tidx < 576)   { src = U1; dst = g_U1t; R = DMODEL; C = 256;  local = tidx - 384; }
    else if (tidx < 1344)  { src = V1; dst = g_V1t; R = 256; C = FDIM;    local = tidx - 576; }
    else if (tidx < 2112)  { src = U2; dst = g_U2t; R = FDIM; C = 256;    local = tidx - 1344; }
    else                   { src = V2; dst = g_V2t; R = 256; C = DMODEL;  local = tidx - 2112; }
    int tilesX = C / 32;
    int tx = local % tilesX, ty = local / tilesX;
    int c0 = tx * 32, r0 = ty * 32;
    int x = threadIdx.x, y = threadIdx.y;
    for (int i = 0; i < 32; i += 8) t[y + i][x] = src[(size_t)(r0 + y + i) * C + c0 + x];
    __syncthreads();
    for (int i = 0; i < 32; i += 8) dst[(size_t)(c0 + y + i) * R + r0 + x] = __float2bfloat16(t[x][y + i]);
}

// ---------------- LayerNorm (fp32 out + optional bf16 out) ----------------
__global__ __launch_bounds__(256) void ln_kernel(const float* __restrict__ in,
                                                 const float* __restrict__ gam,
                                                 const float* __restrict__ bet,
                                                 float* __restrict__ outF,
                                                 bf16* __restrict__ outB)
{
    int row = blockIdx.x;
    int t = threadIdx.x;
    const float* ip = in + (size_t)row * DMODEL;
    float x0 = ip[t], x1 = ip[t + 256], x2 = ip[t + 512];
    __shared__ float rs[256], rq[256];
    rs[t] = x0 + x1 + x2;
    rq[t] = x0 * x0 + x1 * x1 + x2 * x2;
    __syncthreads();
    for (int off = 128; off > 0; off >>= 1) {
        if (t < off) { rs[t] += rs[t + off]; rq[t] += rq[t + off]; }
        __syncthreads();
    }
    float mu = rs[0] * (1.f / 768.f);
    float var = rq[0] * (1.f / 768.f) - mu * mu;
    float rstd = rsqrtf(var + 1e-12f);
    float y0 = (x0 - mu) * rstd * gam[t] + bet[t];
    float y1 = (x1 - mu) * rstd * gam[t + 256] + bet[t + 256];
    float y2 = (x2 - mu) * rstd * gam[t + 512] + bet[t + 512];
    float* op = outF + (size_t)row * DMODEL;
    op[t] = y0; op[t + 256] = y1; op[t + 512] = y2;
    if (outB) {
        bf16* ob = outB + (size_t)row * DMODEL;
        ob[t] = __float2bfloat16(y0);
        ob[t + 256] = __float2bfloat16(y1);
        ob[t + 512] = __float2bfloat16(y2);
    }
}

// ---------------- launch ----------------
#define GEMM_SMEM (STG * (BM + 128) * RST * 2)   // 61440 bytes for BN=128

extern "C" void kernel_launch(void* const* d_in, const int* in_sizes, int n_in,
                              void* d_out, int out_size)
{
    const float* x    = (const float*)d_in[0];
    const float* mask = (const float*)d_in[1];
    const float* Pq = (const float*)d_in[2];
    const float* Vq = (const float*)d_in[3];
    const float* bq = (const float*)d_in[4];
    const float* Pk = (const float*)d_in[5];
    const float* Vk = (const float*)d_in[6];
    const float* bk = (const float*)d_in[7];
    const float* Pv = (const float*)d_in[8];
    const float* Vv = (const float*)d_in[9];
    const float* bv = (const float*)d_in[10];
    const float* Uo = (const float*)d_in[11];
    const float* Vo = (const float*)d_in[12];
    const float* bo = (const float*)d_in[13];
    const float* U1 = (const float*)d_in[14];
    const float* V1 = (const float*)d_in[15];
    const float* b1 = (const float*)d_in[16];
    const float* U2 = (const float*)d_in[17];
    const float* V2 = (const float*)d_in[18];
    const float* b2 = (const float*)d_in[19];
    const float* g1 = (const float*)d_in[20];
    const float* be1 = (const float*)d_in[21];
    const float* g2 = (const float*)d_in[22];
    const float* be2 = (const float*)d_in[23];

    float *bqkv, *pre, *x1f, *part;
    bf16 *xb, *Wtb, *attnb, *t256b, *mid, *x1b;
    bf16 *Uot, *Vot, *U1t, *V1t, *U2t, *V2t;
    cudaGetSymbolAddress((void**)&xb,    g_xb);
    cudaGetSymbolAddress((void**)&Wtb,   g_Wtb);
    cudaGetSymbolAddress((void**)&bqkv,  g_bqkv);
    cudaGetSymbolAddress((void**)&attnb, g_attnb);
    cudaGetSymbolAddress((void**)&t256b, g_t256b);
    cudaGetSymbolAddress((void**)&mid,   g_mid);
    cudaGetSymbolAddress((void**)&part,  g_part);
    cudaGetSymbolAddress((void**)&pre,   g_pre);
    cudaGetSymbolAddress((void**)&x1f,   g_x1);
    cudaGetSymbolAddress((void**)&x1b,   g_x1b);
    cudaGetSymbolAddress((void**)&Uot,   g_Uot);
    cudaGetSymbolAddress((void**)&Vot,   g_Vot);
    cudaGetSymbolAddress((void**)&U1t,   g_U1t);
    cudaGetSymbolAddress((void**)&V1t,   g_V1t);
    cudaGetSymbolAddress((void**)&U2t,   g_U2t);
    cudaGetSymbolAddress((void**)&V2t,   g_V2t);

    // opt-in to >48KB dynamic smem (idempotent)
    cudaFuncSetAttribute(bmma_gemm<128, 0>, cudaFuncAttributeMaxDynamicSharedMemorySize, GEMM_SMEM);
    cudaFuncSetAttribute(bmma_gemm<128, 1>, cudaFuncAttributeMaxDynamicSharedMemorySize, GEMM_SMEM);
    cudaFuncSetAttribute(bmma_gemm<128, 2>, cudaFuncAttributeMaxDynamicSharedMemorySize, GEMM_SMEM);
    cudaFuncSetAttribute(bmma_gemm<128, 3>, cudaFuncAttributeMaxDynamicSharedMemorySize, GEMM_SMEM);
    cudaFuncSetAttribute(bmma_gemm<128, 5>, cudaFuncAttributeMaxDynamicSharedMemorySize, GEMM_SMEM);

    dim3 tb(32, 8);

    // 0) x -> bf16
    f2b_kernel<<<(NTOK * DMODEL / 2 + 255) / 256, 256>>>(x, xb, (long long)NTOK * DMODEL / 2);
    // 1) fold low-rank QKV weights
    fuse_w_kernel<<<(DMODEL * QKVN + 255) / 256, 256>>>(Pq, Vq, bq, Pk, Vk, bk, Pv, Vv, bv);
    // 2) all six weight transposes in one launch
    transpose_all<<<2304, tb>>>(Uo, Vo, U1, V1, U2, V2);

    // 3) QKV = xb @ Wtb^T + bias -> q/k/v planes (bf16)
    bmma_gemm<128, 3><<<dim3(QKVN / 128, NTOK / 128, 1), 256, GEMM_SMEM>>>(
        xb, Wtb, DMODEL, DMODEL, DMODEL, 0, 0,
        nullptr, nullptr, bqkv, nullptr, 0, 0);

    // 4) fused flash attention -> g_attnb [B*M, 768]
    flash_kernel<<<dim3(SEQ / 128, BH), 256>>>(mask);

    // 5) t_part[z] = attn[:, z*384:] @ Uot[:, z*384:]  (split-K x2)
    bmma_gemm<128, 5><<<dim3(2, NTOK / 128, 2), 256, GEMM_SMEM>>>(
        attnb, Uot, DMODEL / 2, DMODEL, DMODEL, DMODEL / 2, DMODEL / 2,
        part, nullptr, nullptr, nullptr, 256, (long long)NTOK * 256);
    // 6) combine -> t256b
    combine_kernel<<<(NTOK * 256 / 2 + 255) / 256, 256>>>(t256b);
    // 7) pre1 = t @ Vo + bo + x
    bmma_gemm<128, 1><<<dim3(DMODEL / 128, NTOK / 128, 1), 256, GEMM_SMEM>>>(
        t256b, Vot, 256, 256, 256, 0, 0,
        pre, nullptr, bo, x, DMODEL, 0);
    // 8) LN1 -> x1 (fp32 + bf16)
    ln_kernel<<<NTOK, 256>>>(pre, g1, be1, x1f, x1b);
    // 9) t_part[z] = x1[:, z*384:] @ U1t[:, z*384:]  (split-K x2)
    bmma_gemm<128, 5><<<dim3(2, NTOK / 128, 2), 256, GEMM_SMEM>>>(
        x1b, U1t, DMODEL / 2, DMODEL, DMODEL, DMODEL / 2, DMODEL / 2,
        part, nullptr, nullptr, nullptr, 256, (long long)NTOK * 256);
    // 10) combine -> t256b
    combine_kernel<<<(NTOK * 256 / 2 + 255) / 256, 256>>>(t256b);
    // 11) mid = gelu(t @ V1 + b1) -> bf16
    bmma_gemm<128, 2><<<dim3(FDIM / 128, NTOK / 128, 1), 256, GEMM_SMEM>>>(
        t256b, V1t, 256, 256, 256, 0, 0,
        nullptr, mid, b1, nullptr, FDIM, 0);
    // 12) t_part[z] = mid[:, z*1536:] @ U2t[:, z*1536:]  (split-K x2)
    bmma_gemm<128, 5><<<dim3(2, NTOK / 128, 2), 256, GEMM_SMEM>>>(
        mid, U2t, FDIM / 2, FDIM, FDIM, FDIM / 2, FDIM / 2,
        part, nullptr, nullptr, nullptr, 256, (long long)NTOK * 256);
    // 13) combine -> t256b
    combine_kernel<<<(NTOK * 256 / 2 + 255) / 256, 256>>>(t256b);
    // 14) pre2 = t @ V2 + b2 + x1
    bmma_gemm<128, 1><<<dim3(DMODEL / 128, NTOK / 128, 1), 256, GEMM_SMEM>>>(
        t256b, V2t, 256, 256, 256, 0, 0,
        pre, nullptr, b2, x1f, DMODEL, 0);
    // 15) LN2 -> out (fp32)
    ln_kernel<<<NTOK, 256>>>(pre, g2, be2, (float*)d_out, nullptr);
}

// round 15
// speedup vs baseline: 8.8236x; 1.0069x over previous
#include <cuda_runtime.h>
#include <cuda_bf16.h>
#include <math.h>
#include <stdint.h>

// ---------------- problem constants ----------------
#define BATCH 4
#define SEQ   2048
#define DMODEL 768
#define NHEAD 12
#define DH    64
#define NTOK  (BATCH*SEQ)          // 8192
#define QKVN  (3*DMODEL)           // 2304
#define FDIM  3072
#define BH    (BATCH*NHEAD)        // 48

typedef __nv_bfloat16 bf16;
typedef __nv_bfloat162 bf162;

// ---------------- scratch (__device__ globals; no allocation) ----------------
__device__ bf16 g_xb[(size_t)NTOK*DMODEL];
__device__ bf16 g_Wtb[(size_t)QKVN*DMODEL];            // [2304][768]
__device__ float g_bqkv[QKVN];
__device__ bf16 g_q[(size_t)BH*SEQ*DH];                // [48][2048][64]
__device__ bf16 g_k[(size_t)BH*SEQ*DH];
__device__ bf16 g_v[(size_t)BH*SEQ*DH];
__device__ bf16 g_attnb[(size_t)NTOK*DMODEL];
__device__ bf16 g_t256b[(size_t)NTOK*256];
__device__ bf16 g_mid[(size_t)NTOK*FDIM];
__device__ float g_part[2][(size_t)NTOK*256];          // split-K fp32 partials
__device__ float g_pre[(size_t)NTOK*DMODEL];
__device__ float g_x1[(size_t)NTOK*DMODEL];
__device__ bf16 g_x1b[(size_t)NTOK*DMODEL];
__device__ bf16 g_Uot[256*DMODEL];
__device__ bf16 g_Vot[DMODEL*256];
__device__ bf16 g_U1t[256*DMODEL];
__device__ bf16 g_V1t[FDIM*256];
__device__ bf16 g_U2t[256*FDIM];
__device__ bf16 g_V2t[DMODEL*256];

// ---------------- PTX helpers (base ISA only: sm_80-compatible) ----------------
__device__ __forceinline__ uint32_t smem_u32(const void* p) {
    uint32_t a;
    asm("{ .reg .u64 t; cvta.to.shared.u64 t, %1; cvt.u32.u64 %0, t; }" : "=r"(a) : "l"(p));
    return a;
}
__device__ __forceinline__ uint32_t pack_bf16x2(float lo, float hi) {
    uint32_t r;
    asm("cvt.rn.bf16x2.f32 %0, %1, %2;" : "=r"(r) : "f"(hi), "f"(lo));
    return r;
}
__device__ __forceinline__ float ex2(float x) {
    float r;
    asm("ex2.approx.ftz.f32 %0, %1;" : "=f"(r) : "f"(x));
    return r;
}
#define CPASYNC16(dst, src) asm volatile("cp.async.cg.shared.global [%0], [%1], 16;" :: "r"(dst), "l"(src))
#define CPCOMMIT()          asm volatile("cp.async.commit_group;" ::: "memory")
#define CPWAIT(n)           asm volatile("cp.async.wait_group %0;" :: "n"(n) : "memory")

__device__ __forceinline__ void ldsm4(uint32_t* r, uint32_t a) {
    asm volatile("ldmatrix.sync.aligned.m8n8.x4.shared.b16 {%0,%1,%2,%3}, [%4];"
        : "=r"(r[0]), "=r"(r[1]), "=r"(r[2]), "=r"(r[3]) : "r"(a));
}
__device__ __forceinline__ void ldsm4t(uint32_t* r, uint32_t a) {
    asm volatile("ldmatrix.sync.aligned.m8n8.x4.trans.shared.b16 {%0,%1,%2,%3}, [%4];"
        : "=r"(r[0]), "=r"(r[1]), "=r"(r[2]), "=r"(r[3]) : "r"(a));
}
__device__ __forceinline__ void mma16816(float* c, const uint32_t* a, const uint32_t* b) {
    asm volatile("mma.sync.aligned.m16n8k16.row.col.f32.bf16.bf16.f32 "
        "{%0,%1,%2,%3}, {%4,%5,%6,%7}, {%8,%9}, {%0,%1,%2,%3};"
        : "+f"(c[0]), "+f"(c[1]), "+f"(c[2]), "+f"(c[3])
        : "r"(a[0]), "r"(a[1]), "r"(a[2]), "r"(a[3]), "r"(b[0]), "r"(b[1]));
}

__device__ __forceinline__ float gelu_exact(float a) {
    return 0.5f * a * (1.f + erff(a * 0.70710678118654752f));
}

// ---------------- generic bf16 mma GEMM: C[128 x BN] = A[M,K] @ B[N,K]^T ----------------
// 3-stage cp.async pipeline, one __syncthreads per K-chunk, paired B ldsm4.
// EPI: 0 = bf16 out
//      1 = f32 out = v + bias[gn] + res[...]
//      2 = bf16 out = gelu(v + bias[gn])
//      3 = QKV scatter (+bias) into g_q/g_k/g_v planes (n0 plane-aligned)
//      5 = f32 partial out at z-indexed buffer (split-K; z also offsets A,B by sA,sB)
#define BM 128
#define BK 32
#define RST 40
#define STG 3

template<int BN, int EPI>
__global__ __launch_bounds__(256) void bmma_gemm(
    const bf16* __restrict__ A, const bf16* __restrict__ B,
    int K, int ldA, int ldB, long long sA, long long sB,
    float* __restrict__ outF, bf16* __restrict__ outB,
    const float* __restrict__ bias, const float* __restrict__ res,
    int ldC, long long sC)
{
    constexpr int NT = BN / 32;
    constexpr int ACH = BM * 4;
    constexpr int TCH = (BM + BN) * 4;
    constexpr int SSA = BM * RST;
    constexpr int SS  = (BM + BN) * RST;

    extern __shared__ bf16 sm[];

    int tid = threadIdx.x;
    int z = blockIdx.z;
    const bf16* Ab = A + (long long)z * sA + (long long)blockIdx.y * BM * ldA;
    const bf16* Bb = B + (long long)z * sB + (long long)blockIdx.x * BN * ldB;
    uint32_t smu = smem_u32(sm);

    float acc[4][NT][4];
#pragma unroll
    for (int i = 0; i < 4; i++)
#pragma unroll
        for (int j = 0; j < NT; j++)
#pragma unroll
            for (int k = 0; k < 4; k++) acc[i][j][k] = 0.f;

    int wid = tid >> 5, lane = tid & 31;
    int wm = (wid >> 2) * 64;
    int wn = (wid & 3) * (BN / 4);

    int nch = K / BK;

    auto prefetch = [&](int c) {
        uint32_t base = smu + (uint32_t)((c % STG) * SS) * 2;
        long long kof = (long long)c * BK;
        for (int i = tid; i < TCH; i += 256) {
            if (i < ACH) {
                int row = i >> 2, c16 = i & 3;
                CPASYNC16(base + (uint32_t)(row * RST + c16 * 8) * 2,
                          Ab + (long long)row * ldA + kof + c16 * 8);
            } else {
                int j = i - ACH;
                int row = j >> 2, c16 = j & 3;
                CPASYNC16(base + (uint32_t)(SSA + row * RST + c16 * 8) * 2,
                          Bb + (long long)row * ldB + kof + c16 * 8);
            }
        }
        CPCOMMIT();
    };

    prefetch(0);
    if (nch > 1) prefetch(1);

    // paired-B ldsm4 lane mapping: rows for (nt, nt+1), k-halves
    int brow = ((lane >> 4) << 3) + (lane & 7);   // +8 for second n-tile
    int bkof = ((lane >> 3) & 1) << 3;            // k half select

    for (int c = 0; c < nch; c++) {
        if (c + 1 < nch) { CPWAIT(1); } else { CPWAIT(0); }
        __syncthreads();
        if (c + 2 < nch) prefetch(c + 2);

        uint32_t Abase = smu + (uint32_t)((c % STG) * SS) * 2;
        uint32_t Bbase = Abase + (uint32_t)SSA * 2;
#pragma unroll
        for (int ks = 0; ks < 2; ks++) {
            uint32_t a[4][4], b[NT][2];
#pragma unroll
            for (int mt = 0; mt < 4; mt++) {
                uint32_t ad = Abase + (uint32_t)((wm + mt * 16 + (lane & 15)) * RST + ks * 16 + (lane >> 4) * 8) * 2;
                ldsm4(a[mt], ad);
            }
#pragma unroll
            for (int np = 0; np < NT; np += 2) {
                uint32_t bd = Bbase + (uint32_t)((wn + np * 8 + brow) * RST + ks * 16 + bkof) * 2;
                ldsm4(&b[np][0], bd);   // fills b[np][0..1], b[np+1][0..1]
            }
#pragma unroll
            for (int mt = 0; mt < 4; mt++)
#pragma unroll
                for (int nt = 0; nt < NT; nt++)
                    mma16816(acc[mt][nt], a[mt], b[nt]);
        }
    }

    int m0 = blockIdx.y * BM, n0 = blockIdx.x * BN;
    bf16* plane = nullptr;
    int nloc0 = 0;
    if (EPI == 3) {
        int pp = n0 / DMODEL;
        plane = (pp == 0 ? g_q : (pp == 1 ? g_k : g_v));
        nloc0 = n0 - pp * DMODEL;
    }
#pragma unroll
    for (int mt = 0; mt < 4; mt++)
#pragma unroll
        for (int nt = 0; nt < NT; nt++)
#pragma unroll
            for (int h2 = 0; h2 < 2; h2++) {
                int gm = m0 + wm + mt * 16 + (lane >> 2) + h2 * 8;
                int gn = n0 + wn + nt * 8 + ((lane & 3) << 1);
                float v0 = acc[mt][nt][h2 * 2];
                float v1 = acc[mt][nt][h2 * 2 + 1];
                if (EPI == 0) {
                    bf16* p = outB + (long long)z * sC + (long long)gm * ldC + gn;
                    *(uint32_t*)p = pack_bf16x2(v0, v1);
                } else if (EPI == 1) {
                    long long o = (long long)gm * ldC + gn;
                    outF[o]     = v0 + bias[gn]     + res[o];
                    outF[o + 1] = v1 + bias[gn + 1] + res[o + 1];
                } else if (EPI == 2) {
                    float a0 = gelu_exact(v0 + bias[gn]);
                    float a1 = gelu_exact(v1 + bias[gn + 1]);
                    bf16* p = outB + (long long)gm * ldC + gn;
                    *(uint32_t*)p = pack_bf16x2(a0, a1);
                } else if (EPI == 3) {
                    float a0 = v0 + bias[gn];
                    float a1 = v1 + bias[gn + 1];
                    int c2 = nloc0 + wn + nt * 8 + ((lane & 3) << 1);
                    int h = c2 >> 6, j = c2 & 63;
                    int b_ = gm >> 11, m = gm & 2047;
                    bf16* pl = plane + (((long long)(b_ * NHEAD + h) << 11) + m) * DH + j;
                    *(uint32_t*)pl = pack_bf16x2(a0, a1);
                } else if (EPI == 5) {
                    float* op = outF + (long long)z * sC + (long long)gm * ldC + gn;
                    *(float2*)op = make_float2(v0, v1);
                }
            }
}

// ---------------- split-K combine: t256b = bf16(part0 + part1) ----------------
__global__ void combine_kernel(bf16* __restrict__ dst)
{
    long long i = (long long)blockIdx.x * blockDim.x + threadIdx.x;
    if (i >= (long long)NTOK * 256 / 2) return;
    float2 a = ((const float2*)g_part[0])[i];
    float2 b = ((const float2*)g_part[1])[i];
    ((uint32_t*)dst)[i] = pack_bf16x2(a.x + b.x, a.y + b.y);
}

// ---------------- flash attention: 128 Q rows/CTA, KV tiles of 64, online softmax (log2 domain) ----------------
#define FBN 64
#define KVP 72   // smem pitch (elems)
#define L2E 1.4426950408889634f

__global__ __launch_bounds__(256) void flash_kernel(const float* __restrict__ mask)
{
    __shared__ bf16 Ks[2][FBN * KVP];
    __shared__ bf16 Vs[2][FBN * KVP];
    __shared__ float Ms[2][FBN];

    int z = blockIdx.y;
    int bq = z / NHEAD, h = z - bq * NHEAD;
    int m0 = blockIdx.x * 128;
    int tid = threadIdx.x, wid = tid >> 5, lane = tid & 31;
    int wm = wid * 16;

    const bf16* Qg = g_q + ((size_t)z * SEQ + m0) * DH;
    const bf16* Kg = g_k + (size_t)z * SEQ * DH;
    const bf16* Vg = g_v + (size_t)z * SEQ * DH;
    const float* mg = mask + (size_t)bq * SEQ;

    uint32_t ks0 = smem_u32(Ks), vs0 = smem_u32(Vs), ms0 = smem_u32(Ms);

    // Q a-fragments straight from gmem (one-time)
    uint32_t qa[4][4];
    {
        const bf16* q0 = Qg + (size_t)(wm + (lane >> 2)) * DH + ((lane & 3) << 1);
#pragma unroll
        for (int t = 0; t < 4; t++) {
            qa[t][0] = *(const uint32_t*)(q0 + t * 16);
            qa[t][1] = *(const uint32_t*)(q0 + 8 * DH + t * 16);
            qa[t][2] = *(const uint32_t*)(q0 + t * 16 + 8);
            qa[t][3] = *(const uint32_t*)(q0 + 8 * DH + t * 16 + 8);
        }
    }

    // prefetch helper
    auto prefetch = [&](int s, int n0) {
        uint32_t kb = ks0 + (uint32_t)(s * FBN * KVP) * 2;
        uint32_t vb = vs0 + (uint32_t)(s * FBN * KVP) * 2;
        for (int i = tid; i < FBN * 8; i += 256) {
            int r = i >> 3, c = (i & 7) << 3;
            CPASYNC16(kb + (uint32_t)(r * KVP + c) * 2, Kg + (size_t)(n0 + r) * DH + c);
            CPASYNC16(vb + (uint32_t)(r * KVP + c) * 2, Vg + (size_t)(n0 + r) * DH + c);
        }
        if (tid < 16)
            CPASYNC16(ms0 + (uint32_t)(s * FBN + tid * 4) * 4, mg + n0 + tid * 4);
        CPCOMMIT();
    };

    prefetch(0, 0);

    float o[8][4];
#pragma unroll
    for (int i = 0; i < 8; i++)
#pragma unroll
        for (int j = 0; j < 4; j++) o[i][j] = 0.f;
    float mi0 = -1e30f, mi1 = -1e30f, li0 = 0.f, li1 = 0.f;

    const float SCL = 0.125f * L2E;   // S scale folded with log2e

    int l = lane & 15;
    int brow = ((lane >> 4) << 3) + (lane & 7);
    int bkof = ((lane >> 3) & 1) << 3;

    for (int s = 0; s < SEQ / FBN; s++) {
        int buf = s & 1;
        CPWAIT(0);
        __syncthreads();
        if (s + 1 < SEQ / FBN) prefetch(buf ^ 1, (s + 1) * FBN);

        uint32_t kb = ks0 + (uint32_t)(buf * FBN * KVP) * 2;
        uint32_t vb = vs0 + (uint32_t)(buf * FBN * KVP) * 2;

        // S = Q @ K^T  (16 x 64 per warp, fp32), paired K ldsm4
        float c[8][4];
#pragma unroll
        for (int nt = 0; nt < 8; nt++)
#pragma unroll
            for (int i = 0; i < 4; i++) c[nt][i] = 0.f;
#pragma unroll
        for (int t = 0; t < 4; t++) {
#pragma unroll
            for (int np = 0; np < 8; np += 2) {
                uint32_t b[4];
                ldsm4(b, kb + (uint32_t)((np * 8 + brow) * KVP + t * 16 + bkof) * 2);
                mma16816(c[np], qa[t], b);
                mma16816(c[np + 1], qa[t], b + 2);
            }
        }

        // scale + mask + online softmax (all in log2 domain)
        float mx0 = -1e30f, mx1 = -1e30f;
#pragma unroll
        for (int nt = 0; nt < 8; nt++) {
            int col = nt * 8 + ((lane & 3) << 1);
            float mk0 = Ms[buf][col] * L2E, mk1 = Ms[buf][col + 1] * L2E;
            c[nt][0] = c[nt][0] * SCL + mk0;
            c[nt][1] = c[nt][1] * SCL + mk1;
            c[nt][2] = c[nt][2] * SCL + mk0;
            c[nt][3] = c[nt][3] * SCL + mk1;
            mx0 = fmaxf(mx0, fmaxf(c[nt][0], c[nt][1]));
            mx1 = fmaxf(mx1, fmaxf(c[nt][2], c[nt][3]));
        }
        mx0 = fmaxf(mx0, __shfl_xor_sync(0xffffffffu, mx0, 1));
        mx0 = fmaxf(mx0, __shfl_xor_sync(0xffffffffu, mx0, 2));
        mx1 = fmaxf(mx1, __shfl_xor_sync(0xffffffffu, mx1, 1));
        mx1 = fmaxf(mx1, __shfl_xor_sync(0xffffffffu, mx1, 2));
        float nm0 = fmaxf(mi0, mx0), nm1 = fmaxf(mi1, mx1);
        float a0 = ex2(mi0 - nm0), a1 = ex2(mi1 - nm1);
        float s0 = 0.f, s1 = 0.f;
#pragma unroll
        for (int nt = 0; nt < 8; nt++) {
            c[nt][0] = ex2(c[nt][0] - nm0);
            c[nt][1] = ex2(c[nt][1] - nm0);
            c[nt][2] = ex2(c[nt][2] - nm1);
            c[nt][3] = ex2(c[nt][3] - nm1);
            s0 += c[nt][0] + c[nt][1];
            s1 += c[nt][2] + c[nt][3];
        }
        s0 += __shfl_xor_sync(0xffffffffu, s0, 1);
        s0 += __shfl_xor_sync(0xffffffffu, s0, 2);
        s1 += __shfl_xor_sync(0xffffffffu, s1, 1);
        s1 += __shfl_xor_sync(0xffffffffu, s1, 2);
        li0 = li0 * a0 + s0;
        li1 = li1 * a1 + s1;
        mi0 = nm0; mi1 = nm1;
#pragma unroll
        for (int dt = 0; dt < 8; dt++) {
            o[dt][0] *= a0; o[dt][1] *= a0;
            o[dt][2] *= a1; o[dt][3] *= a1;
        }

        // O += P @ V   (P packed bf16 from c, paired V ldsm4t covering dt, dt+1)
#pragma unroll
        for (int t = 0; t < 4; t++) {
            uint32_t pa[4];
            pa[0] = pack_bf16x2(c[2 * t][0], c[2 * t][1]);
            pa[1] = pack_bf16x2(c[2 * t][2], c[2 * t][3]);
            pa[2] = pack_bf16x2(c[2 * t + 1][0], c[2 * t + 1][1]);
            pa[3] = pack_bf16x2(c[2 * t + 1][2], c[2 * t + 1][3]);
#pragma unroll
            for (int dp = 0; dp < 8; dp += 2) {
                uint32_t b[4];
                ldsm4t(b, vb + (uint32_t)((t * 16 + l) * KVP + (dp + (lane >> 4)) * 8) * 2);
                mma16816(o[dp], pa, b);
                mma16816(o[dp + 1], pa, b + 2);
            }
        }
    }

    // epilogue
    float inv0 = 1.f / li0, inv1 = 1.f / li1;
    int r0 = m0 + wm + (lane >> 2);
    bf16* out0 = g_attnb + ((size_t)(bq * SEQ + r0)) * DMODEL + h * DH;
    bf16* out1 = out0 + (size_t)8 * DMODEL;
#pragma unroll
    for (int dt = 0; dt < 8; dt++) {
        int col = dt * 8 + ((lane & 3) << 1);
        *(uint32_t*)(out0 + col) = pack_bf16x2(o[dt][0] * inv0, o[dt][1] * inv0);
        *(uint32_t*)(out1 + col) = pack_bf16x2(o[dt][2] * inv1, o[dt][3] * inv1);
    }
}

// ---------------- fp32 -> bf16 convert ----------------
__global__ void f2b_kernel(const float* __restrict__ src, bf16* __restrict__ dst, long long n2)
{
    long long i = (long long)blockIdx.x * blockDim.x + threadIdx.x;
    if (i >= n2) return;
    float2 v = ((const float2*)src)[i];
    ((uint32_t*)dst)[i] = pack_bf16x2(v.x, v.y);
}

// ---------------- fuse low-rank QKV weights (transposed, bf16) ----------------
__global__ void fuse_w_kernel(const float* __restrict__ Pq, const float* __restrict__ Vq, const float* __restrict__ bq,
                              const float* __restrict__ Pk, const float* __restrict__ Vk, const float* __restrict__ bk,
                              const float* __restrict__ Pv, const float* __restrict__ Vv, const float* __restrict__ bv)
{
    int idx = blockIdx.x * blockDim.x + threadIdx.x;
    if (idx >= DMODEL * QKVN) return;
    int c = idx / DMODEL;
    int d = idx - c * DMODEL;
    int p = c / DMODEL;
    int c2 = c - p * DMODEL;
    int h = c2 >> 6, j = c2 & 63;
    const float* P = (p == 0) ? Pq : (p == 1) ? Pk : Pv;
    const float* V = (p == 0) ? Vq : (p == 1) ? Vk : Vv;
    const float* Bv_ = (p == 0) ? bq : (p == 1) ? bk : bv;
    const float* Ph = P + (size_t)h * DMODEL * 32 + (size_t)d * 32;
    const float* Vh = V + (size_t)h * 32 * DH + j;
    float s = 0.f;
#pragma unroll
    for (int r = 0; r < 32; r++) s += Ph[r] * Vh[(size_t)r * DH];
    g_Wtb[(size_t)c * DMODEL + d] = __float2bfloat16(s);
    if (d == 0) g_bqkv[c] = Bv_[h * DH + j];
}

// ---------------- batched weight transpose fp32 -> bf16 (all 6 in one launch) ----------------
__global__ void transpose_all(const float* __restrict__ Uo, const float* __restrict__ Vo,
                              const float* __restrict__ U1, const float* __restrict__ V1,
                              const float* __restrict__ U2, const float* __restrict__ V2)
{
    __shared__ float t[32][33];
    int tidx = blockIdx.x;
    const float* src; bf16* dst; int R, C, local;
    if (tidx < 192)        { src = Uo; dst = g_Uot; R = DMODEL; C = 256;  local = tidx; }
    else if (tidx < 384)   { src = Vo; dst = g_Vot; R = 256; C = DMODEL;  local = tidx - 192; }
    else if (tidx < 576)   { src = U1; dst = g_U1t; R = DMODEL; C = 256;  local = tidx - 384; }
    else if (tidx < 1344)  { src = V1; dst = g_V1t; R = 256; C = FDIM;    local = tidx - 576; }
    else if (tidx < 2112)  { src = U2; dst = g_U2t; R = FDIM; C = 256;    local = tidx - 1344; }
    else                   { src = V2; dst = g_V2t; R = 256; C = DMODEL;  local = tidx - 2112; }
    int tilesX = C / 32;
    int tx = local % tilesX, ty = local / tilesX;
    int c0 = tx * 32, r0 = ty * 32;
    int x = threadIdx.x, y = threadIdx.y;
    for (int i = 0; i < 32; i += 8) t[y + i][x] = src[(size_t)(r0 + y + i) * C + c0 + x];
    __syncthreads();
    for (int i = 0; i < 32; i += 8) dst[(size_t)(c0 + y + i) * R + r0 + x] = __float2bfloat16(t[x][y + i]);
}

// ---------------- LayerNorm (fp32 out + optional bf16 out) ----------------
__global__ __launch_bounds__(256) void ln_kernel(const float* __restrict__ in,
                                                 const float* __restrict__ gam,
                                                 const float* __restrict__ bet,
                                                 float* __restrict__ outF,
                                                 bf16* __restrict__ outB)
{
    int row = blockIdx.x;
    int t = threadIdx.x;
    const float* ip = in + (size_t)row * DMODEL;
    float x0 = ip[t], x1 = ip[t + 256], x2 = ip[t + 512];
    __shared__ float rs[256], rq[256];
    rs[t] = x0 + x1 + x2;
    rq[t] = x0 * x0 + x1 * x1 + x2 * x2;
    __syncthreads();
    for (int off = 128; off > 0; off >>= 1) {
        if (t < off) { rs[t] += rs[t + off]; rq[t] += rq[t + off]; }
        __syncthreads();
    }
    float mu = rs[0] * (1.f / 768.f);
    float var = rq[0] * (1.f / 768.f) - mu * mu;
    float rstd = rsqrtf(var + 1e-12f);
    float y0 = (x0 - mu) * rstd * gam[t] + bet[t];
    float y1 = (x1 - mu) * rstd * gam[t + 256] + bet[t + 256];
    float y2 = (x2 - mu) * rstd * gam[t + 512] + bet[t + 512];
    float* op = outF + (size_t)row * DMODEL;
    op[t] = y0; op[t + 256] = y1; op[t + 512] = y2;
    if (outB) {
        bf16* ob = outB + (size_t)row * DMODEL;
        ob[t] = __float2bfloat16(y0);
        ob[t + 256] = __float2bfloat16(y1);
        ob[t + 512] = __float2bfloat16(y2);
    }
}

// ---------------- launch ----------------
#define GEMM_SMEM (STG * (BM + 128) * RST * 2)   // 61440 bytes for BN=128

extern "C" void kernel_launch(void* const* d_in, const int* in_sizes, int n_in,
                              void* d_out, int out_size)
{
    const float* x    = (const float*)d_in[0];
    const float* mask = (const float*)d_in[1];
    const float* Pq = (const float*)d_in[2];
    const float* Vq = (const float*)d_in[3];
    const float* bq = (const float*)d_in[4];
    const float* Pk = (const float*)d_in[5];
    const float* Vk = (const float*)d_in[6];
    const float* bk = (const float*)d_in[7];
    const float* Pv = (const float*)d_in[8];
    const float* Vv = (const float*)d_in[9];
    const float* bv = (const float*)d_in[10];
    const float* Uo = (const float*)d_in[11];
    const float* Vo = (const float*)d_in[12];
    const float* bo = (const float*)d_in[13];
    const float* U1 = (const float*)d_in[14];
    const float* V1 = (const float*)d_in[15];
    const float* b1 = (const float*)d_in[16];
    const float* U2 = (const float*)d_in[17];
    const float* V2 = (const float*)d_in[18];
    const float* b2 = (const float*)d_in[19];
    const float* g1 = (const float*)d_in[20];
    const float* be1 = (const float*)d_in[21];
    const float* g2 = (const float*)d_in[22];
    const float* be2 = (const float*)d_in[23];

    float *bqkv, *pre, *x1f, *part;
    bf16 *xb, *Wtb, *attnb, *t256b, *mid, *x1b;
    bf16 *Uot, *Vot, *U1t, *V1t, *U2t, *V2t;
    cudaGetSymbolAddress((void**)&xb,    g_xb);
    cudaGetSymbolAddress((void**)&Wtb,   g_Wtb);
    cudaGetSymbolAddress((void**)&bqkv,  g_bqkv);
    cudaGetSymbolAddress((void**)&attnb, g_attnb);
    cudaGetSymbolAddress((void**)&t256b, g_t256b);
    cudaGetSymbolAddress((void**)&mid,   g_mid);
    cudaGetSymbolAddress((void**)&part,  g_part);
    cudaGetSymbolAddress((void**)&pre,   g_pre);
    cudaGetSymbolAddress((void**)&x1f,   g_x1);
    cudaGetSymbolAddress((void**)&x1b,   g_x1b);
    cudaGetSymbolAddress((void**)&Uot,   g_Uot);
    cudaGetSymbolAddress((void**)&Vot,   g_Vot);
    cudaGetSymbolAddress((void**)&U1t,   g_U1t);
    cudaGetSymbolAddress((void**)&V1t,   g_V1t);
    cudaGetSymbolAddress((void**)&U2t,   g_U2t);
    cudaGetSymbolAddress((void**)&V2t,   g_V2t);

    // opt-in to >48KB dynamic smem (idempotent)
    cudaFuncSetAttribute(bmma_gemm<128, 0>, cudaFuncAttributeMaxDynamicSharedMemorySize, GEMM_SMEM);
    cudaFuncSetAttribute(bmma_gemm<128, 1>, cudaFuncAttributeMaxDynamicSharedMemorySize, GEMM_SMEM);
    cudaFuncSetAttribute(bmma_gemm<128, 2>, cudaFuncAttributeMaxDynamicSharedMemorySize, GEMM_SMEM);
    cudaFuncSetAttribute(bmma_gemm<128, 3>, cudaFuncAttributeMaxDynamicSharedMemorySize, GEMM_SMEM);
    cudaFuncSetAttribute(bmma_gemm<128, 5>, cudaFuncAttributeMaxDynamicSharedMemorySize, GEMM_SMEM);

    dim3 tb(32, 8);

    // 0) x -> bf16
    f2b_kernel<<<(NTOK * DMODEL / 2 + 255) / 256, 256>>>(x, xb, (long long)NTOK * DMODEL / 2);
    // 1) fold low-rank QKV weights
    fuse_w_kernel<<<(DMODEL * QKVN + 255) / 256, 256>>>(Pq, Vq, bq, Pk, Vk, bk, Pv, Vv, bv);
    // 2) all six weight transposes in one launch
    transpose_all<<<2304, tb>>>(Uo, Vo, U1, V1, U2, V2);

    // 3) QKV = xb @ Wtb^T + bias -> q/k/v planes (bf16)
    bmma_gemm<128, 3><<<dim3(QKVN / 128, NTOK / 128, 1), 256, GEMM_SMEM>>>(
        xb, Wtb, DMODEL, DMODEL, DMODEL, 0, 0,
        nullptr, nullptr, bqkv, nullptr, 0, 0);

    // 4) fused flash attention -> g_attnb [B*M, 768]
    flash_kernel<<<dim3(SEQ / 128, BH), 256>>>(mask);

    // 5) t_part[z] = attn[:, z*384:] @ Uot[:, z*384:]  (split-K x2)
    bmma_gemm<128, 5><<<dim3(2, NTOK / 128, 2), 256, GEMM_SMEM>>>(
        attnb, Uot, DMODEL / 2, DMODEL, DMODEL, DMODEL / 2, DMODEL / 2,
        part, nullptr, nullptr, nullptr, 256, (long long)NTOK * 256);
    // 6) combine -> t256b
    combine_kernel<<<(NTOK * 256 / 2 + 255) / 256, 256>>>(t256b);
    // 7) pre1 = t @ Vo + bo + x
    bmma_gemm<128, 1><<<dim3(DMODEL / 128, NTOK / 128, 1), 256, GEMM_SMEM>>>(
        t256b, Vot, 256, 256, 256, 0, 0,
        pre, nullptr, bo, x, DMODEL, 0);
    // 8) LN1 -> x1 (fp32 + bf16)
    ln_kernel<<<NTOK, 256>>>(pre, g1, be1, x1f, x1b);
    // 9) t_part[z] = x1[:, z*384:] @ U1t[:, z*384:]  (split-K x2)
    bmma_gemm<128, 5><<<dim3(2, NTOK / 128, 2), 256, GEMM_SMEM>>>(
        x1b, U1t, DMODEL / 2, DMODEL, DMODEL, DMODEL / 2, DMODEL / 2,
        part, nullptr, nullptr, nullptr, 256, (long long)NTOK * 256);
    // 10) combine -> t256b
    combine_kernel<<<(NTOK * 256 / 2 + 255) / 256, 256>>>(t256b);
    // 11) mid = gelu(t @ V1 + b1) -> bf16
    bmma_gemm<128, 2><<<dim3(FDIM / 128, NTOK / 128, 1), 256, GEMM_SMEM>>>(
        t256b, V1t, 256, 256, 256, 0, 0,
        nullptr, mid, b1, nullptr, FDIM, 0);
    // 12) t_part[z] = mid[:, z*1536:] @ U2t[:, z*1536:]  (split-K x2)
    bmma_gemm<128, 5><<<dim3(2, NTOK / 128, 2), 256, GEMM_SMEM>>>(
        mid, U2t, FDIM / 2, FDIM, FDIM, FDIM / 2, FDIM / 2,
        part, nullptr, nullptr, nullptr, 256, (long long)NTOK * 256);
    // 13) combine -> t256b
    combine_kernel<<<(NTOK * 256 / 2 + 255) / 256, 256>>>(t256b);
    // 14) pre2 = t @ V2 + b2 + x1
    bmma_gemm<128, 1><<<dim3(DMODEL / 128, NTOK / 128, 1), 256, GEMM_SMEM>>>(
        t256b, V2t, 256, 256, 256, 0, 0,
        pre, nullptr, b2, x1f, DMODEL, 0);
    // 15) LN2 -> out (fp32)
    ln_kernel<<<NTOK, 256>>>(pre, g2, be2, (float*)d_out, nullptr);
}